// round 5
// baseline (speedup 1.0000x reference)
#include <cuda_runtime.h>
#include <math.h>

#define B_   2
#define N_   4096
#define IC_  256
#define PC_  128
#define OC_  128
#define SCALE_ 0.08838834764831845f   // 1/sqrt(128)
#define LDK  20                        // padded row pitch (floats) for ldmatrix tiles

// ---------------- scratch (device globals) ----------------------------------
static __device__ float g_rp  [(size_t)B_ * N_ * PC_];
static __device__ float g_ri  [(size_t)B_ * N_ * PC_];
static __device__ float g_S   [(size_t)B_ * N_ * N_];    // P = exp(scale*S)
static __device__ float g_csum[B_ * N_];
static __device__ float g_rsum[B_ * N_];
static __device__ float g_outp[(size_t)B_ * N_ * PC_];
static __device__ float g_outi[(size_t)B_ * N_ * PC_];

// ---------------- helpers ----------------------------------------------------
__device__ __forceinline__ unsigned tf32_of(float x) {
    unsigned r; asm("cvt.rna.tf32.f32 %0, %1;" : "=r"(r) : "f"(x)); return r;
}
__device__ __forceinline__ void mma_tf32(float* c, unsigned a0, unsigned a1,
                                         unsigned a2, unsigned a3,
                                         unsigned b0, unsigned b1) {
    asm volatile(
        "mma.sync.aligned.m16n8k8.row.col.f32.tf32.tf32.f32 "
        "{%0,%1,%2,%3}, {%4,%5,%6,%7}, {%8,%9}, {%0,%1,%2,%3};"
        : "+f"(c[0]), "+f"(c[1]), "+f"(c[2]), "+f"(c[3])
        : "r"(a0), "r"(a1), "r"(a2), "r"(a3), "r"(b0), "r"(b1));
}
__device__ __forceinline__ unsigned smem_u32(const void* p) {
    unsigned a;
    asm("{.reg .u64 t; cvta.to.shared.u64 t, %1; cvt.u32.u64 %0, t;}"
        : "=r"(a) : "l"(p));
    return a;
}
__device__ __forceinline__ void ldsm4(unsigned& r0, unsigned& r1,
                                      unsigned& r2, unsigned& r3, unsigned addr) {
    asm volatile("ldmatrix.sync.aligned.m8n8.x4.shared.b16 {%0,%1,%2,%3}, [%4];"
                 : "=r"(r0), "=r"(r1), "=r"(r2), "=r"(r3) : "r"(addr));
}

// ---------------- kernel 0: zero the sum accumulators ------------------------
__global__ void k_zero() {
    int i = blockIdx.x * blockDim.x + threadIdx.x;
    if (i < B_ * N_) { g_csum[i] = 0.f; g_rsum[i] = 0.f; }
}

// ---------------- kernel 1: transpose point_features [B,PC,N] -> rp [B,N,PC]
__global__ void k_transpose(const float* __restrict__ pf) {
    __shared__ float tile[32][33];
    const int b  = blockIdx.z;
    const int n0 = blockIdx.x * 32;
    const int d0 = blockIdx.y * 32;
    const float* src = pf   + (size_t)b * PC_ * N_;
    float*       dst = g_rp + (size_t)b * N_ * PC_;
    const int tx = threadIdx.x, ty = threadIdx.y;   // (32, 8)
#pragma unroll
    for (int j = 0; j < 32; j += 8)
        tile[ty + j][tx] = src[(size_t)(d0 + ty + j) * N_ + n0 + tx];
    __syncthreads();
#pragma unroll
    for (int j = 0; j < 32; j += 8)
        dst[(size_t)(n0 + ty + j) * PC_ + d0 + tx] = tile[tx][ty + j];
}

// ---------------- kernel 2: ri = img^T @ fc2_w^T + fc2_b  (scalar fp32) ------
__global__ void k_ri(const float* __restrict__ img, const float* __restrict__ w,
                     const float* __restrict__ bias) {
    const int b  = blockIdx.z;
    const int n0 = blockIdx.y * 64;
    const float* X = img  + (size_t)b * IC_ * N_;
    float*       R = g_ri + (size_t)b * N_ * PC_;
    __shared__ float As[16][64];
    __shared__ float Bs[16][128];
    const int tx = threadIdx.x, ty = threadIdx.y;
    const int tid = ty * 16 + tx;
    float acc[4][8];
#pragma unroll
    for (int i = 0; i < 4; i++)
#pragma unroll
        for (int j = 0; j < 8; j++) acc[i][j] = 0.f;

    for (int k0 = 0; k0 < IC_; k0 += 16) {
        {
            int l = tid * 4, kk = l / 64, nn = l % 64;
            float4 v = *(const float4*)&X[(size_t)(k0 + kk) * N_ + n0 + nn];
            *(float4*)&As[kk][nn] = v;
        }
        {
            int l = tid * 8, dd = l / 16, kk = l % 16;
            float4 v0 = *(const float4*)&w[(size_t)dd * IC_ + k0 + kk];
            float4 v1 = *(const float4*)&w[(size_t)dd * IC_ + k0 + kk + 4];
            Bs[kk + 0][dd] = v0.x; Bs[kk + 1][dd] = v0.y;
            Bs[kk + 2][dd] = v0.z; Bs[kk + 3][dd] = v0.w;
            Bs[kk + 4][dd] = v1.x; Bs[kk + 5][dd] = v1.y;
            Bs[kk + 6][dd] = v1.z; Bs[kk + 7][dd] = v1.w;
        }
        __syncthreads();
#pragma unroll
        for (int kk = 0; kk < 16; kk++) {
            float a[4], bb[8];
#pragma unroll
            for (int i = 0; i < 4; i++) a[i] = As[kk][ty * 4 + i];
#pragma unroll
            for (int j = 0; j < 8; j++) bb[j] = Bs[kk][tx * 8 + j];
#pragma unroll
            for (int i = 0; i < 4; i++)
#pragma unroll
                for (int j = 0; j < 8; j++) acc[i][j] += a[i] * bb[j];
        }
        __syncthreads();
    }
#pragma unroll
    for (int i = 0; i < 4; i++) {
        int n = n0 + ty * 4 + i;
#pragma unroll
        for (int j = 0; j < 8; j++) {
            int d = tx * 8 + j;
            R[(size_t)n * PC_ + d] = acc[i][j] + bias[d];
        }
    }
}

// ---------------- kernel 3: P = exp(scale * rp @ ri^T) + row/col sums --------
// tf32 mma + ldmatrix.x4 fragments. m-major smem tiles [128][LDK], BK=16.
__global__ __launch_bounds__(256, 2) void k_s() {
    const int b  = blockIdx.z;
    const int i0 = blockIdx.y * 128;
    const int j0 = blockIdx.x * 128;
    const float* A  = g_rp + (size_t)b * N_ * PC_;
    const float* Bm = g_ri + (size_t)b * N_ * PC_;
    float*       Pp = g_S  + (size_t)b * N_ * N_;

    __shared__ unsigned AsT[128][LDK];
    __shared__ unsigned BsT[128][LDK];
    __shared__ float shr[128], shc[128];

    const int tid  = threadIdx.x;
    const int lane = tid & 31, wid = tid >> 5;
    const int wm = wid & 1, wn = wid >> 1;
    const int g = lane >> 2, t = lane & 3;
    const int jm = lane >> 3;                    // ldmatrix matrix index

    const unsigned baseA = smem_u32(&AsT[0][0]) +
        (((wm * 64) + ((jm & 1) * 8) + (lane & 7)) * LDK + ((jm >> 1) * 4)) * 4u;
    const unsigned baseB = smem_u32(&BsT[0][0]) +
        (((wn * 32) + ((jm >> 1) * 8) + (lane & 7)) * LDK + ((jm & 1) * 4)) * 4u;

    // fill coords: each thread stages 2 float4 per operand
    const int fi = tid >> 2;                     // row 0..63  (+64 for r=1)
    const int fc = (tid & 3) * 4;                // col 0,4,8,12

    float acc[4][4][4];
#pragma unroll
    for (int mf = 0; mf < 4; mf++)
#pragma unroll
        for (int nf = 0; nf < 4; nf++)
#pragma unroll
            for (int q = 0; q < 4; q++) acc[mf][nf][q] = 0.f;

    float4 ra[2], rb[2];
#pragma unroll
    for (int r = 0; r < 2; r++) {
        ra[r] = *(const float4*)&A [(size_t)(i0 + fi + r * 64) * PC_ + fc];
        rb[r] = *(const float4*)&Bm[(size_t)(j0 + fi + r * 64) * PC_ + fc];
    }

    for (int k0 = 0; k0 < PC_; k0 += 16) {
#pragma unroll
        for (int r = 0; r < 2; r++) {
            uint4 ua = make_uint4(tf32_of(ra[r].x), tf32_of(ra[r].y),
                                  tf32_of(ra[r].z), tf32_of(ra[r].w));
            *(uint4*)&AsT[fi + r * 64][fc] = ua;
            uint4 ub = make_uint4(tf32_of(rb[r].x), tf32_of(rb[r].y),
                                  tf32_of(rb[r].z), tf32_of(rb[r].w));
            *(uint4*)&BsT[fi + r * 64][fc] = ub;
        }
        __syncthreads();
        if (k0 + 16 < PC_) {
#pragma unroll
            for (int r = 0; r < 2; r++) {
                ra[r] = *(const float4*)&A [(size_t)(i0 + fi + r * 64) * PC_ + k0 + 16 + fc];
                rb[r] = *(const float4*)&Bm[(size_t)(j0 + fi + r * 64) * PC_ + k0 + 16 + fc];
            }
        }
#pragma unroll
        for (int kk = 0; kk < 16; kk += 8) {
            unsigned a[4][4], bb[4][2];
#pragma unroll
            for (int mf = 0; mf < 4; mf++)
                ldsm4(a[mf][0], a[mf][1], a[mf][2], a[mf][3],
                      baseA + (mf * 16 * LDK + kk) * 4u);
            ldsm4(bb[0][0], bb[0][1], bb[1][0], bb[1][1], baseB + kk * 4u);
            ldsm4(bb[2][0], bb[2][1], bb[3][0], bb[3][1],
                  baseB + (16 * LDK + kk) * 4u);
#pragma unroll
            for (int mf = 0; mf < 4; mf++)
#pragma unroll
                for (int nf = 0; nf < 4; nf++)
                    mma_tf32(acc[mf][nf], a[mf][0], a[mf][1], a[mf][2], a[mf][3],
                             bb[nf][0], bb[nf][1]);
        }
        __syncthreads();
    }

    // epilogue: P = exp(scale*acc), store, reduce row/col sums
    if (tid < 128) { shr[tid] = 0.f; shc[tid] = 0.f; }
    __syncthreads();

    float rs[4][2] = {{0.f,0.f},{0.f,0.f},{0.f,0.f},{0.f,0.f}};
    float cs[4][2] = {{0.f,0.f},{0.f,0.f},{0.f,0.f},{0.f,0.f}};
#pragma unroll
    for (int mf = 0; mf < 4; mf++) {
        int row = i0 + wm * 64 + mf * 16 + g;
#pragma unroll
        for (int nf = 0; nf < 4; nf++) {
            int col = j0 + wn * 32 + nf * 8 + 2 * t;
            float p0 = __expf(acc[mf][nf][0] * SCALE_);
            float p1 = __expf(acc[mf][nf][1] * SCALE_);
            float p2 = __expf(acc[mf][nf][2] * SCALE_);
            float p3 = __expf(acc[mf][nf][3] * SCALE_);
            *(float2*)&Pp[(size_t)row * N_ + col]       = make_float2(p0, p1);
            *(float2*)&Pp[(size_t)(row + 8) * N_ + col] = make_float2(p2, p3);
            rs[mf][0] += p0 + p1; rs[mf][1] += p2 + p3;
            cs[nf][0] += p0 + p2; cs[nf][1] += p1 + p3;
        }
    }
#pragma unroll
    for (int mf = 0; mf < 4; mf++)
#pragma unroll
        for (int h = 0; h < 2; h++) {
            float v = rs[mf][h];
            v += __shfl_xor_sync(0xffffffffu, v, 1);
            v += __shfl_xor_sync(0xffffffffu, v, 2);
            if (t == 0) atomicAdd(&shr[wm * 64 + mf * 16 + h * 8 + g], v);
        }
#pragma unroll
    for (int nf = 0; nf < 4; nf++)
#pragma unroll
        for (int q = 0; q < 2; q++) {
            float v = cs[nf][q];
            v += __shfl_xor_sync(0xffffffffu, v, 4);
            v += __shfl_xor_sync(0xffffffffu, v, 8);
            v += __shfl_xor_sync(0xffffffffu, v, 16);
            if (g == 0) atomicAdd(&shc[wn * 32 + nf * 8 + 2 * t + q], v);
        }
    __syncthreads();
    if (tid < 128) {
        atomicAdd(&g_rsum[b * N_ + i0 + tid], shr[tid]);
        atomicAdd(&g_csum[b * N_ + j0 + tid], shc[tid]);
    }
}

// ---------------- kernel 4: AV GEMMs (tf32 + ldmatrix, prefetch) -------------
// mode 0: out_p[i,d] = sum_j P[i,j] * (rp[j,d]/csum[j])
// mode 1: out_i[i,d] = sum_j P[j,i] * (ri[j,d]/rsum[j])
__global__ __launch_bounds__(256, 2) void k_av() {
    const int mode = blockIdx.x;
    const int b    = blockIdx.z;
    const int i0   = blockIdx.y * 128;
    const float* Pp  = g_S + (size_t)b * N_ * N_;
    const float* V   = (mode == 0 ? g_rp : g_ri) + (size_t)b * N_ * PC_;
    const float* sum = (mode == 0 ? g_csum : g_rsum) + b * N_;
    float*       D   = (mode == 0 ? g_outp : g_outi) + (size_t)b * N_ * PC_;

    __shared__ unsigned AsT[128][LDK];
    __shared__ unsigned BsT[128][LDK];

    const int tid  = threadIdx.x;
    const int lane = tid & 31, wid = tid >> 5;
    const int wm = wid & 1, wn = wid >> 1;
    const int g = lane >> 2, t = lane & 3;
    const int jm = lane >> 3;

    const unsigned baseA = smem_u32(&AsT[0][0]) +
        (((wm * 64) + ((jm & 1) * 8) + (lane & 7)) * LDK + ((jm >> 1) * 4)) * 4u;
    const unsigned baseB = smem_u32(&BsT[0][0]) +
        (((wn * 32) + ((jm >> 1) * 8) + (lane & 7)) * LDK + ((jm & 1) * 4)) * 4u;

    // fill coords (mode 0 A): row-major direct
    const int fi = tid >> 2, fc = (tid & 3) * 4;
    // fill coords (mode 1 A, and B): k-row scatter
    const int fk = tid >> 5, fd = (tid & 31) * 4;

    float acc[4][4][4];
#pragma unroll
    for (int mf = 0; mf < 4; mf++)
#pragma unroll
        for (int nf = 0; nf < 4; nf++)
#pragma unroll
            for (int q = 0; q < 4; q++) acc[mf][nf][q] = 0.f;

    float4 ra[2], rb[2];
    float  rinv[2];
#pragma unroll
    for (int r = 0; r < 2; r++) {
        if (mode == 0)
            ra[r] = *(const float4*)&Pp[(size_t)(i0 + fi + r * 64) * N_ + fc];
        else
            ra[r] = *(const float4*)&Pp[(size_t)(fk + r * 8) * N_ + i0 + fd];
        rb[r]   = *(const float4*)&V[(size_t)(fk + r * 8) * PC_ + fd];
        rinv[r] = __fdividef(1.0f, sum[fk + r * 8]);
    }

    for (int k0 = 0; k0 < N_; k0 += 16) {
        if (mode == 0) {
#pragma unroll
            for (int r = 0; r < 2; r++) {
                uint4 ua = make_uint4(tf32_of(ra[r].x), tf32_of(ra[r].y),
                                      tf32_of(ra[r].z), tf32_of(ra[r].w));
                *(uint4*)&AsT[fi + r * 64][fc] = ua;
            }
        } else {
#pragma unroll
            for (int r = 0; r < 2; r++) {
                AsT[fd + 0][fk + r * 8] = tf32_of(ra[r].x);
                AsT[fd + 1][fk + r * 8] = tf32_of(ra[r].y);
                AsT[fd + 2][fk + r * 8] = tf32_of(ra[r].z);
                AsT[fd + 3][fk + r * 8] = tf32_of(ra[r].w);
            }
        }
#pragma unroll
        for (int r = 0; r < 2; r++) {
            float inv = rinv[r];
            BsT[fd + 0][fk + r * 8] = tf32_of(rb[r].x * inv);
            BsT[fd + 1][fk + r * 8] = tf32_of(rb[r].y * inv);
            BsT[fd + 2][fk + r * 8] = tf32_of(rb[r].z * inv);
            BsT[fd + 3][fk + r * 8] = tf32_of(rb[r].w * inv);
        }
        __syncthreads();
        if (k0 + 16 < N_) {
            int kn = k0 + 16;
#pragma unroll
            for (int r = 0; r < 2; r++) {
                if (mode == 0)
                    ra[r] = *(const float4*)&Pp[(size_t)(i0 + fi + r * 64) * N_ + kn + fc];
                else
                    ra[r] = *(const float4*)&Pp[(size_t)(kn + fk + r * 8) * N_ + i0 + fd];
                rb[r]   = *(const float4*)&V[(size_t)(kn + fk + r * 8) * PC_ + fd];
                rinv[r] = __fdividef(1.0f, sum[kn + fk + r * 8]);
            }
        }
#pragma unroll
        for (int kk = 0; kk < 16; kk += 8) {
            unsigned a[4][4], bb[4][2];
#pragma unroll
            for (int mf = 0; mf < 4; mf++)
                ldsm4(a[mf][0], a[mf][1], a[mf][2], a[mf][3],
                      baseA + (mf * 16 * LDK + kk) * 4u);
            ldsm4(bb[0][0], bb[0][1], bb[1][0], bb[1][1], baseB + kk * 4u);
            ldsm4(bb[2][0], bb[2][1], bb[3][0], bb[3][1],
                  baseB + (16 * LDK + kk) * 4u);
#pragma unroll
            for (int mf = 0; mf < 4; mf++)
#pragma unroll
                for (int nf = 0; nf < 4; nf++)
                    mma_tf32(acc[mf][nf], a[mf][0], a[mf][1], a[mf][2], a[mf][3],
                             bb[nf][0], bb[nf][1]);
        }
        __syncthreads();
    }
#pragma unroll
    for (int mf = 0; mf < 4; mf++) {
        int row = i0 + wm * 64 + mf * 16 + g;
#pragma unroll
        for (int nf = 0; nf < 4; nf++) {
            int col = wn * 32 + nf * 8 + 2 * t;
            *(float2*)&D[(size_t)row * PC_ + col]       = make_float2(acc[mf][nf][0], acc[mf][nf][1]);
            *(float2*)&D[(size_t)(row + 8) * PC_ + col] = make_float2(acc[mf][nf][2], acc[mf][nf][3]);
        }
    }
}

// ---------------- kernel 5: conv1d(k=1) + BN(eval) + ReLU  (scalar fp32) -----
__global__ void k_conv(const float* __restrict__ w,     const float* __restrict__ cb,
                       const float* __restrict__ gamma, const float* __restrict__ beta,
                       const float* __restrict__ mean,  const float* __restrict__ var,
                       float* __restrict__ out) {
    const int b  = blockIdx.z;
    const int n0 = blockIdx.x * 64;
    const float* P = g_outp + (size_t)b * N_ * PC_;
    const float* I = g_outi + (size_t)b * N_ * PC_;
    __shared__ float As[16][128];
    __shared__ float Bs[16][64];
    const int tx = threadIdx.x, ty = threadIdx.y;
    const int tid = ty * 16 + tx;
    float acc[8][4];
#pragma unroll
    for (int i = 0; i < 8; i++)
#pragma unroll
        for (int j = 0; j < 4; j++) acc[i][j] = 0.f;

    for (int k0 = 0; k0 < 2 * PC_; k0 += 16) {
        {
            int l = tid * 8, oo = l / 16, kk = l % 16;
            float4 v0 = *(const float4*)&w[(size_t)oo * (2 * PC_) + k0 + kk];
            float4 v1 = *(const float4*)&w[(size_t)oo * (2 * PC_) + k0 + kk + 4];
            As[kk + 0][oo] = v0.x; As[kk + 1][oo] = v0.y;
            As[kk + 2][oo] = v0.z; As[kk + 3][oo] = v0.w;
            As[kk + 4][oo] = v1.x; As[kk + 5][oo] = v1.y;
            As[kk + 6][oo] = v1.z; As[kk + 7][oo] = v1.w;
        }
        {
            int l = tid * 4, nn = l / 16, kk = l % 16;
            const float* src = (k0 < PC_) ? &P[(size_t)(n0 + nn) * PC_ + k0 + kk]
                                          : &I[(size_t)(n0 + nn) * PC_ + k0 - PC_ + kk];
            float4 v = *(const float4*)src;
            Bs[kk + 0][nn] = v.x; Bs[kk + 1][nn] = v.y;
            Bs[kk + 2][nn] = v.z; Bs[kk + 3][nn] = v.w;
        }
        __syncthreads();
#pragma unroll
        for (int kk = 0; kk < 16; kk++) {
            float a[8], bb[4];
#pragma unroll
            for (int i = 0; i < 8; i++) a[i] = As[kk][ty * 8 + i];
#pragma unroll
            for (int j = 0; j < 4; j++) bb[j] = Bs[kk][tx * 4 + j];
#pragma unroll
            for (int i = 0; i < 8; i++)
#pragma unroll
                for (int j = 0; j < 4; j++) acc[i][j] += a[i] * bb[j];
        }
        __syncthreads();
    }
#pragma unroll
    for (int i = 0; i < 8; i++) {
        int o = ty * 8 + i;
        float gm   = gamma[o] * rsqrtf(var[o] + 1e-5f);
        float base = gm * (cb[o] - mean[o]) + beta[o];
        float4 v;
        v.x = fmaxf(gm * acc[i][0] + base, 0.f);
        v.y = fmaxf(gm * acc[i][1] + base, 0.f);
        v.z = fmaxf(gm * acc[i][2] + base, 0.f);
        v.w = fmaxf(gm * acc[i][3] + base, 0.f);
        *(float4*)&out[(size_t)b * OC_ * N_ + (size_t)o * N_ + n0 + tx * 4] = v;
    }
}

// ---------------- launch -----------------------------------------------------
extern "C" void kernel_launch(void* const* d_in, const int* in_sizes, int n_in,
                              void* d_out, int out_size) {
    const float* pf     = (const float*)d_in[0];
    const float* img    = (const float*)d_in[1];
    const float* fc2_w  = (const float*)d_in[2];
    const float* fc2_b  = (const float*)d_in[3];
    const float* conv_w = (const float*)d_in[4];
    const float* conv_b = (const float*)d_in[5];
    const float* gamma  = (const float*)d_in[6];
    const float* beta   = (const float*)d_in[7];
    const float* mean   = (const float*)d_in[8];
    const float* var    = (const float*)d_in[9];
    float* out = (float*)d_out;

    k_zero     <<<(B_ * N_ + 511) / 512, 512>>>();
    k_transpose<<<dim3(N_ / 32, PC_ / 32, B_), dim3(32, 8)>>>(pf);
    k_ri       <<<dim3(1, N_ / 64, B_),        dim3(16, 16)>>>(img, fc2_w, fc2_b);
    k_s        <<<dim3(N_ / 128, N_ / 128, B_), 256>>>();
    k_av       <<<dim3(2, N_ / 128, B_),        256>>>();
    k_conv     <<<dim3(N_ / 64, 1, B_),        dim3(16, 16)>>>(conv_w, conv_b, gamma, beta,
                                                               mean, var, out);
}

// round 6
// speedup vs baseline: 1.4997x; 1.4997x over previous
#include <cuda_runtime.h>
#include <math.h>

#define B_   2
#define N_   4096
#define IC_  256
#define PC_  128
#define OC_  128
#define SCALE_ 0.08838834764831845f   // 1/sqrt(128)
#define LDK  20                        // padded row pitch (floats) for ldmatrix tiles

// ---------------- scratch (device globals) ----------------------------------
static __device__ __align__(16) float g_rp  [(size_t)B_ * N_ * PC_];
static __device__ __align__(16) float g_ri  [(size_t)B_ * N_ * PC_];
static __device__ __align__(16) float g_S   [(size_t)B_ * N_ * N_];   // P = exp(scale*S)
static __device__ __align__(16) float g_csum[B_ * N_];
static __device__ __align__(16) float g_rsum[B_ * N_];
static __device__ __align__(16) float g_outp[(size_t)B_ * N_ * PC_];
static __device__ __align__(16) float g_outi[(size_t)B_ * N_ * PC_];

// ---------------- helpers ----------------------------------------------------
__device__ __forceinline__ unsigned tf32_of(float x) {
    unsigned r; asm("cvt.rna.tf32.f32 %0, %1;" : "=r"(r) : "f"(x)); return r;
}
__device__ __forceinline__ uint4 cvt4(float a, float b, float c, float d) {
    return make_uint4(tf32_of(a), tf32_of(b), tf32_of(c), tf32_of(d));
}
__device__ __forceinline__ void mma_tf32(float* c, unsigned a0, unsigned a1,
                                         unsigned a2, unsigned a3,
                                         unsigned b0, unsigned b1) {
    asm volatile(
        "mma.sync.aligned.m16n8k8.row.col.f32.tf32.tf32.f32 "
        "{%0,%1,%2,%3}, {%4,%5,%6,%7}, {%8,%9}, {%0,%1,%2,%3};"
        : "+f"(c[0]), "+f"(c[1]), "+f"(c[2]), "+f"(c[3])
        : "r"(a0), "r"(a1), "r"(a2), "r"(a3), "r"(b0), "r"(b1));
}
__device__ __forceinline__ unsigned smem_u32(const void* p) {
    unsigned a;
    asm("{.reg .u64 t; cvta.to.shared.u64 t, %1; cvt.u32.u64 %0, t;}"
        : "=r"(a) : "l"(p));
    return a;
}
__device__ __forceinline__ void ldsm4(unsigned& r0, unsigned& r1,
                                      unsigned& r2, unsigned& r3, unsigned addr) {
    asm volatile("ldmatrix.sync.aligned.m8n8.x4.shared.b16 {%0,%1,%2,%3}, [%4];"
                 : "=r"(r0), "=r"(r1), "=r"(r2), "=r"(r3) : "r"(addr));
}

// MMA block over a 128x128 tile: 8 warps (wm 2 x wn 4), warp tile 64x32.
#define MMA_TILE_BODY(AsT, BsT)                                              \
    for (int kk = 0; kk < 16; kk += 8) {                                     \
        unsigned a[4][4], bb[4][2];                                          \
        _Pragma("unroll")                                                    \
        for (int mf = 0; mf < 4; mf++)                                       \
            ldsm4(a[mf][0], a[mf][1], a[mf][2], a[mf][3],                    \
                  baseA + (mf * 16 * LDK + kk) * 4u);                        \
        ldsm4(bb[0][0], bb[0][1], bb[1][0], bb[1][1], baseB + kk * 4u);      \
        ldsm4(bb[2][0], bb[2][1], bb[3][0], bb[3][1],                        \
              baseB + (16 * LDK + kk) * 4u);                                 \
        _Pragma("unroll")                                                    \
        for (int mf = 0; mf < 4; mf++)                                       \
            _Pragma("unroll")                                                \
            for (int nf = 0; nf < 4; nf++)                                   \
                mma_tf32(acc[mf][nf], a[mf][0], a[mf][1], a[mf][2], a[mf][3],\
                         bb[nf][0], bb[nf][1]);                              \
    }

// ---------------- kernel 0: zero the sum accumulators ------------------------
__global__ void k_zero() {
    int i = blockIdx.x * blockDim.x + threadIdx.x;
    if (i < B_ * N_) { g_csum[i] = 0.f; g_rsum[i] = 0.f; }
}

// ---------------- kernel 1: transpose point_features [B,PC,N] -> rp [B,N,PC]
__global__ void k_transpose(const float* __restrict__ pf) {
    __shared__ float tile[32][33];
    const int b  = blockIdx.z;
    const int n0 = blockIdx.x * 32;
    const int d0 = blockIdx.y * 32;
    const float* src = pf   + (size_t)b * PC_ * N_;
    float*       dst = g_rp + (size_t)b * N_ * PC_;
    const int tx = threadIdx.x, ty = threadIdx.y;   // (32, 8)
#pragma unroll
    for (int j = 0; j < 32; j += 8)
        tile[ty + j][tx] = src[(size_t)(d0 + ty + j) * N_ + n0 + tx];
    __syncthreads();
#pragma unroll
    for (int j = 0; j < 32; j += 8)
        dst[(size_t)(n0 + ty + j) * PC_ + d0 + tx] = tile[tx][ty + j];
}

// ---------------- kernel 2: ri = img^T @ fc2_w^T + fc2_b  (tf32 mma) ---------
// A[m=n][k=c] = img[c][n] (transpose fill), B[n=d][k=c] = w[d][c] (direct).
__global__ __launch_bounds__(256, 2) void k_ri(const float* __restrict__ img,
                                               const float* __restrict__ w,
                                               const float* __restrict__ bias) {
    const int b  = blockIdx.y;
    const int n0 = blockIdx.x * 128;
    const float* X = img  + (size_t)b * IC_ * N_;
    float*       R = g_ri + (size_t)b * N_ * PC_;

    __shared__ unsigned AsT[128][LDK];
    __shared__ unsigned BsT[128][LDK];

    const int tid  = threadIdx.x;
    const int lane = tid & 31, wid = tid >> 5;
    const int wm = wid & 1, wn = wid >> 1;
    const int g = lane >> 2, t = lane & 3;
    const int jm = lane >> 3;

    const unsigned baseA = smem_u32(&AsT[0][0]) +
        (((wm * 64) + ((jm & 1) * 8) + (lane & 7)) * LDK + ((jm >> 1) * 4)) * 4u;
    const unsigned baseB = smem_u32(&BsT[0][0]) +
        (((wn * 32) + ((jm >> 1) * 8) + (lane & 7)) * LDK + ((jm & 1) * 4)) * 4u;

    const int rowT = (wid & 3) * 32 + lane;     // transpose-fill dest row
    const int kcb  = wid >> 2;                  // k-chunk base (0/1)
    const int fi = tid >> 2, fc = (tid & 3) * 4;// direct-fill coords

    float acc[4][4][4];
#pragma unroll
    for (int mf = 0; mf < 4; mf++)
#pragma unroll
        for (int nf = 0; nf < 4; nf++)
#pragma unroll
            for (int q = 0; q < 4; q++) acc[mf][nf][q] = 0.f;

    float va[2][4]; float4 rb[2];
#pragma unroll
    for (int r = 0; r < 2; r++) {
        int kc = kcb + 2 * r;
#pragma unroll
        for (int j = 0; j < 4; j++)
            va[r][j] = X[(size_t)(kc * 4 + j) * N_ + n0 + rowT];
        rb[r] = *(const float4*)&w[(size_t)(fi + r * 64) * IC_ + fc];
    }

    for (int k0 = 0; k0 < IC_; k0 += 16) {
#pragma unroll
        for (int r = 0; r < 2; r++) {
            int kc = kcb + 2 * r;
            *(uint4*)&AsT[rowT][kc * 4]    = cvt4(va[r][0], va[r][1], va[r][2], va[r][3]);
            *(uint4*)&BsT[fi + r * 64][fc] = cvt4(rb[r].x, rb[r].y, rb[r].z, rb[r].w);
        }
        __syncthreads();
        if (k0 + 16 < IC_) {
            int kn = k0 + 16;
#pragma unroll
            for (int r = 0; r < 2; r++) {
                int kc = kcb + 2 * r;
#pragma unroll
                for (int j = 0; j < 4; j++)
                    va[r][j] = X[(size_t)(kn + kc * 4 + j) * N_ + n0 + rowT];
                rb[r] = *(const float4*)&w[(size_t)(fi + r * 64) * IC_ + kn + fc];
            }
        }
        MMA_TILE_BODY(AsT, BsT)
        __syncthreads();
    }
#pragma unroll
    for (int mf = 0; mf < 4; mf++) {
        int row = n0 + wm * 64 + mf * 16 + g;
#pragma unroll
        for (int nf = 0; nf < 4; nf++) {
            int col = wn * 32 + nf * 8 + 2 * t;
            float b0 = bias[col], b1 = bias[col + 1];
            *(float2*)&R[(size_t)row * PC_ + col] =
                make_float2(acc[mf][nf][0] + b0, acc[mf][nf][1] + b1);
            *(float2*)&R[(size_t)(row + 8) * PC_ + col] =
                make_float2(acc[mf][nf][2] + b0, acc[mf][nf][3] + b1);
        }
    }
}

// ---------------- kernel 3: P = exp(scale * rp @ ri^T) + row/col sums --------
__global__ __launch_bounds__(256, 2) void k_s() {
    const int b  = blockIdx.z;
    const int i0 = blockIdx.y * 128;
    const int j0 = blockIdx.x * 128;
    const float* A  = g_rp + (size_t)b * N_ * PC_;
    const float* Bm = g_ri + (size_t)b * N_ * PC_;
    float*       Pp = g_S  + (size_t)b * N_ * N_;

    __shared__ unsigned AsT[128][LDK];
    __shared__ unsigned BsT[128][LDK];
    __shared__ float shr[128], shc[128];

    const int tid  = threadIdx.x;
    const int lane = tid & 31, wid = tid >> 5;
    const int wm = wid & 1, wn = wid >> 1;
    const int g = lane >> 2, t = lane & 3;
    const int jm = lane >> 3;

    const unsigned baseA = smem_u32(&AsT[0][0]) +
        (((wm * 64) + ((jm & 1) * 8) + (lane & 7)) * LDK + ((jm >> 1) * 4)) * 4u;
    const unsigned baseB = smem_u32(&BsT[0][0]) +
        (((wn * 32) + ((jm >> 1) * 8) + (lane & 7)) * LDK + ((jm & 1) * 4)) * 4u;

    const int fi = tid >> 2, fc = (tid & 3) * 4;

    float acc[4][4][4];
#pragma unroll
    for (int mf = 0; mf < 4; mf++)
#pragma unroll
        for (int nf = 0; nf < 4; nf++)
#pragma unroll
            for (int q = 0; q < 4; q++) acc[mf][nf][q] = 0.f;

    float4 ra[2], rb[2];
#pragma unroll
    for (int r = 0; r < 2; r++) {
        ra[r] = *(const float4*)&A [(size_t)(i0 + fi + r * 64) * PC_ + fc];
        rb[r] = *(const float4*)&Bm[(size_t)(j0 + fi + r * 64) * PC_ + fc];
    }

    for (int k0 = 0; k0 < PC_; k0 += 16) {
#pragma unroll
        for (int r = 0; r < 2; r++) {
            *(uint4*)&AsT[fi + r * 64][fc] = cvt4(ra[r].x, ra[r].y, ra[r].z, ra[r].w);
            *(uint4*)&BsT[fi + r * 64][fc] = cvt4(rb[r].x, rb[r].y, rb[r].z, rb[r].w);
        }
        __syncthreads();
        if (k0 + 16 < PC_) {
#pragma unroll
            for (int r = 0; r < 2; r++) {
                ra[r] = *(const float4*)&A [(size_t)(i0 + fi + r * 64) * PC_ + k0 + 16 + fc];
                rb[r] = *(const float4*)&Bm[(size_t)(j0 + fi + r * 64) * PC_ + k0 + 16 + fc];
            }
        }
        MMA_TILE_BODY(AsT, BsT)
        __syncthreads();
    }

    if (tid < 128) { shr[tid] = 0.f; shc[tid] = 0.f; }
    __syncthreads();

    float rs[4][2] = {{0.f,0.f},{0.f,0.f},{0.f,0.f},{0.f,0.f}};
    float cs[4][2] = {{0.f,0.f},{0.f,0.f},{0.f,0.f},{0.f,0.f}};
#pragma unroll
    for (int mf = 0; mf < 4; mf++) {
        int row = i0 + wm * 64 + mf * 16 + g;
#pragma unroll
        for (int nf = 0; nf < 4; nf++) {
            int col = j0 + wn * 32 + nf * 8 + 2 * t;
            float p0 = __expf(acc[mf][nf][0] * SCALE_);
            float p1 = __expf(acc[mf][nf][1] * SCALE_);
            float p2 = __expf(acc[mf][nf][2] * SCALE_);
            float p3 = __expf(acc[mf][nf][3] * SCALE_);
            *(float2*)&Pp[(size_t)row * N_ + col]       = make_float2(p0, p1);
            *(float2*)&Pp[(size_t)(row + 8) * N_ + col] = make_float2(p2, p3);
            rs[mf][0] += p0 + p1; rs[mf][1] += p2 + p3;
            cs[nf][0] += p0 + p2; cs[nf][1] += p1 + p3;
        }
    }
#pragma unroll
    for (int mf = 0; mf < 4; mf++)
#pragma unroll
        for (int h = 0; h < 2; h++) {
            float v = rs[mf][h];
            v += __shfl_xor_sync(0xffffffffu, v, 1);
            v += __shfl_xor_sync(0xffffffffu, v, 2);
            if (t == 0) atomicAdd(&shr[wm * 64 + mf * 16 + h * 8 + g], v);
        }
#pragma unroll
    for (int nf = 0; nf < 4; nf++)
#pragma unroll
        for (int q = 0; q < 2; q++) {
            float v = cs[nf][q];
            v += __shfl_xor_sync(0xffffffffu, v, 4);
            v += __shfl_xor_sync(0xffffffffu, v, 8);
            v += __shfl_xor_sync(0xffffffffu, v, 16);
            if (g == 0) atomicAdd(&shc[wn * 32 + nf * 8 + 2 * t + q], v);
        }
    __syncthreads();
    if (tid < 128) {
        atomicAdd(&g_rsum[b * N_ + i0 + tid], shr[tid]);
        atomicAdd(&g_csum[b * N_ + j0 + tid], shc[tid]);
    }
}

// ---------------- kernel 4: AV GEMMs (tf32 + ldmatrix, conflict-free fills) --
// mode 0: out_p[i,d] = sum_j P[i,j] * (rp[j,d]/csum[j])
// mode 1: out_i[i,d] = sum_j P[j,i] * (ri[j,d]/rsum[j])
__global__ __launch_bounds__(256, 2) void k_av() {
    const int mode = blockIdx.x;
    const int b    = blockIdx.z;
    const int i0   = blockIdx.y * 128;
    const float* Pp  = g_S + (size_t)b * N_ * N_;
    const float* V   = (mode == 0 ? g_rp : g_ri) + (size_t)b * N_ * PC_;
    const float* sum = (mode == 0 ? g_csum : g_rsum) + b * N_;
    float*       D   = (mode == 0 ? g_outp : g_outi) + (size_t)b * N_ * PC_;

    __shared__ unsigned AsT[128][LDK];
    __shared__ unsigned BsT[128][LDK];

    const int tid  = threadIdx.x;
    const int lane = tid & 31, wid = tid >> 5;
    const int wm = wid & 1, wn = wid >> 1;
    const int g = lane >> 2, t = lane & 3;
    const int jm = lane >> 3;

    const unsigned baseA = smem_u32(&AsT[0][0]) +
        (((wm * 64) + ((jm & 1) * 8) + (lane & 7)) * LDK + ((jm >> 1) * 4)) * 4u;
    const unsigned baseB = smem_u32(&BsT[0][0]) +
        (((wn * 32) + ((jm >> 1) * 8) + (lane & 7)) * LDK + ((jm & 1) * 4)) * 4u;

    const int rowT = (wid & 3) * 32 + lane;     // transpose-fill dest row
    const int kcb  = wid >> 2;
    const int fi = tid >> 2, fc = (tid & 3) * 4;

    float acc[4][4][4];
#pragma unroll
    for (int mf = 0; mf < 4; mf++)
#pragma unroll
        for (int nf = 0; nf < 4; nf++)
#pragma unroll
            for (int q = 0; q < 4; q++) acc[mf][nf][q] = 0.f;

    float va[2][4], vb[2][4];
#pragma unroll
    for (int r = 0; r < 2; r++) {
        int kc = kcb + 2 * r;
        if (mode == 0) {
            float4 v = *(const float4*)&Pp[(size_t)(i0 + fi + r * 64) * N_ + fc];
            va[r][0] = v.x; va[r][1] = v.y; va[r][2] = v.z; va[r][3] = v.w;
        } else {
#pragma unroll
            for (int j = 0; j < 4; j++)
                va[r][j] = Pp[(size_t)(kc * 4 + j) * N_ + i0 + rowT];
        }
        float4 s = *(const float4*)&sum[kc * 4];
        vb[r][0] = V[(size_t)(kc * 4 + 0) * PC_ + rowT] * __fdividef(1.f, s.x);
        vb[r][1] = V[(size_t)(kc * 4 + 1) * PC_ + rowT] * __fdividef(1.f, s.y);
        vb[r][2] = V[(size_t)(kc * 4 + 2) * PC_ + rowT] * __fdividef(1.f, s.z);
        vb[r][3] = V[(size_t)(kc * 4 + 3) * PC_ + rowT] * __fdividef(1.f, s.w);
    }

    for (int k0 = 0; k0 < N_; k0 += 16) {
#pragma unroll
        for (int r = 0; r < 2; r++) {
            int kc = kcb + 2 * r;
            if (mode == 0)
                *(uint4*)&AsT[fi + r * 64][fc] = cvt4(va[r][0], va[r][1], va[r][2], va[r][3]);
            else
                *(uint4*)&AsT[rowT][kc * 4]    = cvt4(va[r][0], va[r][1], va[r][2], va[r][3]);
            *(uint4*)&BsT[rowT][kc * 4]        = cvt4(vb[r][0], vb[r][1], vb[r][2], vb[r][3]);
        }
        __syncthreads();
        if (k0 + 16 < N_) {
            int kn = k0 + 16;
#pragma unroll
            for (int r = 0; r < 2; r++) {
                int kc = kcb + 2 * r;
                if (mode == 0) {
                    float4 v = *(const float4*)&Pp[(size_t)(i0 + fi + r * 64) * N_ + kn + fc];
                    va[r][0] = v.x; va[r][1] = v.y; va[r][2] = v.z; va[r][3] = v.w;
                } else {
#pragma unroll
                    for (int j = 0; j < 4; j++)
                        va[r][j] = Pp[(size_t)(kn + kc * 4 + j) * N_ + i0 + rowT];
                }
                float4 s = *(const float4*)&sum[kn + kc * 4];
                vb[r][0] = V[(size_t)(kn + kc * 4 + 0) * PC_ + rowT] * __fdividef(1.f, s.x);
                vb[r][1] = V[(size_t)(kn + kc * 4 + 1) * PC_ + rowT] * __fdividef(1.f, s.y);
                vb[r][2] = V[(size_t)(kn + kc * 4 + 2) * PC_ + rowT] * __fdividef(1.f, s.z);
                vb[r][3] = V[(size_t)(kn + kc * 4 + 3) * PC_ + rowT] * __fdividef(1.f, s.w);
            }
        }
        MMA_TILE_BODY(AsT, BsT)
        __syncthreads();
    }
#pragma unroll
    for (int mf = 0; mf < 4; mf++) {
        int row = i0 + wm * 64 + mf * 16 + g;
#pragma unroll
        for (int nf = 0; nf < 4; nf++) {
            int col = wn * 32 + nf * 8 + 2 * t;
            *(float2*)&D[(size_t)row * PC_ + col]       = make_float2(acc[mf][nf][0], acc[mf][nf][1]);
            *(float2*)&D[(size_t)(row + 8) * PC_ + col] = make_float2(acc[mf][nf][2], acc[mf][nf][3]);
        }
    }
}

// ---------------- kernel 5: conv1d(k=1)+BN+ReLU  (tf32 mma) ------------------
// A[m=o][k=c] = conv_w direct; B[n][k=c] = fusion[n][c] direct.
__global__ __launch_bounds__(256, 2) void k_conv(const float* __restrict__ w,
                                                 const float* __restrict__ cb,
                                                 const float* __restrict__ gamma,
                                                 const float* __restrict__ beta,
                                                 const float* __restrict__ mean,
                                                 const float* __restrict__ var,
                                                 float* __restrict__ out) {
    const int b  = blockIdx.y;
    const int n0 = blockIdx.x * 128;
    const float* P = g_outp + (size_t)b * N_ * PC_;
    const float* I = g_outi + (size_t)b * N_ * PC_;

    __shared__ unsigned AsT[128][LDK];
    __shared__ unsigned BsT[128][LDK];

    const int tid  = threadIdx.x;
    const int lane = tid & 31, wid = tid >> 5;
    const int wm = wid & 1, wn = wid >> 1;
    const int g = lane >> 2, t = lane & 3;
    const int jm = lane >> 3;

    const unsigned baseA = smem_u32(&AsT[0][0]) +
        (((wm * 64) + ((jm & 1) * 8) + (lane & 7)) * LDK + ((jm >> 1) * 4)) * 4u;
    const unsigned baseB = smem_u32(&BsT[0][0]) +
        (((wn * 32) + ((jm >> 1) * 8) + (lane & 7)) * LDK + ((jm & 1) * 4)) * 4u;

    const int fi = tid >> 2, fc = (tid & 3) * 4;

    float acc[4][4][4];
#pragma unroll
    for (int mf = 0; mf < 4; mf++)
#pragma unroll
        for (int nf = 0; nf < 4; nf++)
#pragma unroll
            for (int q = 0; q < 4; q++) acc[mf][nf][q] = 0.f;

    float4 ra[2], rb[2];
#pragma unroll
    for (int r = 0; r < 2; r++) {
        ra[r] = *(const float4*)&w[(size_t)(fi + r * 64) * (2 * PC_) + fc];
        rb[r] = *(const float4*)&P[(size_t)(n0 + fi + r * 64) * PC_ + fc];
    }

    for (int k0 = 0; k0 < 2 * PC_; k0 += 16) {
#pragma unroll
        for (int r = 0; r < 2; r++) {
            *(uint4*)&AsT[fi + r * 64][fc] = cvt4(ra[r].x, ra[r].y, ra[r].z, ra[r].w);
            *(uint4*)&BsT[fi + r * 64][fc] = cvt4(rb[r].x, rb[r].y, rb[r].z, rb[r].w);
        }
        __syncthreads();
        if (k0 + 16 < 2 * PC_) {
            int kn = k0 + 16;
#pragma unroll
            for (int r = 0; r < 2; r++) {
                ra[r] = *(const float4*)&w[(size_t)(fi + r * 64) * (2 * PC_) + kn + fc];
                const float* src = (kn < PC_)
                    ? &P[(size_t)(n0 + fi + r * 64) * PC_ + kn + fc]
                    : &I[(size_t)(n0 + fi + r * 64) * PC_ + kn - PC_ + fc];
                rb[r] = *(const float4*)src;
            }
        }
        MMA_TILE_BODY(AsT, BsT)
        __syncthreads();
    }
#pragma unroll
    for (int mf = 0; mf < 4; mf++) {
        int o0 = wm * 64 + mf * 16 + g;
        int o1 = o0 + 8;
        float gm0 = gamma[o0] * rsqrtf(var[o0] + 1e-5f);
        float gm1 = gamma[o1] * rsqrtf(var[o1] + 1e-5f);
        float ba0 = gm0 * (cb[o0] - mean[o0]) + beta[o0];
        float ba1 = gm1 * (cb[o1] - mean[o1]) + beta[o1];
        float* out0 = out + (size_t)b * OC_ * N_ + (size_t)o0 * N_;
        float* out1 = out + (size_t)b * OC_ * N_ + (size_t)o1 * N_;
#pragma unroll
        for (int nf = 0; nf < 4; nf++) {
            int col = n0 + wn * 32 + nf * 8 + 2 * t;
            *(float2*)&out0[col] = make_float2(
                fmaxf(gm0 * acc[mf][nf][0] + ba0, 0.f),
                fmaxf(gm0 * acc[mf][nf][1] + ba0, 0.f));
            *(float2*)&out1[col] = make_float2(
                fmaxf(gm1 * acc[mf][nf][2] + ba1, 0.f),
                fmaxf(gm1 * acc[mf][nf][3] + ba1, 0.f));
        }
    }
}

// ---------------- launch -----------------------------------------------------
extern "C" void kernel_launch(void* const* d_in, const int* in_sizes, int n_in,
                              void* d_out, int out_size) {
    const float* pf     = (const float*)d_in[0];
    const float* img    = (const float*)d_in[1];
    const float* fc2_w  = (const float*)d_in[2];
    const float* fc2_b  = (const float*)d_in[3];
    const float* conv_w = (const float*)d_in[4];
    const float* conv_b = (const float*)d_in[5];
    const float* gamma  = (const float*)d_in[6];
    const float* beta   = (const float*)d_in[7];
    const float* mean   = (const float*)d_in[8];
    const float* var    = (const float*)d_in[9];
    float* out = (float*)d_out;

    k_zero     <<<(B_ * N_ + 511) / 512, 512>>>();
    k_transpose<<<dim3(N_ / 32, PC_ / 32, B_), dim3(32, 8)>>>(pf);
    k_ri       <<<dim3(N_ / 128, B_),           256>>>(img, fc2_w, fc2_b);
    k_s        <<<dim3(N_ / 128, N_ / 128, B_), 256>>>();
    k_av       <<<dim3(2, N_ / 128, B_),        256>>>();
    k_conv     <<<dim3(N_ / 128, B_),           256>>>(conv_w, conv_b, gamma, beta,
                                                       mean, var, out);
}

// round 7
// speedup vs baseline: 1.5339x; 1.0228x over previous
#include <cuda_runtime.h>
#include <math.h>

#define B_   2
#define N_   4096
#define IC_  256
#define PC_  128
#define OC_  128
#define SCALE_ 0.08838834764831845f   // 1/sqrt(128)
#define LDK  20                        // padded row pitch (floats) for ldmatrix tiles
#define BUFB (128u * LDK * 4u)         // bytes per smem buffer plane

// ---------------- scratch (device globals) ----------------------------------
static __device__ __align__(16) float g_rp  [(size_t)B_ * N_ * PC_];
static __device__ __align__(16) float g_ri  [(size_t)B_ * N_ * PC_];
static __device__ __align__(16) float g_S   [(size_t)B_ * N_ * N_];   // P = exp(scale*S)
static __device__ __align__(16) float g_csum[B_ * N_];
static __device__ __align__(16) float g_rsum[B_ * N_];
static __device__ __align__(16) float g_outp[(size_t)B_ * N_ * PC_];
static __device__ __align__(16) float g_outi[(size_t)B_ * N_ * PC_];

// ---------------- helpers ----------------------------------------------------
__device__ __forceinline__ unsigned tf32_of(float x) {
    unsigned r; asm("cvt.rna.tf32.f32 %0, %1;" : "=r"(r) : "f"(x)); return r;
}
__device__ __forceinline__ uint4 cvt4(float a, float b, float c, float d) {
    return make_uint4(tf32_of(a), tf32_of(b), tf32_of(c), tf32_of(d));
}
__device__ __forceinline__ void mma_tf32(float* c, unsigned a0, unsigned a1,
                                         unsigned a2, unsigned a3,
                                         unsigned b0, unsigned b1) {
    asm volatile(
        "mma.sync.aligned.m16n8k8.row.col.f32.tf32.tf32.f32 "
        "{%0,%1,%2,%3}, {%4,%5,%6,%7}, {%8,%9}, {%0,%1,%2,%3};"
        : "+f"(c[0]), "+f"(c[1]), "+f"(c[2]), "+f"(c[3])
        : "r"(a0), "r"(a1), "r"(a2), "r"(a3), "r"(b0), "r"(b1));
}
__device__ __forceinline__ unsigned smem_u32(const void* p) {
    unsigned a;
    asm("{.reg .u64 t; cvta.to.shared.u64 t, %1; cvt.u32.u64 %0, t;}"
        : "=r"(a) : "l"(p));
    return a;
}
__device__ __forceinline__ void ldsm4(unsigned& r0, unsigned& r1,
                                      unsigned& r2, unsigned& r3, unsigned addr) {
    asm volatile("ldmatrix.sync.aligned.m8n8.x4.shared.b16 {%0,%1,%2,%3}, [%4];"
                 : "=r"(r0), "=r"(r1), "=r"(r2), "=r"(r3) : "r"(addr));
}

// MMA block over a 128x128 tile from buffer plane at byte offset `off`.
#define MMA_TILE_BODY(off)                                                   \
    for (int kk = 0; kk < 16; kk += 8) {                                     \
        unsigned a[4][4], bb[4][2];                                          \
        _Pragma("unroll")                                                    \
        for (int mf = 0; mf < 4; mf++)                                       \
            ldsm4(a[mf][0], a[mf][1], a[mf][2], a[mf][3],                    \
                  baseA + (off) + (mf * 16 * LDK + kk) * 4u);                \
        ldsm4(bb[0][0], bb[0][1], bb[1][0], bb[1][1],                        \
              baseB + (off) + kk * 4u);                                      \
        ldsm4(bb[2][0], bb[2][1], bb[3][0], bb[3][1],                        \
              baseB + (off) + (16 * LDK + kk) * 4u);                         \
        _Pragma("unroll")                                                    \
        for (int mf = 0; mf < 4; mf++)                                       \
            _Pragma("unroll")                                                \
            for (int nf = 0; nf < 4; nf++)                                   \
                mma_tf32(acc[mf][nf], a[mf][0], a[mf][1], a[mf][2], a[mf][3],\
                         bb[nf][0], bb[nf][1]);                              \
    }

// ---------------- kernel 0: zero the sum accumulators ------------------------
__global__ void k_zero() {
    int i = blockIdx.x * blockDim.x + threadIdx.x;
    if (i < B_ * N_) { g_csum[i] = 0.f; g_rsum[i] = 0.f; }
}

// ---------------- kernel 1: transpose point_features [B,PC,N] -> rp [B,N,PC]
__global__ void k_transpose(const float* __restrict__ pf) {
    __shared__ float tile[32][33];
    const int b  = blockIdx.z;
    const int n0 = blockIdx.x * 32;
    const int d0 = blockIdx.y * 32;
    const float* src = pf   + (size_t)b * PC_ * N_;
    float*       dst = g_rp + (size_t)b * N_ * PC_;
    const int tx = threadIdx.x, ty = threadIdx.y;   // (32, 8)
#pragma unroll
    for (int j = 0; j < 32; j += 8)
        tile[ty + j][tx] = src[(size_t)(d0 + ty + j) * N_ + n0 + tx];
    __syncthreads();
#pragma unroll
    for (int j = 0; j < 32; j += 8)
        dst[(size_t)(n0 + ty + j) * PC_ + d0 + tx] = tile[tx][ty + j];
}

// ---------------- kernel 2: ri = img^T @ fc2_w^T + fc2_b  (tf32 mma, 2-buf) --
__global__ __launch_bounds__(256, 2) void k_ri(const float* __restrict__ img,
                                               const float* __restrict__ w,
                                               const float* __restrict__ bias) {
    const int b  = blockIdx.y;
    const int n0 = blockIdx.x * 128;
    const float* X = img  + (size_t)b * IC_ * N_;
    float*       R = g_ri + (size_t)b * N_ * PC_;

    __shared__ unsigned AsT[2][128][LDK];
    __shared__ unsigned BsT[2][128][LDK];

    const int tid  = threadIdx.x;
    const int lane = tid & 31, wid = tid >> 5;
    const int wm = wid & 1, wn = wid >> 1;
    const int g = lane >> 2, t = lane & 3;
    const int jm = lane >> 3;

    const unsigned baseA = smem_u32(&AsT[0][0][0]) +
        (((wm * 64) + ((jm & 1) * 8) + (lane & 7)) * LDK + ((jm >> 1) * 4)) * 4u;
    const unsigned baseB = smem_u32(&BsT[0][0][0]) +
        (((wn * 32) + ((jm >> 1) * 8) + (lane & 7)) * LDK + ((jm & 1) * 4)) * 4u;

    const int rowT = (wid & 3) * 32 + lane;     // transpose-fill dest row
    const int kcb  = wid >> 2;                  // k-chunk base (0/1)
    const int fi = tid >> 2, fc = (tid & 3) * 4;// direct-fill coords

    float acc[4][4][4];
#pragma unroll
    for (int mf = 0; mf < 4; mf++)
#pragma unroll
        for (int nf = 0; nf < 4; nf++)
#pragma unroll
            for (int q = 0; q < 4; q++) acc[mf][nf][q] = 0.f;

    float va[2][4]; float4 rb[2];
#pragma unroll
    for (int r = 0; r < 2; r++) {
        int kc = kcb + 2 * r;
#pragma unroll
        for (int j = 0; j < 4; j++)
            va[r][j] = X[(size_t)(kc * 4 + j) * N_ + n0 + rowT];
        rb[r] = *(const float4*)&w[(size_t)(fi + r * 64) * IC_ + fc];
    }

    int p = 0;
    for (int k0 = 0; k0 < IC_; k0 += 16) {
#pragma unroll
        for (int r = 0; r < 2; r++) {
            int kc = kcb + 2 * r;
            *(uint4*)&AsT[p][rowT][kc * 4]    = cvt4(va[r][0], va[r][1], va[r][2], va[r][3]);
            *(uint4*)&BsT[p][fi + r * 64][fc] = cvt4(rb[r].x, rb[r].y, rb[r].z, rb[r].w);
        }
        __syncthreads();
        if (k0 + 16 < IC_) {
            int kn = k0 + 16;
#pragma unroll
            for (int r = 0; r < 2; r++) {
                int kc = kcb + 2 * r;
#pragma unroll
                for (int j = 0; j < 4; j++)
                    va[r][j] = X[(size_t)(kn + kc * 4 + j) * N_ + n0 + rowT];
                rb[r] = *(const float4*)&w[(size_t)(fi + r * 64) * IC_ + kn + fc];
            }
        }
        const unsigned off = p * BUFB;
        MMA_TILE_BODY(off)
        p ^= 1;
    }
#pragma unroll
    for (int mf = 0; mf < 4; mf++) {
        int row = n0 + wm * 64 + mf * 16 + g;
#pragma unroll
        for (int nf = 0; nf < 4; nf++) {
            int col = wn * 32 + nf * 8 + 2 * t;
            float b0 = bias[col], b1 = bias[col + 1];
            *(float2*)&R[(size_t)row * PC_ + col] =
                make_float2(acc[mf][nf][0] + b0, acc[mf][nf][1] + b1);
            *(float2*)&R[(size_t)(row + 8) * PC_ + col] =
                make_float2(acc[mf][nf][2] + b0, acc[mf][nf][3] + b1);
        }
    }
}

// ---------------- kernel 3: P = exp(scale * rp @ ri^T) + row/col sums --------
__global__ __launch_bounds__(256, 2) void k_s() {
    const int b  = blockIdx.z;
    const int i0 = blockIdx.y * 128;
    const int j0 = blockIdx.x * 128;
    const float* A  = g_rp + (size_t)b * N_ * PC_;
    const float* Bm = g_ri + (size_t)b * N_ * PC_;
    float*       Pp = g_S  + (size_t)b * N_ * N_;

    __shared__ unsigned AsT[2][128][LDK];
    __shared__ unsigned BsT[2][128][LDK];
    __shared__ float shr[128], shc[128];

    const int tid  = threadIdx.x;
    const int lane = tid & 31, wid = tid >> 5;
    const int wm = wid & 1, wn = wid >> 1;
    const int g = lane >> 2, t = lane & 3;
    const int jm = lane >> 3;

    const unsigned baseA = smem_u32(&AsT[0][0][0]) +
        (((wm * 64) + ((jm & 1) * 8) + (lane & 7)) * LDK + ((jm >> 1) * 4)) * 4u;
    const unsigned baseB = smem_u32(&BsT[0][0][0]) +
        (((wn * 32) + ((jm >> 1) * 8) + (lane & 7)) * LDK + ((jm & 1) * 4)) * 4u;

    const int fi = tid >> 2, fc = (tid & 3) * 4;

    float acc[4][4][4];
#pragma unroll
    for (int mf = 0; mf < 4; mf++)
#pragma unroll
        for (int nf = 0; nf < 4; nf++)
#pragma unroll
            for (int q = 0; q < 4; q++) acc[mf][nf][q] = 0.f;

    float4 ra[2], rb[2];
#pragma unroll
    for (int r = 0; r < 2; r++) {
        ra[r] = *(const float4*)&A [(size_t)(i0 + fi + r * 64) * PC_ + fc];
        rb[r] = *(const float4*)&Bm[(size_t)(j0 + fi + r * 64) * PC_ + fc];
    }

    int p = 0;
    for (int k0 = 0; k0 < PC_; k0 += 16) {
#pragma unroll
        for (int r = 0; r < 2; r++) {
            *(uint4*)&AsT[p][fi + r * 64][fc] = cvt4(ra[r].x, ra[r].y, ra[r].z, ra[r].w);
            *(uint4*)&BsT[p][fi + r * 64][fc] = cvt4(rb[r].x, rb[r].y, rb[r].z, rb[r].w);
        }
        __syncthreads();
        if (k0 + 16 < PC_) {
#pragma unroll
            for (int r = 0; r < 2; r++) {
                ra[r] = *(const float4*)&A [(size_t)(i0 + fi + r * 64) * PC_ + k0 + 16 + fc];
                rb[r] = *(const float4*)&Bm[(size_t)(j0 + fi + r * 64) * PC_ + k0 + 16 + fc];
            }
        }
        const unsigned off = p * BUFB;
        MMA_TILE_BODY(off)
        p ^= 1;
    }

    if (tid < 128) { shr[tid] = 0.f; shc[tid] = 0.f; }
    __syncthreads();

    float rs[4][2] = {{0.f,0.f},{0.f,0.f},{0.f,0.f},{0.f,0.f}};
    float cs[4][2] = {{0.f,0.f},{0.f,0.f},{0.f,0.f},{0.f,0.f}};
#pragma unroll
    for (int mf = 0; mf < 4; mf++) {
        int row = i0 + wm * 64 + mf * 16 + g;
#pragma unroll
        for (int nf = 0; nf < 4; nf++) {
            int col = j0 + wn * 32 + nf * 8 + 2 * t;
            float p0 = __expf(acc[mf][nf][0] * SCALE_);
            float p1 = __expf(acc[mf][nf][1] * SCALE_);
            float p2 = __expf(acc[mf][nf][2] * SCALE_);
            float p3 = __expf(acc[mf][nf][3] * SCALE_);
            *(float2*)&Pp[(size_t)row * N_ + col]       = make_float2(p0, p1);
            *(float2*)&Pp[(size_t)(row + 8) * N_ + col] = make_float2(p2, p3);
            rs[mf][0] += p0 + p1; rs[mf][1] += p2 + p3;
            cs[nf][0] += p0 + p2; cs[nf][1] += p1 + p3;
        }
    }
#pragma unroll
    for (int mf = 0; mf < 4; mf++)
#pragma unroll
        for (int h = 0; h < 2; h++) {
            float v = rs[mf][h];
            v += __shfl_xor_sync(0xffffffffu, v, 1);
            v += __shfl_xor_sync(0xffffffffu, v, 2);
            if (t == 0) atomicAdd(&shr[wm * 64 + mf * 16 + h * 8 + g], v);
        }
#pragma unroll
    for (int nf = 0; nf < 4; nf++)
#pragma unroll
        for (int q = 0; q < 2; q++) {
            float v = cs[nf][q];
            v += __shfl_xor_sync(0xffffffffu, v, 4);
            v += __shfl_xor_sync(0xffffffffu, v, 8);
            v += __shfl_xor_sync(0xffffffffu, v, 16);
            if (g == 0) atomicAdd(&shc[wn * 32 + nf * 8 + 2 * t + q], v);
        }
    __syncthreads();
    if (tid < 128) {
        atomicAdd(&g_rsum[b * N_ + i0 + tid], shr[tid]);
        atomicAdd(&g_csum[b * N_ + j0 + tid], shc[tid]);
    }
}

// ---------------- kernel 4: AV GEMMs (tf32 + ldmatrix, 2-buf pipeline) -------
// mode 0: out_p[i,d] = sum_j P[i,j] * (rp[j,d]/csum[j])
// mode 1: out_i[i,d] = sum_j P[j,i] * (ri[j,d]/rsum[j])
__global__ __launch_bounds__(256, 2) void k_av() {
    const int mode = blockIdx.x;
    const int b    = blockIdx.z;
    const int i0   = blockIdx.y * 128;
    const float* Pp  = g_S + (size_t)b * N_ * N_;
    const float* V   = (mode == 0 ? g_rp : g_ri) + (size_t)b * N_ * PC_;
    const float* sum = (mode == 0 ? g_csum : g_rsum) + b * N_;
    float*       D   = (mode == 0 ? g_outp : g_outi) + (size_t)b * N_ * PC_;

    __shared__ unsigned AsT[2][128][LDK];
    __shared__ unsigned BsT[2][128][LDK];

    const int tid  = threadIdx.x;
    const int lane = tid & 31, wid = tid >> 5;
    const int wm = wid & 1, wn = wid >> 1;
    const int g = lane >> 2, t = lane & 3;
    const int jm = lane >> 3;

    const unsigned baseA = smem_u32(&AsT[0][0][0]) +
        (((wm * 64) + ((jm & 1) * 8) + (lane & 7)) * LDK + ((jm >> 1) * 4)) * 4u;
    const unsigned baseB = smem_u32(&BsT[0][0][0]) +
        (((wn * 32) + ((jm >> 1) * 8) + (lane & 7)) * LDK + ((jm & 1) * 4)) * 4u;

    const int rowT = (wid & 3) * 32 + lane;     // transpose-fill dest row
    const int kcb  = wid >> 2;
    const int fi = tid >> 2, fc = (tid & 3) * 4;

    float acc[4][4][4];
#pragma unroll
    for (int mf = 0; mf < 4; mf++)
#pragma unroll
        for (int nf = 0; nf < 4; nf++)
#pragma unroll
            for (int q = 0; q < 4; q++) acc[mf][nf][q] = 0.f;

    float va[2][4], vb[2][4];
#pragma unroll
    for (int r = 0; r < 2; r++) {
        int kc = kcb + 2 * r;
        if (mode == 0) {
            float4 v = *(const float4*)&Pp[(size_t)(i0 + fi + r * 64) * N_ + fc];
            va[r][0] = v.x; va[r][1] = v.y; va[r][2] = v.z; va[r][3] = v.w;
        } else {
#pragma unroll
            for (int j = 0; j < 4; j++)
                va[r][j] = Pp[(size_t)(kc * 4 + j) * N_ + i0 + rowT];
        }
        float4 s = *(const float4*)&sum[kc * 4];
        vb[r][0] = V[(size_t)(kc * 4 + 0) * PC_ + rowT] * __fdividef(1.f, s.x);
        vb[r][1] = V[(size_t)(kc * 4 + 1) * PC_ + rowT] * __fdividef(1.f, s.y);
        vb[r][2] = V[(size_t)(kc * 4 + 2) * PC_ + rowT] * __fdividef(1.f, s.z);
        vb[r][3] = V[(size_t)(kc * 4 + 3) * PC_ + rowT] * __fdividef(1.f, s.w);
    }

    int p = 0;
    for (int k0 = 0; k0 < N_; k0 += 16) {
#pragma unroll
        for (int r = 0; r < 2; r++) {
            int kc = kcb + 2 * r;
            if (mode == 0)
                *(uint4*)&AsT[p][fi + r * 64][fc] = cvt4(va[r][0], va[r][1], va[r][2], va[r][3]);
            else
                *(uint4*)&AsT[p][rowT][kc * 4]    = cvt4(va[r][0], va[r][1], va[r][2], va[r][3]);
            *(uint4*)&BsT[p][rowT][kc * 4]        = cvt4(vb[r][0], vb[r][1], vb[r][2], vb[r][3]);
        }
        __syncthreads();
        if (k0 + 16 < N_) {
            int kn = k0 + 16;
#pragma unroll
            for (int r = 0; r < 2; r++) {
                int kc = kcb + 2 * r;
                if (mode == 0) {
                    float4 v = *(const float4*)&Pp[(size_t)(i0 + fi + r * 64) * N_ + kn + fc];
                    va[r][0] = v.x; va[r][1] = v.y; va[r][2] = v.z; va[r][3] = v.w;
                } else {
#pragma unroll
                    for (int j = 0; j < 4; j++)
                        va[r][j] = Pp[(size_t)(kn + kc * 4 + j) * N_ + i0 + rowT];
                }
                float4 s = *(const float4*)&sum[kn + kc * 4];
                vb[r][0] = V[(size_t)(kn + kc * 4 + 0) * PC_ + rowT] * __fdividef(1.f, s.x);
                vb[r][1] = V[(size_t)(kn + kc * 4 + 1) * PC_ + rowT] * __fdividef(1.f, s.y);
                vb[r][2] = V[(size_t)(kn + kc * 4 + 2) * PC_ + rowT] * __fdividef(1.f, s.z);
                vb[r][3] = V[(size_t)(kn + kc * 4 + 3) * PC_ + rowT] * __fdividef(1.f, s.w);
            }
        }
        const unsigned off = p * BUFB;
        MMA_TILE_BODY(off)
        p ^= 1;
    }
#pragma unroll
    for (int mf = 0; mf < 4; mf++) {
        int row = i0 + wm * 64 + mf * 16 + g;
#pragma unroll
        for (int nf = 0; nf < 4; nf++) {
            int col = wn * 32 + nf * 8 + 2 * t;
            *(float2*)&D[(size_t)row * PC_ + col]       = make_float2(acc[mf][nf][0], acc[mf][nf][1]);
            *(float2*)&D[(size_t)(row + 8) * PC_ + col] = make_float2(acc[mf][nf][2], acc[mf][nf][3]);
        }
    }
}

// ---------------- kernel 5: conv1d(k=1)+BN+ReLU  (tf32 mma, 2-buf) -----------
__global__ __launch_bounds__(256, 2) void k_conv(const float* __restrict__ w,
                                                 const float* __restrict__ cb,
                                                 const float* __restrict__ gamma,
                                                 const float* __restrict__ beta,
                                                 const float* __restrict__ mean,
                                                 const float* __restrict__ var,
                                                 float* __restrict__ out) {
    const int b  = blockIdx.y;
    const int n0 = blockIdx.x * 128;
    const float* P = g_outp + (size_t)b * N_ * PC_;
    const float* I = g_outi + (size_t)b * N_ * PC_;

    __shared__ unsigned AsT[2][128][LDK];
    __shared__ unsigned BsT[2][128][LDK];

    const int tid  = threadIdx.x;
    const int lane = tid & 31, wid = tid >> 5;
    const int wm = wid & 1, wn = wid >> 1;
    const int g = lane >> 2, t = lane & 3;
    const int jm = lane >> 3;

    const unsigned baseA = smem_u32(&AsT[0][0][0]) +
        (((wm * 64) + ((jm & 1) * 8) + (lane & 7)) * LDK + ((jm >> 1) * 4)) * 4u;
    const unsigned baseB = smem_u32(&BsT[0][0][0]) +
        (((wn * 32) + ((jm >> 1) * 8) + (lane & 7)) * LDK + ((jm & 1) * 4)) * 4u;

    const int fi = tid >> 2, fc = (tid & 3) * 4;

    float acc[4][4][4];
#pragma unroll
    for (int mf = 0; mf < 4; mf++)
#pragma unroll
        for (int nf = 0; nf < 4; nf++)
#pragma unroll
            for (int q = 0; q < 4; q++) acc[mf][nf][q] = 0.f;

    float4 ra[2], rb[2];
#pragma unroll
    for (int r = 0; r < 2; r++) {
        ra[r] = *(const float4*)&w[(size_t)(fi + r * 64) * (2 * PC_) + fc];
        rb[r] = *(const float4*)&P[(size_t)(n0 + fi + r * 64) * PC_ + fc];
    }

    int p = 0;
    for (int k0 = 0; k0 < 2 * PC_; k0 += 16) {
#pragma unroll
        for (int r = 0; r < 2; r++) {
            *(uint4*)&AsT[p][fi + r * 64][fc] = cvt4(ra[r].x, ra[r].y, ra[r].z, ra[r].w);
            *(uint4*)&BsT[p][fi + r * 64][fc] = cvt4(rb[r].x, rb[r].y, rb[r].z, rb[r].w);
        }
        __syncthreads();
        if (k0 + 16 < 2 * PC_) {
            int kn = k0 + 16;
#pragma unroll
            for (int r = 0; r < 2; r++) {
                ra[r] = *(const float4*)&w[(size_t)(fi + r * 64) * (2 * PC_) + kn + fc];
                const float* src = (kn < PC_)
                    ? &P[(size_t)(n0 + fi + r * 64) * PC_ + kn + fc]
                    : &I[(size_t)(n0 + fi + r * 64) * PC_ + kn - PC_ + fc];
                rb[r] = *(const float4*)src;
            }
        }
        const unsigned off = p * BUFB;
        MMA_TILE_BODY(off)
        p ^= 1;
    }
#pragma unroll
    for (int mf = 0; mf < 4; mf++) {
        int o0 = wm * 64 + mf * 16 + g;
        int o1 = o0 + 8;
        float gm0 = gamma[o0] * rsqrtf(var[o0] + 1e-5f);
        float gm1 = gamma[o1] * rsqrtf(var[o1] + 1e-5f);
        float ba0 = gm0 * (cb[o0] - mean[o0]) + beta[o0];
        float ba1 = gm1 * (cb[o1] - mean[o1]) + beta[o1];
        float* out0 = out + (size_t)b * OC_ * N_ + (size_t)o0 * N_;
        float* out1 = out + (size_t)b * OC_ * N_ + (size_t)o1 * N_;
#pragma unroll
        for (int nf = 0; nf < 4; nf++) {
            int col = n0 + wn * 32 + nf * 8 + 2 * t;
            *(float2*)&out0[col] = make_float2(
                fmaxf(gm0 * acc[mf][nf][0] + ba0, 0.f),
                fmaxf(gm0 * acc[mf][nf][1] + ba0, 0.f));
            *(float2*)&out1[col] = make_float2(
                fmaxf(gm1 * acc[mf][nf][2] + ba1, 0.f),
                fmaxf(gm1 * acc[mf][nf][3] + ba1, 0.f));
        }
    }
}

// ---------------- launch -----------------------------------------------------
extern "C" void kernel_launch(void* const* d_in, const int* in_sizes, int n_in,
                              void* d_out, int out_size) {
    const float* pf     = (const float*)d_in[0];
    const float* img    = (const float*)d_in[1];
    const float* fc2_w  = (const float*)d_in[2];
    const float* fc2_b  = (const float*)d_in[3];
    const float* conv_w = (const float*)d_in[4];
    const float* conv_b = (const float*)d_in[5];
    const float* gamma  = (const float*)d_in[6];
    const float* beta   = (const float*)d_in[7];
    const float* mean   = (const float*)d_in[8];
    const float* var    = (const float*)d_in[9];
    float* out = (float*)d_out;

    k_zero     <<<(B_ * N_ + 511) / 512, 512>>>();
    k_transpose<<<dim3(N_ / 32, PC_ / 32, B_), dim3(32, 8)>>>(pf);
    k_ri       <<<dim3(N_ / 128, B_),           256>>>(img, fc2_w, fc2_b);
    k_s        <<<dim3(N_ / 128, N_ / 128, B_), 256>>>();
    k_av       <<<dim3(2, N_ / 128, B_),        256>>>();
    k_conv     <<<dim3(N_ / 128, B_),           256>>>(conv_w, conv_b, gamma, beta,
                                                       mean, var, out);
}

// round 8
// speedup vs baseline: 2.3500x; 1.5321x over previous
#include <cuda_runtime.h>
#include <math.h>

#define B_   2
#define N_   4096
#define IC_  256
#define PC_  128
#define OC_  128
#define SCALE_ 0.08838834764831845f   // 1/sqrt(128)
#define LDK  20                        // padded row pitch (floats) for ldmatrix tiles
#define BUFB (128u * LDK * 4u)         // bytes per smem buffer plane
#define KSPL (N_ / 4)                  // k-range per k_av split

// ---------------- scratch (device globals) ----------------------------------
static __device__ __align__(16) float g_rp  [(size_t)B_ * N_ * PC_];
static __device__ __align__(16) float g_ri  [(size_t)B_ * N_ * PC_];
static __device__ __align__(16) float g_S   [(size_t)B_ * N_ * N_];   // P = exp(scale*S)
static __device__ __align__(16) float g_csum[B_ * N_];
static __device__ __align__(16) float g_rsum[B_ * N_];
static __device__ __align__(16) float g_vp  [(size_t)B_ * N_ * OC_]; // (rp@Wp^T)/csum
static __device__ __align__(16) float g_vi  [(size_t)B_ * N_ * OC_]; // (ri@Wi^T)/rsum
static __device__ __align__(16) float g_d   [8][(size_t)B_ * N_ * OC_]; // partials

// ---------------- helpers ----------------------------------------------------
__device__ __forceinline__ unsigned tf32_of(float x) {
    unsigned r; asm("cvt.rna.tf32.f32 %0, %1;" : "=r"(r) : "f"(x)); return r;
}
__device__ __forceinline__ uint4 cvt4(float a, float b, float c, float d) {
    return make_uint4(tf32_of(a), tf32_of(b), tf32_of(c), tf32_of(d));
}
__device__ __forceinline__ void mma_tf32(float* c, unsigned a0, unsigned a1,
                                         unsigned a2, unsigned a3,
                                         unsigned b0, unsigned b1) {
    asm volatile(
        "mma.sync.aligned.m16n8k8.row.col.f32.tf32.tf32.f32 "
        "{%0,%1,%2,%3}, {%4,%5,%6,%7}, {%8,%9}, {%0,%1,%2,%3};"
        : "+f"(c[0]), "+f"(c[1]), "+f"(c[2]), "+f"(c[3])
        : "r"(a0), "r"(a1), "r"(a2), "r"(a3), "r"(b0), "r"(b1));
}
__device__ __forceinline__ unsigned smem_u32(const void* p) {
    unsigned a;
    asm("{.reg .u64 t; cvta.to.shared.u64 t, %1; cvt.u32.u64 %0, t;}"
        : "=r"(a) : "l"(p));
    return a;
}
__device__ __forceinline__ void ldsm4(unsigned& r0, unsigned& r1,
                                      unsigned& r2, unsigned& r3, unsigned addr) {
    asm volatile("ldmatrix.sync.aligned.m8n8.x4.shared.b16 {%0,%1,%2,%3}, [%4];"
                 : "=r"(r0), "=r"(r1), "=r"(r2), "=r"(r3) : "r"(addr));
}

// MMA block over a 128x128 tile from buffer plane at byte offset `off`.
#define MMA_TILE_BODY(off)                                                   \
    for (int kk = 0; kk < 16; kk += 8) {                                     \
        unsigned a[4][4], bb[4][2];                                          \
        _Pragma("unroll")                                                    \
        for (int mf = 0; mf < 4; mf++)                                       \
            ldsm4(a[mf][0], a[mf][1], a[mf][2], a[mf][3],                    \
                  baseA + (off) + (mf * 16 * LDK + kk) * 4u);                \
        ldsm4(bb[0][0], bb[0][1], bb[1][0], bb[1][1],                        \
              baseB + (off) + kk * 4u);                                      \
        ldsm4(bb[2][0], bb[2][1], bb[3][0], bb[3][1],                        \
              baseB + (off) + (16 * LDK + kk) * 4u);                         \
        _Pragma("unroll")                                                    \
        for (int mf = 0; mf < 4; mf++)                                       \
            _Pragma("unroll")                                                \
            for (int nf = 0; nf < 4; nf++)                                   \
                mma_tf32(acc[mf][nf], a[mf][0], a[mf][1], a[mf][2], a[mf][3],\
                         bb[nf][0], bb[nf][1]);                              \
    }

#define WARP_COORDS                                                          \
    const int tid  = threadIdx.x;                                            \
    const int lane = tid & 31, wid = tid >> 5;                               \
    const int wm = wid & 1, wn = wid >> 1;                                   \
    const int g = lane >> 2, t = lane & 3;                                   \
    const int jm = lane >> 3;                                                \
    (void)g; (void)t;

#define LDSM_BASES(AsT, BsT)                                                 \
    const unsigned baseA = smem_u32(&AsT[0][0][0]) +                         \
        (((wm * 64) + ((jm & 1) * 8) + (lane & 7)) * LDK + ((jm >> 1) * 4)) * 4u; \
    const unsigned baseB = smem_u32(&BsT[0][0][0]) +                         \
        (((wn * 32) + ((jm >> 1) * 8) + (lane & 7)) * LDK + ((jm & 1) * 4)) * 4u;

#define ZERO_ACC                                                             \
    float acc[4][4][4];                                                      \
    _Pragma("unroll")                                                        \
    for (int mf = 0; mf < 4; mf++)                                           \
        _Pragma("unroll")                                                    \
        for (int nf = 0; nf < 4; nf++)                                       \
            _Pragma("unroll")                                                 \
            for (int q = 0; q < 4; q++) acc[mf][nf][q] = 0.f;

// ---------------- kernel 0: zero the sum accumulators ------------------------
__global__ void k_zero() {
    int i = blockIdx.x * blockDim.x + threadIdx.x;
    if (i < B_ * N_) { g_csum[i] = 0.f; g_rsum[i] = 0.f; }
}

// ---------------- kernel 1: transpose point_features [B,PC,N] -> rp [B,N,PC]
__global__ void k_transpose(const float* __restrict__ pf) {
    __shared__ float tile[32][33];
    const int b  = blockIdx.z;
    const int n0 = blockIdx.x * 32;
    const int d0 = blockIdx.y * 32;
    const float* src = pf   + (size_t)b * PC_ * N_;
    float*       dst = g_rp + (size_t)b * N_ * PC_;
    const int tx = threadIdx.x, ty = threadIdx.y;   // (32, 8)
#pragma unroll
    for (int j = 0; j < 32; j += 8)
        tile[ty + j][tx] = src[(size_t)(d0 + ty + j) * N_ + n0 + tx];
    __syncthreads();
#pragma unroll
    for (int j = 0; j < 32; j += 8)
        dst[(size_t)(n0 + ty + j) * PC_ + d0 + tx] = tile[tx][ty + j];
}

// ---------------- kernel 2: ri = img^T @ fc2_w^T + fc2_b  (tf32 mma, 2-buf) --
__global__ __launch_bounds__(256, 2) void k_ri(const float* __restrict__ img,
                                               const float* __restrict__ w,
                                               const float* __restrict__ bias) {
    const int b  = blockIdx.y;
    const int n0 = blockIdx.x * 128;
    const float* X = img  + (size_t)b * IC_ * N_;
    float*       R = g_ri + (size_t)b * N_ * PC_;

    __shared__ unsigned AsT[2][128][LDK];
    __shared__ unsigned BsT[2][128][LDK];

    WARP_COORDS
    LDSM_BASES(AsT, BsT)

    const int rowT = (wid & 3) * 32 + lane;     // transpose-fill dest row
    const int kcb  = wid >> 2;                  // k-chunk base (0/1)
    const int fi = tid >> 2, fc = (tid & 3) * 4;// direct-fill coords

    ZERO_ACC

    float va[2][4]; float4 rb[2];
#pragma unroll
    for (int r = 0; r < 2; r++) {
        int kc = kcb + 2 * r;
#pragma unroll
        for (int j = 0; j < 4; j++)
            va[r][j] = X[(size_t)(kc * 4 + j) * N_ + n0 + rowT];
        rb[r] = *(const float4*)&w[(size_t)(fi + r * 64) * IC_ + fc];
    }

    int p = 0;
    for (int k0 = 0; k0 < IC_; k0 += 16) {
#pragma unroll
        for (int r = 0; r < 2; r++) {
            int kc = kcb + 2 * r;
            *(uint4*)&AsT[p][rowT][kc * 4]    = cvt4(va[r][0], va[r][1], va[r][2], va[r][3]);
            *(uint4*)&BsT[p][fi + r * 64][fc] = cvt4(rb[r].x, rb[r].y, rb[r].z, rb[r].w);
        }
        __syncthreads();
        if (k0 + 16 < IC_) {
            int kn = k0 + 16;
#pragma unroll
            for (int r = 0; r < 2; r++) {
                int kc = kcb + 2 * r;
#pragma unroll
                for (int j = 0; j < 4; j++)
                    va[r][j] = X[(size_t)(kn + kc * 4 + j) * N_ + n0 + rowT];
                rb[r] = *(const float4*)&w[(size_t)(fi + r * 64) * IC_ + kn + fc];
            }
        }
        const unsigned off = p * BUFB;
        MMA_TILE_BODY(off)
        p ^= 1;
    }
#pragma unroll
    for (int mf = 0; mf < 4; mf++) {
        int row = n0 + wm * 64 + mf * 16 + g;
#pragma unroll
        for (int nf = 0; nf < 4; nf++) {
            int col = wn * 32 + nf * 8 + 2 * t;
            float b0 = bias[col], b1 = bias[col + 1];
            *(float2*)&R[(size_t)row * PC_ + col] =
                make_float2(acc[mf][nf][0] + b0, acc[mf][nf][1] + b1);
            *(float2*)&R[(size_t)(row + 8) * PC_ + col] =
                make_float2(acc[mf][nf][2] + b0, acc[mf][nf][3] + b1);
        }
    }
}

// ---------------- kernel 3: P = exp(scale * rp @ ri^T) + row/col sums --------
__global__ __launch_bounds__(256, 2) void k_s() {
    const int b  = blockIdx.z;
    const int i0 = blockIdx.y * 128;
    const int j0 = blockIdx.x * 128;
    const float* A  = g_rp + (size_t)b * N_ * PC_;
    const float* Bm = g_ri + (size_t)b * N_ * PC_;
    float*       Pp = g_S  + (size_t)b * N_ * N_;

    __shared__ unsigned AsT[2][128][LDK];
    __shared__ unsigned BsT[2][128][LDK];
    __shared__ float shr[128], shc[128];

    WARP_COORDS
    LDSM_BASES(AsT, BsT)

    const int fi = tid >> 2, fc = (tid & 3) * 4;

    ZERO_ACC

    float4 ra[2], rb[2];
#pragma unroll
    for (int r = 0; r < 2; r++) {
        ra[r] = *(const float4*)&A [(size_t)(i0 + fi + r * 64) * PC_ + fc];
        rb[r] = *(const float4*)&Bm[(size_t)(j0 + fi + r * 64) * PC_ + fc];
    }

    int p = 0;
    for (int k0 = 0; k0 < PC_; k0 += 16) {
#pragma unroll
        for (int r = 0; r < 2; r++) {
            *(uint4*)&AsT[p][fi + r * 64][fc] = cvt4(ra[r].x, ra[r].y, ra[r].z, ra[r].w);
            *(uint4*)&BsT[p][fi + r * 64][fc] = cvt4(rb[r].x, rb[r].y, rb[r].z, rb[r].w);
        }
        __syncthreads();
        if (k0 + 16 < PC_) {
#pragma unroll
            for (int r = 0; r < 2; r++) {
                ra[r] = *(const float4*)&A [(size_t)(i0 + fi + r * 64) * PC_ + k0 + 16 + fc];
                rb[r] = *(const float4*)&Bm[(size_t)(j0 + fi + r * 64) * PC_ + k0 + 16 + fc];
            }
        }
        const unsigned off = p * BUFB;
        MMA_TILE_BODY(off)
        p ^= 1;
    }

    if (tid < 128) { shr[tid] = 0.f; shc[tid] = 0.f; }
    __syncthreads();

    float rs[4][2] = {{0.f,0.f},{0.f,0.f},{0.f,0.f},{0.f,0.f}};
    float cs[4][2] = {{0.f,0.f},{0.f,0.f},{0.f,0.f},{0.f,0.f}};
#pragma unroll
    for (int mf = 0; mf < 4; mf++) {
        int row = i0 + wm * 64 + mf * 16 + g;
#pragma unroll
        for (int nf = 0; nf < 4; nf++) {
            int col = j0 + wn * 32 + nf * 8 + 2 * t;
            float p0 = __expf(acc[mf][nf][0] * SCALE_);
            float p1 = __expf(acc[mf][nf][1] * SCALE_);
            float p2 = __expf(acc[mf][nf][2] * SCALE_);
            float p3 = __expf(acc[mf][nf][3] * SCALE_);
            *(float2*)&Pp[(size_t)row * N_ + col]       = make_float2(p0, p1);
            *(float2*)&Pp[(size_t)(row + 8) * N_ + col] = make_float2(p2, p3);
            rs[mf][0] += p0 + p1; rs[mf][1] += p2 + p3;
            cs[nf][0] += p0 + p2; cs[nf][1] += p1 + p3;
        }
    }
#pragma unroll
    for (int mf = 0; mf < 4; mf++)
#pragma unroll
        for (int h = 0; h < 2; h++) {
            float v = rs[mf][h];
            v += __shfl_xor_sync(0xffffffffu, v, 1);
            v += __shfl_xor_sync(0xffffffffu, v, 2);
            if (t == 0) atomicAdd(&shr[wm * 64 + mf * 16 + h * 8 + g], v);
        }
#pragma unroll
    for (int nf = 0; nf < 4; nf++)
#pragma unroll
        for (int q = 0; q < 2; q++) {
            float v = cs[nf][q];
            v += __shfl_xor_sync(0xffffffffu, v, 4);
            v += __shfl_xor_sync(0xffffffffu, v, 8);
            v += __shfl_xor_sync(0xffffffffu, v, 16);
            if (g == 0) atomicAdd(&shc[wn * 32 + nf * 8 + 2 * t + q], v);
        }
    __syncthreads();
    if (tid < 128) {
        atomicAdd(&g_rsum[b * N_ + i0 + tid], shr[tid]);
        atomicAdd(&g_csum[b * N_ + j0 + tid], shc[tid]);
    }
}

// ---------------- kernel 4: vp = (rp@Wp^T)/csum, vi = (ri@Wi^T)/rsum ---------
// which = blockIdx.y: 0 -> vp (w cols [0,128)), 1 -> vi (w cols [128,256)).
__global__ __launch_bounds__(256, 2) void k_vp(const float* __restrict__ w) {
    const int which = blockIdx.y;
    const int b  = blockIdx.z;
    const int j0 = blockIdx.x * 128;
    const float* Src = (which ? g_ri : g_rp) + (size_t)b * N_ * PC_;
    const float* sum = (which ? g_rsum : g_csum) + b * N_;
    float*       Dst = (which ? g_vi : g_vp) + (size_t)b * N_ * OC_;

    __shared__ unsigned AsT[2][128][LDK];
    __shared__ unsigned BsT[2][128][LDK];

    WARP_COORDS
    LDSM_BASES(AsT, BsT)

    const int fi = tid >> 2, fc = (tid & 3) * 4;

    ZERO_ACC

    float4 ra[2], rb[2];
#pragma unroll
    for (int r = 0; r < 2; r++) {
        ra[r] = *(const float4*)&Src[(size_t)(j0 + fi + r * 64) * PC_ + fc];
        rb[r] = *(const float4*)&w[(size_t)(fi + r * 64) * (2 * PC_) + which * PC_ + fc];
    }

    int p = 0;
    for (int k0 = 0; k0 < PC_; k0 += 16) {
#pragma unroll
        for (int r = 0; r < 2; r++) {
            *(uint4*)&AsT[p][fi + r * 64][fc] = cvt4(ra[r].x, ra[r].y, ra[r].z, ra[r].w);
            *(uint4*)&BsT[p][fi + r * 64][fc] = cvt4(rb[r].x, rb[r].y, rb[r].z, rb[r].w);
        }
        __syncthreads();
        if (k0 + 16 < PC_) {
            int kn = k0 + 16;
#pragma unroll
            for (int r = 0; r < 2; r++) {
                ra[r] = *(const float4*)&Src[(size_t)(j0 + fi + r * 64) * PC_ + kn + fc];
                rb[r] = *(const float4*)&w[(size_t)(fi + r * 64) * (2 * PC_) + which * PC_ + kn + fc];
            }
        }
        const unsigned off = p * BUFB;
        MMA_TILE_BODY(off)
        p ^= 1;
    }
#pragma unroll
    for (int mf = 0; mf < 4; mf++) {
        int row = j0 + wm * 64 + mf * 16 + g;
        float inv0 = __fdividef(1.f, sum[row]);
        float inv8 = __fdividef(1.f, sum[row + 8]);
#pragma unroll
        for (int nf = 0; nf < 4; nf++) {
            int col = wn * 32 + nf * 8 + 2 * t;
            *(float2*)&Dst[(size_t)row * OC_ + col] =
                make_float2(acc[mf][nf][0] * inv0, acc[mf][nf][1] * inv0);
            *(float2*)&Dst[(size_t)(row + 8) * OC_ + col] =
                make_float2(acc[mf][nf][2] * inv8, acc[mf][nf][3] * inv8);
        }
    }
}

// ---------------- kernel 5: AV partial GEMMs (tf32 + ldmatrix, 4-way ksplit) -
// mode 0: d += P[i, k-range] @ vp[k-range, :]
// mode 1: d += P[k-range, i]^T @ vi[k-range, :]
__global__ __launch_bounds__(256, 2) void k_av() {
    const int mode = blockIdx.x & 1;
    const int ks   = blockIdx.x >> 1;      // 0..3
    const int b    = blockIdx.z;
    const int i0   = blockIdx.y * 128;
    const int kb   = ks * KSPL;
    const float* Pp = g_S + (size_t)b * N_ * N_;
    const float* V  = (mode == 0 ? g_vp : g_vi) + (size_t)b * N_ * OC_;
    float*       D  = g_d[(mode << 2) | ks] + (size_t)b * N_ * OC_;

    __shared__ unsigned AsT[2][128][LDK];
    __shared__ unsigned BsT[2][128][LDK];

    WARP_COORDS
    LDSM_BASES(AsT, BsT)

    const int rowT = (wid & 3) * 32 + lane;     // transpose-fill dest row
    const int kcb  = wid >> 2;
    const int fi = tid >> 2, fc = (tid & 3) * 4;

    ZERO_ACC

    float va[2][4], vb[2][4];
#pragma unroll
    for (int r = 0; r < 2; r++) {
        int kc = kcb + 2 * r;
        if (mode == 0) {
            float4 v = *(const float4*)&Pp[(size_t)(i0 + fi + r * 64) * N_ + kb + fc];
            va[r][0] = v.x; va[r][1] = v.y; va[r][2] = v.z; va[r][3] = v.w;
        } else {
#pragma unroll
            for (int j = 0; j < 4; j++)
                va[r][j] = Pp[(size_t)(kb + kc * 4 + j) * N_ + i0 + rowT];
        }
#pragma unroll
        for (int j = 0; j < 4; j++)
            vb[r][j] = V[(size_t)(kb + kc * 4 + j) * OC_ + rowT];
    }

    int p = 0;
    for (int k0 = kb; k0 < kb + KSPL; k0 += 16) {
#pragma unroll
        for (int r = 0; r < 2; r++) {
            int kc = kcb + 2 * r;
            if (mode == 0)
                *(uint4*)&AsT[p][fi + r * 64][fc] = cvt4(va[r][0], va[r][1], va[r][2], va[r][3]);
            else
                *(uint4*)&AsT[p][rowT][kc * 4]    = cvt4(va[r][0], va[r][1], va[r][2], va[r][3]);
            *(uint4*)&BsT[p][rowT][kc * 4]        = cvt4(vb[r][0], vb[r][1], vb[r][2], vb[r][3]);
        }
        __syncthreads();
        if (k0 + 16 < kb + KSPL) {
            int kn = k0 + 16;
#pragma unroll
            for (int r = 0; r < 2; r++) {
                int kc = kcb + 2 * r;
                if (mode == 0) {
                    float4 v = *(const float4*)&Pp[(size_t)(i0 + fi + r * 64) * N_ + kn + fc];
                    va[r][0] = v.x; va[r][1] = v.y; va[r][2] = v.z; va[r][3] = v.w;
                } else {
#pragma unroll
                    for (int j = 0; j < 4; j++)
                        va[r][j] = Pp[(size_t)(kn + kc * 4 + j) * N_ + i0 + rowT];
                }
#pragma unroll
                for (int j = 0; j < 4; j++)
                    vb[r][j] = V[(size_t)(kn + kc * 4 + j) * OC_ + rowT];
            }
        }
        const unsigned off = p * BUFB;
        MMA_TILE_BODY(off)
        p ^= 1;
    }
#pragma unroll
    for (int mf = 0; mf < 4; mf++) {
        int row = i0 + wm * 64 + mf * 16 + g;
#pragma unroll
        for (int nf = 0; nf < 4; nf++) {
            int col = wn * 32 + nf * 8 + 2 * t;
            *(float2*)&D[(size_t)row * OC_ + col]       = make_float2(acc[mf][nf][0], acc[mf][nf][1]);
            *(float2*)&D[(size_t)(row + 8) * OC_ + col] = make_float2(acc[mf][nf][2], acc[mf][nf][3]);
        }
    }
}

// ---------------- kernel 6: sum partials + BN + ReLU + transpose to [B,OC,N] -
__global__ void k_bn(const float* __restrict__ cb,    const float* __restrict__ gamma,
                     const float* __restrict__ beta,  const float* __restrict__ mean,
                     const float* __restrict__ var,   float* __restrict__ out) {
    __shared__ float tile[32][33];
    const int b  = blockIdx.z;
    const int n0 = blockIdx.x * 32;
    const int o0 = blockIdx.y * 32;
    const int tx = threadIdx.x, ty = threadIdx.y;   // (32, 8)
#pragma unroll
    for (int j = 0; j < 32; j += 8) {
        size_t idx = (size_t)b * N_ * OC_ + (size_t)(n0 + ty + j) * OC_ + o0 + tx;
        float s = 0.f;
#pragma unroll
        for (int m = 0; m < 8; m++) s += g_d[m][idx];
        tile[ty + j][tx] = s;
    }
    __syncthreads();
#pragma unroll
    for (int j = 0; j < 32; j += 8) {
        int o = o0 + ty + j;
        float gm   = gamma[o] * rsqrtf(var[o] + 1e-5f);
        float base = gm * (cb[o] - mean[o]) + beta[o];
        out[(size_t)b * OC_ * N_ + (size_t)o * N_ + n0 + tx] =
            fmaxf(gm * tile[tx][ty + j] + base, 0.f);
    }
}

// ---------------- launch -----------------------------------------------------
extern "C" void kernel_launch(void* const* d_in, const int* in_sizes, int n_in,
                              void* d_out, int out_size) {
    const float* pf     = (const float*)d_in[0];
    const float* img    = (const float*)d_in[1];
    const float* fc2_w  = (const float*)d_in[2];
    const float* fc2_b  = (const float*)d_in[3];
    const float* conv_w = (const float*)d_in[4];
    const float* conv_b = (const float*)d_in[5];
    const float* gamma  = (const float*)d_in[6];
    const float* beta   = (const float*)d_in[7];
    const float* mean   = (const float*)d_in[8];
    const float* var    = (const float*)d_in[9];
    float* out = (float*)d_out;

    k_zero     <<<(B_ * N_ + 511) / 512, 512>>>();
    k_transpose<<<dim3(N_ / 32, PC_ / 32, B_), dim3(32, 8)>>>(pf);
    k_ri       <<<dim3(N_ / 128, B_),           256>>>(img, fc2_w, fc2_b);
    k_s        <<<dim3(N_ / 128, N_ / 128, B_), 256>>>();
    k_vp       <<<dim3(N_ / 128, 2, B_),        256>>>(conv_w);
    k_av       <<<dim3(8, N_ / 128, B_),        256>>>();
    k_bn       <<<dim3(N_ / 32, OC_ / 32, B_),  dim3(32, 8)>>>(conv_b, gamma, beta,
                                                               mean, var, out);
}

// round 10
// speedup vs baseline: 2.3906x; 1.0173x over previous
#include <cuda_runtime.h>
#include <math.h>

#define B_   2
#define N_   4096
#define IC_  256
#define PC_  128
#define OC_  128
#define SCALE_ 0.08838834764831845f   // 1/sqrt(128)
#define LDK  20                        // padded row pitch (floats) for ldmatrix tiles
#define BUFB (128u * LDK * 4u)         // bytes per smem buffer plane
#define KSPL (N_ / 4)                  // k-range per k_av split

// ---------------- scratch (device globals) ----------------------------------
static __device__ __align__(16) float g_rp  [(size_t)B_ * N_ * PC_];   // tf32-rounded
static __device__ __align__(16) float g_ri  [(size_t)B_ * N_ * PC_];   // tf32-rounded
static __device__ __align__(16) float g_S   [(size_t)B_ * N_ * N_];    // P  (tf32-rounded)
static __device__ __align__(16) float g_ST  [(size_t)B_ * N_ * N_];    // P^T (tf32-rounded)
static __device__ __align__(16) float g_csum[B_ * N_];
static __device__ __align__(16) float g_rsum[B_ * N_];
static __device__ __align__(16) float g_vT  [2][(size_t)B_ * OC_ * N_]; // v^T [d][n], rounded
static __device__ __align__(16) float g_d   [8][(size_t)B_ * N_ * OC_]; // partials

// ---------------- helpers ----------------------------------------------------
__device__ __forceinline__ unsigned tf32_of(float x) {
    unsigned r; asm("cvt.rna.tf32.f32 %0, %1;" : "=r"(r) : "f"(x)); return r;
}
__device__ __forceinline__ float tf32f(float x) { return __uint_as_float(tf32_of(x)); }
__device__ __forceinline__ uint4 cvt4(float a, float b, float c, float d) {
    return make_uint4(tf32_of(a), tf32_of(b), tf32_of(c), tf32_of(d));
}
__device__ __forceinline__ void mma_tf32(float* c, unsigned a0, unsigned a1,
                                         unsigned a2, unsigned a3,
                                         unsigned b0, unsigned b1) {
    asm volatile(
        "mma.sync.aligned.m16n8k8.row.col.f32.tf32.tf32.f32 "
        "{%0,%1,%2,%3}, {%4,%5,%6,%7}, {%8,%9}, {%0,%1,%2,%3};"
        : "+f"(c[0]), "+f"(c[1]), "+f"(c[2]), "+f"(c[3])
        : "r"(a0), "r"(a1), "r"(a2), "r"(a3), "r"(b0), "r"(b1));
}
__device__ __forceinline__ unsigned smem_u32(const void* p) {
    unsigned a;
    asm("{.reg .u64 t; cvta.to.shared.u64 t, %1; cvt.u32.u64 %0, t;}"
        : "=r"(a) : "l"(p));
    return a;
}
__device__ __forceinline__ void ldsm4(unsigned& r0, unsigned& r1,
                                      unsigned& r2, unsigned& r3, unsigned addr) {
    asm volatile("ldmatrix.sync.aligned.m8n8.x4.shared.b16 {%0,%1,%2,%3}, [%4];"
                 : "=r"(r0), "=r"(r1), "=r"(r2), "=r"(r3) : "r"(addr));
}
#define CPA16(dst, src) asm volatile("cp.async.cg.shared.global [%0], [%1], 16;" \
                                     :: "r"(dst), "l"(src) : "memory")
#define CPA_COMMIT()    asm volatile("cp.async.commit_group;" ::: "memory")
#define CPA_WAIT0()     asm volatile("cp.async.wait_group 0;" ::: "memory")
#define CPA_WAIT1()     asm volatile("cp.async.wait_group 1;" ::: "memory")

// MMA block over a 128x128 tile from buffer plane at byte offset `off`.
#define MMA_TILE_BODY(off)                                                   \
    for (int kk = 0; kk < 16; kk += 8) {                                     \
        unsigned a[4][4], bb[4][2];                                          \
        _Pragma("unroll")                                                    \
        for (int mf = 0; mf < 4; mf++)                                       \
            ldsm4(a[mf][0], a[mf][1], a[mf][2], a[mf][3],                    \
                  baseA + (off) + (mf * 16 * LDK + kk) * 4u);                \
        ldsm4(bb[0][0], bb[0][1], bb[1][0], bb[1][1],                        \
              baseB + (off) + kk * 4u);                                      \
        ldsm4(bb[2][0], bb[2][1], bb[3][0], bb[3][1],                        \
              baseB + (off) + (16 * LDK + kk) * 4u);                         \
        _Pragma("unroll")                                                    \
        for (int mf = 0; mf < 4; mf++)                                       \
            _Pragma("unroll")                                                \
            for (int nf = 0; nf < 4; nf++)                                   \
                mma_tf32(acc[mf][nf], a[mf][0], a[mf][1], a[mf][2], a[mf][3],\
                         bb[nf][0], bb[nf][1]);                              \
    }

#define WARP_COORDS                                                          \
    const int tid  = threadIdx.x;                                            \
    const int lane = tid & 31, wid = tid >> 5;                               \
    const int wm = wid & 1, wn = wid >> 1;                                   \
    const int g = lane >> 2, t = lane & 3;                                   \
    const int jm = lane >> 3;                                                \
    (void)g; (void)t;

#define LDSM_BASES(AsT, BsT)                                                 \
    const unsigned baseA = smem_u32(&AsT[0][0][0]) +                         \
        (((wm * 64) + ((jm & 1) * 8) + (lane & 7)) * LDK + ((jm >> 1) * 4)) * 4u; \
    const unsigned baseB = smem_u32(&BsT[0][0][0]) +                         \
        (((wn * 32) + ((jm >> 1) * 8) + (lane & 7)) * LDK + ((jm & 1) * 4)) * 4u;

#define ZERO_ACC                                                             \
    float acc[4][4][4];                                                      \
    _Pragma("unroll")                                                        \
    for (int mf = 0; mf < 4; mf++)                                           \
        _Pragma("unroll")                                                    \
        for (int nf = 0; nf < 4; nf++)                                       \
            _Pragma("unroll")                                                 \
            for (int q = 0; q < 4; q++) acc[mf][nf][q] = 0.f;

// ---------------- kernel 0: zero the sum accumulators ------------------------
__global__ void k_zero() {
    int i = blockIdx.x * blockDim.x + threadIdx.x;
    if (i < B_ * N_) { g_csum[i] = 0.f; g_rsum[i] = 0.f; }
}

// ---------------- kernel 1: transpose pf [B,PC,N] -> rp [B,N,PC] (tf32-rnd) --
__global__ void k_transpose(const float* __restrict__ pf) {
    __shared__ float tile[32][33];
    const int b  = blockIdx.z;
    const int n0 = blockIdx.x * 32;
    const int d0 = blockIdx.y * 32;
    const float* src = pf   + (size_t)b * PC_ * N_;
    float*       dst = g_rp + (size_t)b * N_ * PC_;
    const int tx = threadIdx.x, ty = threadIdx.y;   // (32, 8)
#pragma unroll
    for (int j = 0; j < 32; j += 8)
        tile[ty + j][tx] = src[(size_t)(d0 + ty + j) * N_ + n0 + tx];
    __syncthreads();
#pragma unroll
    for (int j = 0; j < 32; j += 8)
        dst[(size_t)(n0 + ty + j) * PC_ + d0 + tx] = tf32f(tile[tx][ty + j]);
}

// ---------------- kernel 2: ri = img^T @ fc2_w^T + fc2_b  (tf32 mma, 2-buf) --
__global__ __launch_bounds__(256, 2) void k_ri(const float* __restrict__ img,
                                               const float* __restrict__ w,
                                               const float* __restrict__ bias) {
    const int b  = blockIdx.y;
    const int n0 = blockIdx.x * 128;
    const float* X = img  + (size_t)b * IC_ * N_;
    float*       R = g_ri + (size_t)b * N_ * PC_;

    __shared__ __align__(16) unsigned AsT[2][128][LDK];
    __shared__ __align__(16) unsigned BsT[2][128][LDK];

    WARP_COORDS
    LDSM_BASES(AsT, BsT)

    const int rowT = (wid & 3) * 32 + lane;
    const int kcb  = wid >> 2;
    const int fi = tid >> 2, fc = (tid & 3) * 4;

    ZERO_ACC

    float va[2][4]; float4 rb[2];
#pragma unroll
    for (int r = 0; r < 2; r++) {
        int kc = kcb + 2 * r;
#pragma unroll
        for (int j = 0; j < 4; j++)
            va[r][j] = X[(size_t)(kc * 4 + j) * N_ + n0 + rowT];
        rb[r] = *(const float4*)&w[(size_t)(fi + r * 64) * IC_ + fc];
    }

    int p = 0;
    for (int k0 = 0; k0 < IC_; k0 += 16) {
#pragma unroll
        for (int r = 0; r < 2; r++) {
            int kc = kcb + 2 * r;
            *(uint4*)&AsT[p][rowT][kc * 4]    = cvt4(va[r][0], va[r][1], va[r][2], va[r][3]);
            *(uint4*)&BsT[p][fi + r * 64][fc] = cvt4(rb[r].x, rb[r].y, rb[r].z, rb[r].w);
        }
        __syncthreads();
        if (k0 + 16 < IC_) {
            int kn = k0 + 16;
#pragma unroll
            for (int r = 0; r < 2; r++) {
                int kc = kcb + 2 * r;
#pragma unroll
                for (int j = 0; j < 4; j++)
                    va[r][j] = X[(size_t)(kn + kc * 4 + j) * N_ + n0 + rowT];
                rb[r] = *(const float4*)&w[(size_t)(fi + r * 64) * IC_ + kn + fc];
            }
        }
        const unsigned off = p * BUFB;
        MMA_TILE_BODY(off)
        __syncthreads();
        p ^= 1;
    }
#pragma unroll
    for (int mf = 0; mf < 4; mf++) {
        int row = n0 + wm * 64 + mf * 16 + g;
#pragma unroll
        for (int nf = 0; nf < 4; nf++) {
            int col = wn * 32 + nf * 8 + 2 * t;
            float b0 = bias[col], b1 = bias[col + 1];
            *(float2*)&R[(size_t)row * PC_ + col] =
                make_float2(tf32f(acc[mf][nf][0] + b0), tf32f(acc[mf][nf][1] + b1));
            *(float2*)&R[(size_t)(row + 8) * PC_ + col] =
                make_float2(tf32f(acc[mf][nf][2] + b0), tf32f(acc[mf][nf][3] + b1));
        }
    }
}

// ---------------- kernel 3: P = exp(scale * rp @ ri^T), P^T, row/col sums ----
// cp.async fills (sources pre-rounded), 2-buf, ldmatrix + mma.
__global__ __launch_bounds__(256, 2) void k_s() {
    const int b  = blockIdx.z;
    const int i0 = blockIdx.y * 128;
    const int j0 = blockIdx.x * 128;
    const float* A  = g_rp + (size_t)b * N_ * PC_;
    const float* Bm = g_ri + (size_t)b * N_ * PC_;
    float*       Pp = g_S  + (size_t)b * N_ * N_;
    float*       Pt = g_ST + (size_t)b * N_ * N_;

    __shared__ __align__(16) unsigned AsT[2][128][LDK];
    __shared__ __align__(16) unsigned BsT[2][128][LDK];
    __shared__ float shr[128], shc[128];

    WARP_COORDS
    LDSM_BASES(AsT, BsT)

    const unsigned sAu = smem_u32(&AsT[0][0][0]);
    const unsigned sBu = smem_u32(&BsT[0][0][0]);
    const int frow = tid >> 2, fq = (tid & 3) * 4;   // 2 x (row, quad) per operand

#define FILL_S(pp, kk0)                                                      \
    _Pragma("unroll")                                                        \
    for (int r = 0; r < 2; r++) {                                            \
        int row = frow + r * 64;                                             \
        unsigned o = (pp) * BUFB + (row * LDK + fq) * 4u;                    \
        CPA16(sAu + o, &A [(size_t)(i0 + row) * PC_ + (kk0) + fq]);          \
        CPA16(sBu + o, &Bm[(size_t)(j0 + row) * PC_ + (kk0) + fq]);          \
    }                                                                        \
    CPA_COMMIT();

    ZERO_ACC

    FILL_S(0, 0)
    int p = 0;
    for (int ch = 0; ch < PC_ / 16; ch++) {
        if (ch + 1 < PC_ / 16) { FILL_S(p ^ 1, (ch + 1) * 16) CPA_WAIT1(); }
        else                   { CPA_WAIT0(); }
        __syncthreads();
        const unsigned off = p * BUFB;
        MMA_TILE_BODY(off)
        __syncthreads();
        p ^= 1;
    }
#undef FILL_S

    if (tid < 128) { shr[tid] = 0.f; shc[tid] = 0.f; }
    __syncthreads();

    float rs[4][2] = {{0.f,0.f},{0.f,0.f},{0.f,0.f},{0.f,0.f}};
    float cs[4][2] = {{0.f,0.f},{0.f,0.f},{0.f,0.f},{0.f,0.f}};
#pragma unroll
    for (int mf = 0; mf < 4; mf++) {
        int row = i0 + wm * 64 + mf * 16 + g;
#pragma unroll
        for (int nf = 0; nf < 4; nf++) {
            int col = j0 + wn * 32 + nf * 8 + 2 * t;
            float p0 = __expf(acc[mf][nf][0] * SCALE_);
            float p1 = __expf(acc[mf][nf][1] * SCALE_);
            float p2 = __expf(acc[mf][nf][2] * SCALE_);
            float p3 = __expf(acc[mf][nf][3] * SCALE_);
            float q0 = tf32f(p0), q1 = tf32f(p1), q2 = tf32f(p2), q3 = tf32f(p3);
            *(float2*)&Pp[(size_t)row * N_ + col]       = make_float2(q0, q1);
            *(float2*)&Pp[(size_t)(row + 8) * N_ + col] = make_float2(q2, q3);
            Pt[(size_t)col * N_ + row]           = q0;
            Pt[(size_t)(col + 1) * N_ + row]     = q1;
            Pt[(size_t)col * N_ + row + 8]       = q2;
            Pt[(size_t)(col + 1) * N_ + row + 8] = q3;
            rs[mf][0] += p0 + p1; rs[mf][1] += p2 + p3;
            cs[nf][0] += p0 + p2; cs[nf][1] += p1 + p3;
        }
    }
#pragma unroll
    for (int mf = 0; mf < 4; mf++)
#pragma unroll
        for (int h = 0; h < 2; h++) {
            float v = rs[mf][h];
            v += __shfl_xor_sync(0xffffffffu, v, 1);
            v += __shfl_xor_sync(0xffffffffu, v, 2);
            if (t == 0) atomicAdd(&shr[wm * 64 + mf * 16 + h * 8 + g], v);
        }
#pragma unroll
    for (int nf = 0; nf < 4; nf++)
#pragma unroll
        for (int q = 0; q < 2; q++) {
            float v = cs[nf][q];
            v += __shfl_xor_sync(0xffffffffu, v, 4);
            v += __shfl_xor_sync(0xffffffffu, v, 8);
            v += __shfl_xor_sync(0xffffffffu, v, 16);
            if (g == 0) atomicAdd(&shc[wn * 32 + nf * 8 + 2 * t + q], v);
        }
    __syncthreads();
    if (tid < 128) {
        atomicAdd(&g_rsum[b * N_ + i0 + tid], shr[tid]);
        atomicAdd(&g_csum[b * N_ + j0 + tid], shc[tid]);
    }
}

// ---------------- kernel 4: vT[which][d][n] = ((src@W^T)/sum)^T  (rounded) ---
__global__ __launch_bounds__(256, 2) void k_vp(const float* __restrict__ w) {
    const int which = blockIdx.y;
    const int b  = blockIdx.z;
    const int j0 = blockIdx.x * 128;
    const float* Src = (which ? g_ri : g_rp) + (size_t)b * N_ * PC_;
    const float* sum = (which ? g_rsum : g_csum) + b * N_;
    float*       Dst = g_vT[which] + (size_t)b * OC_ * N_;

    __shared__ __align__(16) unsigned AsT[2][128][LDK];
    __shared__ __align__(16) unsigned BsT[2][128][LDK];

    WARP_COORDS
    LDSM_BASES(AsT, BsT)

    const int fi = tid >> 2, fc = (tid & 3) * 4;

    ZERO_ACC

    float4 ra[2], rb[2];
#pragma unroll
    for (int r = 0; r < 2; r++) {
        ra[r] = *(const float4*)&Src[(size_t)(j0 + fi + r * 64) * PC_ + fc];
        rb[r] = *(const float4*)&w[(size_t)(fi + r * 64) * (2 * PC_) + which * PC_ + fc];
    }

    int p = 0;
    for (int k0 = 0; k0 < PC_; k0 += 16) {
#pragma unroll
        for (int r = 0; r < 2; r++) {
            *(uint4*)&AsT[p][fi + r * 64][fc] = cvt4(ra[r].x, ra[r].y, ra[r].z, ra[r].w);
            *(uint4*)&BsT[p][fi + r * 64][fc] = cvt4(rb[r].x, rb[r].y, rb[r].z, rb[r].w);
        }
        __syncthreads();
        if (k0 + 16 < PC_) {
            int kn = k0 + 16;
#pragma unroll
            for (int r = 0; r < 2; r++) {
                ra[r] = *(const float4*)&Src[(size_t)(j0 + fi + r * 64) * PC_ + kn + fc];
                rb[r] = *(const float4*)&w[(size_t)(fi + r * 64) * (2 * PC_) + which * PC_ + kn + fc];
            }
        }
        const unsigned off = p * BUFB;
        MMA_TILE_BODY(off)
        __syncthreads();
        p ^= 1;
    }
#pragma unroll
    for (int mf = 0; mf < 4; mf++) {
        int row = j0 + wm * 64 + mf * 16 + g;
        float inv0 = __fdividef(1.f, sum[row]);
        float inv8 = __fdividef(1.f, sum[row + 8]);
#pragma unroll
        for (int nf = 0; nf < 4; nf++) {
            int col = wn * 32 + nf * 8 + 2 * t;
            Dst[(size_t)col * N_ + row]           = tf32f(acc[mf][nf][0] * inv0);
            Dst[(size_t)(col + 1) * N_ + row]     = tf32f(acc[mf][nf][1] * inv0);
            Dst[(size_t)col * N_ + row + 8]       = tf32f(acc[mf][nf][2] * inv8);
            Dst[(size_t)(col + 1) * N_ + row + 8] = tf32f(acc[mf][nf][3] * inv8);
        }
    }
}

// ---------------- kernel 5: AV partial GEMMs (cp.async + ldmatrix + mma) -----
// mode 0: d = P [i-block, krange] @ vp[krange, :]   (A rows from g_S)
// mode 1: d = P^T[i-block, krange] @ vi[krange, :]  (A rows from g_ST)
__global__ __launch_bounds__(256, 2) void k_av() {
    const int mode = blockIdx.x & 1;
    const int ks   = blockIdx.x >> 1;      // 0..3
    const int b    = blockIdx.z;
    const int i0   = blockIdx.y * 128;
    const int kb   = ks * KSPL;
    const float* M  = (mode == 0 ? g_S : g_ST) + (size_t)b * N_ * N_;
    const float* Vt = g_vT[mode] + (size_t)b * OC_ * N_;
    float*       D  = g_d[(mode << 2) | ks] + (size_t)b * N_ * OC_;

    __shared__ __align__(16) unsigned AsT[2][128][LDK];
    __shared__ __align__(16) unsigned BsT[2][128][LDK];

    WARP_COORDS
    LDSM_BASES(AsT, BsT)

    const unsigned sAu = smem_u32(&AsT[0][0][0]);
    const unsigned sBu = smem_u32(&BsT[0][0][0]);
    const int frow = tid >> 2, fq = (tid & 3) * 4;

#define FILL_AV(pp, kk0)                                                     \
    _Pragma("unroll")                                                        \
    for (int r = 0; r < 2; r++) {                                            \
        int row = frow + r * 64;                                             \
        unsigned o = (pp) * BUFB + (row * LDK + fq) * 4u;                    \
        CPA16(sAu + o, &M [(size_t)(i0 + row) * N_ + (kk0) + fq]);           \
        CPA16(sBu + o, &Vt[(size_t)row * N_ + (kk0) + fq]);                  \
    }                                                                        \
    CPA_COMMIT();

    ZERO_ACC

    FILL_AV(0, kb)
    int p = 0;
    const int NCH = KSPL / 16;
    for (int ch = 0; ch < NCH; ch++) {
        if (ch + 1 < NCH) { FILL_AV(p ^ 1, kb + (ch + 1) * 16) CPA_WAIT1(); }
        else              { CPA_WAIT0(); }
        __syncthreads();
        const unsigned off = p * BUFB;
        MMA_TILE_BODY(off)
        __syncthreads();
        p ^= 1;
    }
#undef FILL_AV

#pragma unroll
    for (int mf = 0; mf < 4; mf++) {
        int row = i0 + wm * 64 + mf * 16 + g;
#pragma unroll
        for (int nf = 0; nf < 4; nf++) {
            int col = wn * 32 + nf * 8 + 2 * t;
            *(float2*)&D[(size_t)row * OC_ + col]       = make_float2(acc[mf][nf][0], acc[mf][nf][1]);
            *(float2*)&D[(size_t)(row + 8) * OC_ + col] = make_float2(acc[mf][nf][2], acc[mf][nf][3]);
        }
    }
}

// ---------------- kernel 6: sum partials + BN + ReLU + transpose to [B,OC,N] -
__global__ void k_bn(const float* __restrict__ cb,    const float* __restrict__ gamma,
                     const float* __restrict__ beta,  const float* __restrict__ mean,
                     const float* __restrict__ var,   float* __restrict__ out) {
    __shared__ float tile[32][33];
    const int b  = blockIdx.z;
    const int n0 = blockIdx.x * 32;
    const int o0 = blockIdx.y * 32;
    const int tx = threadIdx.x, ty = threadIdx.y;   // (32, 8)
#pragma unroll
    for (int j = 0; j < 32; j += 8) {
        size_t idx = (size_t)b * N_ * OC_ + (size_t)(n0 + ty + j) * OC_ + o0 + tx;
        float s = 0.f;
#pragma unroll
        for (int m = 0; m < 8; m++) s += g_d[m][idx];
        tile[ty + j][tx] = s;
    }
    __syncthreads();
#pragma unroll
    for (int j = 0; j < 32; j += 8) {
        int o = o0 + ty + j;
        float gm   = gamma[o] * rsqrtf(var[o] + 1e-5f);
        float base = gm * (cb[o] - mean[o]) + beta[o];
        out[(size_t)b * OC_ * N_ + (size_t)o * N_ + n0 + tx] =
            fmaxf(gm * tile[tx][ty + j] + base, 0.f);
    }
}

// ---------------- launch -----------------------------------------------------
extern "C" void kernel_launch(void* const* d_in, const int* in_sizes, int n_in,
                              void* d_out, int out_size) {
    const float* pf     = (const float*)d_in[0];
    const float* img    = (const float*)d_in[1];
    const float* fc2_w  = (const float*)d_in[2];
    const float* fc2_b  = (const float*)d_in[3];
    const float* conv_w = (const float*)d_in[4];
    const float* conv_b = (const float*)d_in[5];
    const float* gamma  = (const float*)d_in[6];
    const float* beta   = (const float*)d_in[7];
    const float* mean   = (const float*)d_in[8];
    const float* var    = (const float*)d_in[9];
    float* out = (float*)d_out;

    k_zero     <<<(B_ * N_ + 511) / 512, 512>>>();
    k_transpose<<<dim3(N_ / 32, PC_ / 32, B_), dim3(32, 8)>>>(pf);
    k_ri       <<<dim3(N_ / 128, B_),           256>>>(img, fc2_w, fc2_b);
    k_s        <<<dim3(N_ / 128, N_ / 128, B_), 256>>>();
    k_vp       <<<dim3(N_ / 128, 2, B_),        256>>>(conv_w);
    k_av       <<<dim3(8, N_ / 128, B_),        256>>>();
    k_bn       <<<dim3(N_ / 32, OC_ / 32, B_),  dim3(32, 8)>>>(conv_b, gamma, beta,
                                                               mean, var, out);
}

// round 11
// speedup vs baseline: 3.1573x; 1.3207x over previous
#include <cuda_runtime.h>
#include <cuda_fp16.h>
#include <math.h>

#define B_   2
#define N_   4096
#define IC_  256
#define PC_  128
#define OC_  128
#define SCALE_ 0.08838834764831845f   // 1/sqrt(128)
#define VSCALE 4096.0f                 // vT scaling to stay in fp16 normal range
#define LDK  20                        // tf32 tile pitch (floats) — k_ri only
#define BUFB (128u * LDK * 4u)
#define LDH  40                        // fp16 tile pitch (halves), 80 B/row
#define BUFH (128u * LDH * 2u)         // 10240 B per fp16 plane
#define KSPL (N_ / 4)

// ---------------- scratch (device globals) ----------------------------------
static __device__ __align__(16) __half g_rp16[(size_t)B_ * N_ * PC_];
static __device__ __align__(16) __half g_ri16[(size_t)B_ * N_ * PC_];
static __device__ __align__(16) __half g_S16 [(size_t)B_ * N_ * N_];   // P
static __device__ __align__(16) __half g_ST16[(size_t)B_ * N_ * N_];   // P^T
static __device__ __align__(16) __half g_vT16[2][(size_t)B_ * OC_ * N_]; // v^T * VSCALE
static __device__ __align__(16) float  g_csum[B_ * N_];
static __device__ __align__(16) float  g_rsum[B_ * N_];
static __device__ __align__(16) float  g_d   [8][(size_t)B_ * N_ * OC_]; // fp32 partials

// ---------------- helpers ----------------------------------------------------
__device__ __forceinline__ unsigned tf32_of(float x) {
    unsigned r; asm("cvt.rna.tf32.f32 %0, %1;" : "=r"(r) : "f"(x)); return r;
}
__device__ __forceinline__ uint4 cvt4(float a, float b, float c, float d) {
    return make_uint4(tf32_of(a), tf32_of(b), tf32_of(c), tf32_of(d));
}
__device__ __forceinline__ unsigned h2pack(float a, float b) {
    __half2 h = __floats2half2_rn(a, b);
    return *reinterpret_cast<unsigned*>(&h);
}
__device__ __forceinline__ void mma_tf32(float* c, unsigned a0, unsigned a1,
                                         unsigned a2, unsigned a3,
                                         unsigned b0, unsigned b1) {
    asm volatile(
        "mma.sync.aligned.m16n8k8.row.col.f32.tf32.tf32.f32 "
        "{%0,%1,%2,%3}, {%4,%5,%6,%7}, {%8,%9}, {%0,%1,%2,%3};"
        : "+f"(c[0]), "+f"(c[1]), "+f"(c[2]), "+f"(c[3])
        : "r"(a0), "r"(a1), "r"(a2), "r"(a3), "r"(b0), "r"(b1));
}
__device__ __forceinline__ void mma_f16(float* c, unsigned a0, unsigned a1,
                                        unsigned a2, unsigned a3,
                                        unsigned b0, unsigned b1) {
    asm volatile(
        "mma.sync.aligned.m16n8k16.row.col.f32.f16.f16.f32 "
        "{%0,%1,%2,%3}, {%4,%5,%6,%7}, {%8,%9}, {%0,%1,%2,%3};"
        : "+f"(c[0]), "+f"(c[1]), "+f"(c[2]), "+f"(c[3])
        : "r"(a0), "r"(a1), "r"(a2), "r"(a3), "r"(b0), "r"(b1));
}
__device__ __forceinline__ unsigned smem_u32(const void* p) {
    unsigned a;
    asm("{.reg .u64 t; cvta.to.shared.u64 t, %1; cvt.u32.u64 %0, t;}"
        : "=r"(a) : "l"(p));
    return a;
}
__device__ __forceinline__ void ldsm4(unsigned& r0, unsigned& r1,
                                      unsigned& r2, unsigned& r3, unsigned addr) {
    asm volatile("ldmatrix.sync.aligned.m8n8.x4.shared.b16 {%0,%1,%2,%3}, [%4];"
                 : "=r"(r0), "=r"(r1), "=r"(r2), "=r"(r3) : "r"(addr));
}
#define CPA16(dst, src) asm volatile("cp.async.cg.shared.global [%0], [%1], 16;" \
                                     :: "r"(dst), "l"(src) : "memory")
#define CPA_COMMIT()    asm volatile("cp.async.commit_group;" ::: "memory")
#define CPA_WAIT0()     asm volatile("cp.async.wait_group 0;" ::: "memory")
#define CPA_WAIT1()     asm volatile("cp.async.wait_group 1;" ::: "memory")

#define WARP_COORDS                                                          \
    const int tid  = threadIdx.x;                                            \
    const int lane = tid & 31, wid = tid >> 5;                               \
    const int wm = wid & 1, wn = wid >> 1;                                   \
    const int g = lane >> 2, t = lane & 3;                                   \
    const int jm = lane >> 3;                                                \
    (void)g; (void)t; (void)jm;

#define ZERO_ACC                                                             \
    float acc[4][4][4];                                                      \
    _Pragma("unroll")                                                        \
    for (int mf = 0; mf < 4; mf++)                                           \
        _Pragma("unroll")                                                    \
        for (int nf = 0; nf < 4; nf++)                                       \
            _Pragma("unroll")                                                 \
            for (int q = 0; q < 4; q++) acc[mf][nf][q] = 0.f;

// ----- tf32 path (k_ri only) -----
#define LDSM_BASES(AsT, BsT)                                                 \
    const unsigned baseA = smem_u32(&AsT[0][0][0]) +                         \
        (((wm * 64) + ((jm & 1) * 8) + (lane & 7)) * LDK + ((jm >> 1) * 4)) * 4u; \
    const unsigned baseB = smem_u32(&BsT[0][0][0]) +                         \
        (((wn * 32) + ((jm >> 1) * 8) + (lane & 7)) * LDK + ((jm & 1) * 4)) * 4u;

#define MMA_TILE_BODY(off)                                                   \
    for (int kk = 0; kk < 16; kk += 8) {                                     \
        unsigned a[4][4], bb[4][2];                                          \
        _Pragma("unroll")                                                    \
        for (int mf = 0; mf < 4; mf++)                                       \
            ldsm4(a[mf][0], a[mf][1], a[mf][2], a[mf][3],                    \
                  baseA + (off) + (mf * 16 * LDK + kk) * 4u);                \
        ldsm4(bb[0][0], bb[0][1], bb[1][0], bb[1][1],                        \
              baseB + (off) + kk * 4u);                                      \
        ldsm4(bb[2][0], bb[2][1], bb[3][0], bb[3][1],                        \
              baseB + (off) + (16 * LDK + kk) * 4u);                         \
        _Pragma("unroll")                                                    \
        for (int mf = 0; mf < 4; mf++)                                       \
            _Pragma("unroll")                                                \
            for (int nf = 0; nf < 4; nf++)                                   \
                mma_tf32(acc[mf][nf], a[mf][0], a[mf][1], a[mf][2], a[mf][3],\
                         bb[nf][0], bb[nf][1]);                              \
    }

// ----- fp16 path (k_s, k_vp, k_av): BK = 32 halves -----
#define LDSM16_BASES(AsT, BsT)                                               \
    const unsigned baseA = smem_u32(AsT) +                                   \
        (((wm * 64) + (lane & 15)) * LDH + ((lane >> 4) * 8)) * 2u;          \
    const unsigned baseB = smem_u32(BsT) +                                   \
        (((wn * 32) + (lane & 7) + ((lane >> 4) * 8)) * LDH +                \
         (((lane >> 3) & 1) * 8)) * 2u;

#define MMA16_TILE_BODY(off)                                                 \
    _Pragma("unroll")                                                        \
    for (int kk = 0; kk < 2; kk++) {                                         \
        unsigned a[4][4], bb[4][2];                                          \
        _Pragma("unroll")                                                    \
        for (int mf = 0; mf < 4; mf++)                                       \
            ldsm4(a[mf][0], a[mf][1], a[mf][2], a[mf][3],                    \
                  baseA + (off) + (mf * 16 * LDH + kk * 16) * 2u);           \
        ldsm4(bb[0][0], bb[0][1], bb[1][0], bb[1][1],                        \
              baseB + (off) + (kk * 16) * 2u);                               \
        ldsm4(bb[2][0], bb[2][1], bb[3][0], bb[3][1],                        \
              baseB + (off) + (16 * LDH + kk * 16) * 2u);                    \
        _Pragma("unroll")                                                    \
        for (int mf = 0; mf < 4; mf++)                                       \
            _Pragma("unroll")                                                \
            for (int nf = 0; nf < 4; nf++)                                   \
                mma_f16(acc[mf][nf], a[mf][0], a[mf][1], a[mf][2], a[mf][3], \
                        bb[nf][0], bb[nf][1]);                               \
    }

// ---------------- kernel 0: zero the sum accumulators ------------------------
__global__ void k_zero() {
    int i = blockIdx.x * blockDim.x + threadIdx.x;
    if (i < B_ * N_) { g_csum[i] = 0.f; g_rsum[i] = 0.f; }
}

// ---------------- kernel 1: transpose pf [B,PC,N] -> rp16 [B,N,PC] -----------
__global__ void k_transpose(const float* __restrict__ pf) {
    __shared__ float tile[32][33];
    const int b  = blockIdx.z;
    const int n0 = blockIdx.x * 32;
    const int d0 = blockIdx.y * 32;
    const float* src = pf + (size_t)b * PC_ * N_;
    __half*      dst = g_rp16 + (size_t)b * N_ * PC_;
    const int tx = threadIdx.x, ty = threadIdx.y;   // (32, 8)
#pragma unroll
    for (int j = 0; j < 32; j += 8)
        tile[ty + j][tx] = src[(size_t)(d0 + ty + j) * N_ + n0 + tx];
    __syncthreads();
#pragma unroll
    for (int j = 0; j < 32; j += 8)
        dst[(size_t)(n0 + ty + j) * PC_ + d0 + tx] = __float2half_rn(tile[tx][ty + j]);
}

// ---------------- kernel 2: ri16 = half(img^T @ fc2_w^T + fc2_b) -------------
__global__ __launch_bounds__(256, 2) void k_ri(const float* __restrict__ img,
                                               const float* __restrict__ w,
                                               const float* __restrict__ bias) {
    const int b  = blockIdx.y;
    const int n0 = blockIdx.x * 128;
    const float* X = img + (size_t)b * IC_ * N_;
    __half*      R = g_ri16 + (size_t)b * N_ * PC_;

    __shared__ __align__(16) unsigned AsT[2][128][LDK];
    __shared__ __align__(16) unsigned BsT[2][128][LDK];

    WARP_COORDS
    LDSM_BASES(AsT, BsT)

    const int rowT = (wid & 3) * 32 + lane;
    const int kcb  = wid >> 2;
    const int fi = tid >> 2, fc = (tid & 3) * 4;

    ZERO_ACC

    float va[2][4]; float4 rb[2];
#pragma unroll
    for (int r = 0; r < 2; r++) {
        int kc = kcb + 2 * r;
#pragma unroll
        for (int j = 0; j < 4; j++)
            va[r][j] = X[(size_t)(kc * 4 + j) * N_ + n0 + rowT];
        rb[r] = *(const float4*)&w[(size_t)(fi + r * 64) * IC_ + fc];
    }

    int p = 0;
    for (int k0 = 0; k0 < IC_; k0 += 16) {
#pragma unroll
        for (int r = 0; r < 2; r++) {
            int kc = kcb + 2 * r;
            *(uint4*)&AsT[p][rowT][kc * 4]    = cvt4(va[r][0], va[r][1], va[r][2], va[r][3]);
            *(uint4*)&BsT[p][fi + r * 64][fc] = cvt4(rb[r].x, rb[r].y, rb[r].z, rb[r].w);
        }
        __syncthreads();
        if (k0 + 16 < IC_) {
            int kn = k0 + 16;
#pragma unroll
            for (int r = 0; r < 2; r++) {
                int kc = kcb + 2 * r;
#pragma unroll
                for (int j = 0; j < 4; j++)
                    va[r][j] = X[(size_t)(kn + kc * 4 + j) * N_ + n0 + rowT];
                rb[r] = *(const float4*)&w[(size_t)(fi + r * 64) * IC_ + kn + fc];
            }
        }
        const unsigned off = p * BUFB;
        MMA_TILE_BODY(off)
        __syncthreads();
        p ^= 1;
    }
#pragma unroll
    for (int mf = 0; mf < 4; mf++) {
        int row = n0 + wm * 64 + mf * 16 + g;
#pragma unroll
        for (int nf = 0; nf < 4; nf++) {
            int col = wn * 32 + nf * 8 + 2 * t;
            float b0 = bias[col], b1 = bias[col + 1];
            *(unsigned*)&R[(size_t)row * PC_ + col] =
                h2pack(acc[mf][nf][0] + b0, acc[mf][nf][1] + b1);
            *(unsigned*)&R[(size_t)(row + 8) * PC_ + col] =
                h2pack(acc[mf][nf][2] + b0, acc[mf][nf][3] + b1);
        }
    }
}

// ---------------- kernel 3: P = exp(scale * rp @ ri^T); P, P^T (fp16), sums --
__global__ __launch_bounds__(256, 2) void k_s() {
    const int b  = blockIdx.z;
    const int i0 = blockIdx.y * 128;
    const int j0 = blockIdx.x * 128;
    const __half* A16 = g_rp16 + (size_t)b * N_ * PC_ + (size_t)i0 * PC_;
    const __half* B16 = g_ri16 + (size_t)b * N_ * PC_ + (size_t)j0 * PC_;
    __half*       Pp  = g_S16  + (size_t)b * N_ * N_;
    __half*       Pt  = g_ST16 + (size_t)b * N_ * N_;

    __shared__ __align__(16) __half AsT[2][128][LDH];
    __shared__ __align__(16) __half BsT[2][128][LDH];
    __shared__ float shr[128], shc[128];

    WARP_COORDS
    LDSM16_BASES(AsT, BsT)

    const unsigned sAu = smem_u32(AsT);
    const unsigned sBu = smem_u32(BsT);
    const int frow = tid >> 1, fg0 = (tid & 1) * 2;

#define FILL_S16(pp, kk0)                                                    \
    _Pragma("unroll")                                                        \
    for (int r = 0; r < 2; r++) {                                            \
        int gq = fg0 + r;                                                    \
        unsigned o = (pp) * BUFH + ((unsigned)frow * LDH + gq * 8) * 2u;     \
        CPA16(sAu + o, A16 + (size_t)frow * PC_ + (kk0) + gq * 8);           \
        CPA16(sBu + o, B16 + (size_t)frow * PC_ + (kk0) + gq * 8);           \
    }                                                                        \
    CPA_COMMIT();

    ZERO_ACC

    FILL_S16(0, 0)
    int p = 0;
    for (int ch = 0; ch < 4; ch++) {             // PC_/32 chunks
        if (ch + 1 < 4) { FILL_S16(p ^ 1, (ch + 1) * 32) CPA_WAIT1(); }
        else            { CPA_WAIT0(); }
        __syncthreads();
        const unsigned off = p * BUFH;
        MMA16_TILE_BODY(off)
        __syncthreads();
        p ^= 1;
    }
#undef FILL_S16

    if (tid < 128) { shr[tid] = 0.f; shc[tid] = 0.f; }
    __syncthreads();

    float rs[4][2] = {{0.f,0.f},{0.f,0.f},{0.f,0.f},{0.f,0.f}};
    float cs[4][2] = {{0.f,0.f},{0.f,0.f},{0.f,0.f},{0.f,0.f}};
#pragma unroll
    for (int mf = 0; mf < 4; mf++) {
        int row = i0 + wm * 64 + mf * 16 + g;
#pragma unroll
        for (int nf = 0; nf < 4; nf++) {
            int col = j0 + wn * 32 + nf * 8 + 2 * t;
            float p0 = __expf(acc[mf][nf][0] * SCALE_);
            float p1 = __expf(acc[mf][nf][1] * SCALE_);
            float p2 = __expf(acc[mf][nf][2] * SCALE_);
            float p3 = __expf(acc[mf][nf][3] * SCALE_);
            *(unsigned*)&Pp[(size_t)row * N_ + col]       = h2pack(p0, p1);
            *(unsigned*)&Pp[(size_t)(row + 8) * N_ + col] = h2pack(p2, p3);
            Pt[(size_t)col * N_ + row]           = __float2half_rn(p0);
            Pt[(size_t)(col + 1) * N_ + row]     = __float2half_rn(p1);
            Pt[(size_t)col * N_ + row + 8]       = __float2half_rn(p2);
            Pt[(size_t)(col + 1) * N_ + row + 8] = __float2half_rn(p3);
            rs[mf][0] += p0 + p1; rs[mf][1] += p2 + p3;
            cs[nf][0] += p0 + p2; cs[nf][1] += p1 + p3;
        }
    }
#pragma unroll
    for (int mf = 0; mf < 4; mf++)
#pragma unroll
        for (int h = 0; h < 2; h++) {
            float v = rs[mf][h];
            v += __shfl_xor_sync(0xffffffffu, v, 1);
            v += __shfl_xor_sync(0xffffffffu, v, 2);
            if (t == 0) atomicAdd(&shr[wm * 64 + mf * 16 + h * 8 + g], v);
        }
#pragma unroll
    for (int nf = 0; nf < 4; nf++)
#pragma unroll
        for (int q = 0; q < 2; q++) {
            float v = cs[nf][q];
            v += __shfl_xor_sync(0xffffffffu, v, 4);
            v += __shfl_xor_sync(0xffffffffu, v, 8);
            v += __shfl_xor_sync(0xffffffffu, v, 16);
            if (g == 0) atomicAdd(&shc[wn * 32 + nf * 8 + 2 * t + q], v);
        }
    __syncthreads();
    if (tid < 128) {
        atomicAdd(&g_rsum[b * N_ + i0 + tid], shr[tid]);
        atomicAdd(&g_csum[b * N_ + j0 + tid], shc[tid]);
    }
}

// ---------------- kernel 4: vT16 = half(VSCALE * ((Src@W^T)/sum))^T ----------
__global__ __launch_bounds__(256, 2) void k_vp(const float* __restrict__ w) {
    const int which = blockIdx.y;
    const int b  = blockIdx.z;
    const int j0 = blockIdx.x * 128;
    const __half* Src = (which ? g_ri16 : g_rp16) + (size_t)b * N_ * PC_ + (size_t)j0 * PC_;
    const float*  sum = (which ? g_rsum : g_csum) + b * N_;
    __half*       Dst = g_vT16[which] + (size_t)b * OC_ * N_;

    __shared__ __align__(16) __half AsT[2][128][LDH];
    __shared__ __align__(16) __half BsT[2][128][LDH];

    WARP_COORDS
    LDSM16_BASES(AsT, BsT)

    const unsigned sAu = smem_u32(AsT);
    const int frow = tid >> 1, fg0 = (tid & 1) * 2;

    ZERO_ACC

#define FILL_VP(pp, kk0)                                                     \
    _Pragma("unroll")                                                        \
    for (int r = 0; r < 2; r++) {                                            \
        int gq = fg0 + r;                                                    \
        unsigned o = (pp) * BUFH + ((unsigned)frow * LDH + gq * 8) * 2u;     \
        CPA16(sAu + o, Src + (size_t)frow * PC_ + (kk0) + gq * 8);           \
        const float* ws = &w[(size_t)frow * (2 * PC_) + which * PC_ + (kk0) + gq * 8]; \
        float4 v0 = *(const float4*)ws, v1 = *(const float4*)(ws + 4);       \
        *(uint4*)((char*)BsT + (pp) * BUFH + frow * (LDH * 2) + gq * 16) =   \
            make_uint4(h2pack(v0.x, v0.y), h2pack(v0.z, v0.w),               \
                       h2pack(v1.x, v1.y), h2pack(v1.z, v1.w));              \
    }                                                                        \
    CPA_COMMIT();

    FILL_VP(0, 0)
    int p = 0;
    for (int ch = 0; ch < 4; ch++) {
        if (ch + 1 < 4) { FILL_VP(p ^ 1, (ch + 1) * 32) CPA_WAIT1(); }
        else            { CPA_WAIT0(); }
        __syncthreads();
        const unsigned off = p * BUFH;
        MMA16_TILE_BODY(off)
        __syncthreads();
        p ^= 1;
    }
#undef FILL_VP

#pragma unroll
    for (int mf = 0; mf < 4; mf++) {
        int row = j0 + wm * 64 + mf * 16 + g;
        float inv0 = __fdividef(VSCALE, sum[row]);
        float inv8 = __fdividef(VSCALE, sum[row + 8]);
#pragma unroll
        for (int nf = 0; nf < 4; nf++) {
            int col = wn * 32 + nf * 8 + 2 * t;
            Dst[(size_t)col * N_ + row]           = __float2half_rn(acc[mf][nf][0] * inv0);
            Dst[(size_t)(col + 1) * N_ + row]     = __float2half_rn(acc[mf][nf][1] * inv0);
            Dst[(size_t)col * N_ + row + 8]       = __float2half_rn(acc[mf][nf][2] * inv8);
            Dst[(size_t)(col + 1) * N_ + row + 8] = __float2half_rn(acc[mf][nf][3] * inv8);
        }
    }
}

// ---------------- kernel 5: AV partial GEMMs (fp16, cp.async, 4-way ksplit) --
// mode 0: d = P [i-block, krange] @ vT0^T ; mode 1: d = P^T[i-block, krange] @ vT1^T
__global__ __launch_bounds__(256, 2) void k_av() {
    const int mode = blockIdx.x & 1;
    const int ks   = blockIdx.x >> 1;
    const int b    = blockIdx.z;
    const int i0   = blockIdx.y * 128;
    const int kb   = ks * KSPL;
    const __half* M  = (mode == 0 ? g_S16 : g_ST16) + (size_t)b * N_ * N_ + (size_t)i0 * N_;
    const __half* Vt = g_vT16[mode] + (size_t)b * OC_ * N_;
    float*        D  = g_d[(mode << 2) | ks] + (size_t)b * N_ * OC_;

    __shared__ __align__(16) __half AsT[2][128][LDH];
    __shared__ __align__(16) __half BsT[2][128][LDH];

    WARP_COORDS
    LDSM16_BASES(AsT, BsT)

    const unsigned sAu = smem_u32(AsT);
    const unsigned sBu = smem_u32(BsT);
    const int frow = tid >> 1, fg0 = (tid & 1) * 2;

#define FILL_AV16(pp, kk0)                                                   \
    _Pragma("unroll")                                                        \
    for (int r = 0; r < 2; r++) {                                            \
        int gq = fg0 + r;                                                    \
        unsigned o = (pp) * BUFH + ((unsigned)frow * LDH + gq * 8) * 2u;     \
        CPA16(sAu + o, M  + (size_t)frow * N_ + (kk0) + gq * 8);             \
        CPA16(sBu + o, Vt + (size_t)frow * N_ + (kk0) + gq * 8);             \
    }                                                                        \
    CPA_COMMIT();

    ZERO_ACC

    FILL_AV16(0, kb)
    int p = 0;
    const int NCH = KSPL / 32;
    for (int ch = 0; ch < NCH; ch++) {
        if (ch + 1 < NCH) { FILL_AV16(p ^ 1, kb + (ch + 1) * 32) CPA_WAIT1(); }
        else              { CPA_WAIT0(); }
        __syncthreads();
        const unsigned off = p * BUFH;
        MMA16_TILE_BODY(off)
        __syncthreads();
        p ^= 1;
    }
#undef FILL_AV16

#pragma unroll
    for (int mf = 0; mf < 4; mf++) {
        int row = i0 + wm * 64 + mf * 16 + g;
#pragma unroll
        for (int nf = 0; nf < 4; nf++) {
            int col = wn * 32 + nf * 8 + 2 * t;
            *(float2*)&D[(size_t)row * OC_ + col]       = make_float2(acc[mf][nf][0], acc[mf][nf][1]);
            *(float2*)&D[(size_t)(row + 8) * OC_ + col] = make_float2(acc[mf][nf][2], acc[mf][nf][3]);
        }
    }
}

// ---------------- kernel 6: sum partials/VSCALE + BN + ReLU + transpose ------
__global__ void k_bn(const float* __restrict__ cb,    const float* __restrict__ gamma,
                     const float* __restrict__ beta,  const float* __restrict__ mean,
                     const float* __restrict__ var,   float* __restrict__ out) {
    __shared__ float tile[32][33];
    const int b  = blockIdx.z;
    const int n0 = blockIdx.x * 32;
    const int o0 = blockIdx.y * 32;
    const int tx = threadIdx.x, ty = threadIdx.y;   // (32, 8)
#pragma unroll
    for (int j = 0; j < 32; j += 8) {
        size_t idx = (size_t)b * N_ * OC_ + (size_t)(n0 + ty + j) * OC_ + o0 + tx;
        float s = 0.f;
#pragma unroll
        for (int m = 0; m < 8; m++) s += g_d[m][idx];
        tile[ty + j][tx] = s * (1.0f / VSCALE);
    }
    __syncthreads();
#pragma unroll
    for (int j = 0; j < 32; j += 8) {
        int o = o0 + ty + j;
        float gm   = gamma[o] * rsqrtf(var[o] + 1e-5f);
        float base = gm * (cb[o] - mean[o]) + beta[o];
        out[(size_t)b * OC_ * N_ + (size_t)o * N_ + n0 + tx] =
            fmaxf(gm * tile[tx][ty + j] + base, 0.f);
    }
}

// ---------------- launch -----------------------------------------------------
extern "C" void kernel_launch(void* const* d_in, const int* in_sizes, int n_in,
                              void* d_out, int out_size) {
    const float* pf     = (const float*)d_in[0];
    const float* img    = (const float*)d_in[1];
    const float* fc2_w  = (const float*)d_in[2];
    const float* fc2_b  = (const float*)d_in[3];
    const float* conv_w = (const float*)d_in[4];
    const float* conv_b = (const float*)d_in[5];
    const float* gamma  = (const float*)d_in[6];
    const float* beta   = (const float*)d_in[7];
    const float* mean   = (const float*)d_in[8];
    const float* var    = (const float*)d_in[9];
    float* out = (float*)d_out;

    k_zero     <<<(B_ * N_ + 511) / 512, 512>>>();
    k_transpose<<<dim3(N_ / 32, PC_ / 32, B_), dim3(32, 8)>>>(pf);
    k_ri       <<<dim3(N_ / 128, B_),           256>>>(img, fc2_w, fc2_b);
    k_s        <<<dim3(N_ / 128, N_ / 128, B_), 256>>>();
    k_vp       <<<dim3(N_ / 128, 2, B_),        256>>>(conv_w);
    k_av       <<<dim3(8, N_ / 128, B_),        256>>>();
    k_bn       <<<dim3(N_ / 32, OC_ / 32, B_),  dim3(32, 8)>>>(conv_b, gamma, beta,
                                                               mean, var, out);
}

// round 12
// speedup vs baseline: 3.3609x; 1.0645x over previous
#include <cuda_runtime.h>
#include <cuda_fp16.h>
#include <math.h>

#define B_   2
#define N_   4096
#define IC_  256
#define PC_  128
#define OC_  128
#define SCALE_ 0.08838834764831845f   // 1/sqrt(128)
#define VSCALE 4096.0f                 // vT scaling to stay in fp16 normal range
#define LDK  20                        // tf32 tile pitch (floats) — k_ri only
#define BUFB (128u * LDK * 4u)
#define LDH  40                        // fp16 tile pitch (halves), 80 B/row
#define BUFH (128u * LDH * 2u)         // 10240 B per fp16 plane
#define KSPL (N_ / 4)
#define LDT  136                       // staged-transpose tile pitch (halves)

// ---------------- scratch (device globals) ----------------------------------
static __device__ __align__(16) __half g_rp16[(size_t)B_ * N_ * PC_];
static __device__ __align__(16) __half g_ri16[(size_t)B_ * N_ * PC_];
static __device__ __align__(16) __half g_S16 [(size_t)B_ * N_ * N_];   // P
static __device__ __align__(16) __half g_ST16[(size_t)B_ * N_ * N_];   // P^T
static __device__ __align__(16) __half g_vT16[2][(size_t)B_ * OC_ * N_]; // v^T * VSCALE
static __device__ __align__(16) float  g_csum[B_ * N_];
static __device__ __align__(16) float  g_rsum[B_ * N_];
static __device__ __align__(16) float  g_d   [8][(size_t)B_ * N_ * OC_]; // fp32 partials

// ---------------- helpers ----------------------------------------------------
__device__ __forceinline__ unsigned tf32_of(float x) {
    unsigned r; asm("cvt.rna.tf32.f32 %0, %1;" : "=r"(r) : "f"(x)); return r;
}
__device__ __forceinline__ uint4 cvt4(float a, float b, float c, float d) {
    return make_uint4(tf32_of(a), tf32_of(b), tf32_of(c), tf32_of(d));
}
__device__ __forceinline__ unsigned h2pack(float a, float b) {
    __half2 h = __floats2half2_rn(a, b);
    return *reinterpret_cast<unsigned*>(&h);
}
__device__ __forceinline__ void mma_tf32(float* c, unsigned a0, unsigned a1,
                                         unsigned a2, unsigned a3,
                                         unsigned b0, unsigned b1) {
    asm volatile(
        "mma.sync.aligned.m16n8k8.row.col.f32.tf32.tf32.f32 "
        "{%0,%1,%2,%3}, {%4,%5,%6,%7}, {%8,%9}, {%0,%1,%2,%3};"
        : "+f"(c[0]), "+f"(c[1]), "+f"(c[2]), "+f"(c[3])
        : "r"(a0), "r"(a1), "r"(a2), "r"(a3), "r"(b0), "r"(b1));
}
__device__ __forceinline__ void mma_f16(float* c, unsigned a0, unsigned a1,
                                        unsigned a2, unsigned a3,
                                        unsigned b0, unsigned b1) {
    asm volatile(
        "mma.sync.aligned.m16n8k16.row.col.f32.f16.f16.f32 "
        "{%0,%1,%2,%3}, {%4,%5,%6,%7}, {%8,%9}, {%0,%1,%2,%3};"
        : "+f"(c[0]), "+f"(c[1]), "+f"(c[2]), "+f"(c[3])
        : "r"(a0), "r"(a1), "r"(a2), "r"(a3), "r"(b0), "r"(b1));
}
__device__ __forceinline__ unsigned smem_u32(const void* p) {
    unsigned a;
    asm("{.reg .u64 t; cvta.to.shared.u64 t, %1; cvt.u32.u64 %0, t;}"
        : "=r"(a) : "l"(p));
    return a;
}
__device__ __forceinline__ void ldsm4(unsigned& r0, unsigned& r1,
                                      unsigned& r2, unsigned& r3, unsigned addr) {
    asm volatile("ldmatrix.sync.aligned.m8n8.x4.shared.b16 {%0,%1,%2,%3}, [%4];"
                 : "=r"(r0), "=r"(r1), "=r"(r2), "=r"(r3) : "r"(addr));
}
#define CPA16(dst, src) asm volatile("cp.async.cg.shared.global [%0], [%1], 16;" \
                                     :: "r"(dst), "l"(src) : "memory")
#define CPA_COMMIT()    asm volatile("cp.async.commit_group;" ::: "memory")
#define CPA_WAIT0()     asm volatile("cp.async.wait_group 0;" ::: "memory")
#define CPA_WAIT1()     asm volatile("cp.async.wait_group 1;" ::: "memory")

#define WARP_COORDS                                                          \
    const int tid  = threadIdx.x;                                            \
    const int lane = tid & 31, wid = tid >> 5;                               \
    const int wm = wid & 1, wn = wid >> 1;                                   \
    const int g = lane >> 2, t = lane & 3;                                   \
    const int jm = lane >> 3;                                                \
    (void)g; (void)t; (void)jm;

#define ZERO_ACC                                                             \
    float acc[4][4][4];                                                      \
    _Pragma("unroll")                                                        \
    for (int mf = 0; mf < 4; mf++)                                           \
        _Pragma("unroll")                                                    \
        for (int nf = 0; nf < 4; nf++)                                       \
            _Pragma("unroll")                                                 \
            for (int q = 0; q < 4; q++) acc[mf][nf][q] = 0.f;

// ----- tf32 path (k_ri only) -----
#define LDSM_BASES(AsT, BsT)                                                 \
    const unsigned baseA = smem_u32(&AsT[0][0][0]) +                         \
        (((wm * 64) + ((jm & 1) * 8) + (lane & 7)) * LDK + ((jm >> 1) * 4)) * 4u; \
    const unsigned baseB = smem_u32(&BsT[0][0][0]) +                         \
        (((wn * 32) + ((jm >> 1) * 8) + (lane & 7)) * LDK + ((jm & 1) * 4)) * 4u;

#define MMA_TILE_BODY(off)                                                   \
    for (int kk = 0; kk < 16; kk += 8) {                                     \
        unsigned a[4][4], bb[4][2];                                          \
        _Pragma("unroll")                                                    \
        for (int mf = 0; mf < 4; mf++)                                       \
            ldsm4(a[mf][0], a[mf][1], a[mf][2], a[mf][3],                    \
                  baseA + (off) + (mf * 16 * LDK + kk) * 4u);                \
        ldsm4(bb[0][0], bb[0][1], bb[1][0], bb[1][1],                        \
              baseB + (off) + kk * 4u);                                      \
        ldsm4(bb[2][0], bb[2][1], bb[3][0], bb[3][1],                        \
              baseB + (off) + (16 * LDK + kk) * 4u);                         \
        _Pragma("unroll")                                                    \
        for (int mf = 0; mf < 4; mf++)                                       \
            _Pragma("unroll")                                                \
            for (int nf = 0; nf < 4; nf++)                                   \
                mma_tf32(acc[mf][nf], a[mf][0], a[mf][1], a[mf][2], a[mf][3],\
                         bb[nf][0], bb[nf][1]);                              \
    }

// ----- fp16 path: BK = 32 halves, bases given as raw smem addresses -----
#define LDSM16_BASES_U(aU, bU)                                               \
    const unsigned baseA = (aU) +                                            \
        ((((wm * 64) + (lane & 15)) * LDH + ((lane >> 4) * 8)) * 2u);        \
    const unsigned baseB = (bU) +                                            \
        ((((wn * 32) + (lane & 7) + ((lane >> 4) * 8)) * LDH +               \
          (((lane >> 3) & 1) * 8)) * 2u);

#define MMA16_TILE_BODY(off)                                                 \
    _Pragma("unroll")                                                        \
    for (int kk = 0; kk < 2; kk++) {                                         \
        unsigned a[4][4], bb[4][2];                                          \
        _Pragma("unroll")                                                    \
        for (int mf = 0; mf < 4; mf++)                                       \
            ldsm4(a[mf][0], a[mf][1], a[mf][2], a[mf][3],                    \
                  baseA + (off) + (mf * 16 * LDH + kk * 16) * 2u);           \
        ldsm4(bb[0][0], bb[0][1], bb[1][0], bb[1][1],                        \
              baseB + (off) + (kk * 16) * 2u);                               \
        ldsm4(bb[2][0], bb[2][1], bb[3][0], bb[3][1],                        \
              baseB + (off) + (16 * LDH + kk * 16) * 2u);                    \
        _Pragma("unroll")                                                    \
        for (int mf = 0; mf < 4; mf++)                                       \
            _Pragma("unroll")                                                \
            for (int nf = 0; nf < 4; nf++)                                   \
                mma_f16(acc[mf][nf], a[mf][0], a[mf][1], a[mf][2], a[mf][3], \
                        bb[nf][0], bb[nf][1]);                               \
    }

// ---------------- kernel 0: zero the sum accumulators ------------------------
__global__ void k_zero() {
    int i = blockIdx.x * blockDim.x + threadIdx.x;
    if (i < B_ * N_) { g_csum[i] = 0.f; g_rsum[i] = 0.f; }
}

// ---------------- kernel 1: transpose pf [B,PC,N] -> rp16 [B,N,PC] -----------
__global__ void k_transpose(const float* __restrict__ pf) {
    __shared__ float tile[32][33];
    const int b  = blockIdx.z;
    const int n0 = blockIdx.x * 32;
    const int d0 = blockIdx.y * 32;
    const float* src = pf + (size_t)b * PC_ * N_;
    __half*      dst = g_rp16 + (size_t)b * N_ * PC_;
    const int tx = threadIdx.x, ty = threadIdx.y;   // (32, 8)
#pragma unroll
    for (int j = 0; j < 32; j += 8)
        tile[ty + j][tx] = src[(size_t)(d0 + ty + j) * N_ + n0 + tx];
    __syncthreads();
#pragma unroll
    for (int j = 0; j < 32; j += 8)
        dst[(size_t)(n0 + ty + j) * PC_ + d0 + tx] = __float2half_rn(tile[tx][ty + j]);
}

// ---------------- kernel 2: ri16 = half(img^T @ fc2_w^T + fc2_b) -------------
__global__ __launch_bounds__(256, 2) void k_ri(const float* __restrict__ img,
                                               const float* __restrict__ w,
                                               const float* __restrict__ bias) {
    const int b  = blockIdx.y;
    const int n0 = blockIdx.x * 128;
    const float* X = img + (size_t)b * IC_ * N_;
    __half*      R = g_ri16 + (size_t)b * N_ * PC_;

    __shared__ __align__(16) unsigned AsT[2][128][LDK];
    __shared__ __align__(16) unsigned BsT[2][128][LDK];

    WARP_COORDS
    LDSM_BASES(AsT, BsT)

    const int rowT = (wid & 3) * 32 + lane;
    const int kcb  = wid >> 2;
    const int fi = tid >> 2, fc = (tid & 3) * 4;

    ZERO_ACC

    float va[2][4]; float4 rb[2];
#pragma unroll
    for (int r = 0; r < 2; r++) {
        int kc = kcb + 2 * r;
#pragma unroll
        for (int j = 0; j < 4; j++)
            va[r][j] = X[(size_t)(kc * 4 + j) * N_ + n0 + rowT];
        rb[r] = *(const float4*)&w[(size_t)(fi + r * 64) * IC_ + fc];
    }

    int p = 0;
    for (int k0 = 0; k0 < IC_; k0 += 16) {
#pragma unroll
        for (int r = 0; r < 2; r++) {
            int kc = kcb + 2 * r;
            *(uint4*)&AsT[p][rowT][kc * 4]    = cvt4(va[r][0], va[r][1], va[r][2], va[r][3]);
            *(uint4*)&BsT[p][fi + r * 64][fc] = cvt4(rb[r].x, rb[r].y, rb[r].z, rb[r].w);
        }
        __syncthreads();
        if (k0 + 16 < IC_) {
            int kn = k0 + 16;
#pragma unroll
            for (int r = 0; r < 2; r++) {
                int kc = kcb + 2 * r;
#pragma unroll
                for (int j = 0; j < 4; j++)
                    va[r][j] = X[(size_t)(kn + kc * 4 + j) * N_ + n0 + rowT];
                rb[r] = *(const float4*)&w[(size_t)(fi + r * 64) * IC_ + kn + fc];
            }
        }
        const unsigned off = p * BUFB;
        MMA_TILE_BODY(off)
        __syncthreads();
        p ^= 1;
    }
#pragma unroll
    for (int mf = 0; mf < 4; mf++) {
        int row = n0 + wm * 64 + mf * 16 + g;
#pragma unroll
        for (int nf = 0; nf < 4; nf++) {
            int col = wn * 32 + nf * 8 + 2 * t;
            float b0 = bias[col], b1 = bias[col + 1];
            *(unsigned*)&R[(size_t)row * PC_ + col] =
                h2pack(acc[mf][nf][0] + b0, acc[mf][nf][1] + b1);
            *(unsigned*)&R[(size_t)(row + 8) * PC_ + col] =
                h2pack(acc[mf][nf][2] + b0, acc[mf][nf][3] + b1);
        }
    }
}

// ---------------- kernel 3: P = exp(scale * rp @ ri^T); P, staged P^T, sums --
__global__ __launch_bounds__(256, 2) void k_s() {
    const int b  = blockIdx.z;
    const int i0 = blockIdx.y * 128;
    const int j0 = blockIdx.x * 128;
    const __half* A16 = g_rp16 + (size_t)b * N_ * PC_ + (size_t)i0 * PC_;
    const __half* B16 = g_ri16 + (size_t)b * N_ * PC_ + (size_t)j0 * PC_;
    __half*       Pp  = g_S16  + (size_t)b * N_ * N_;
    __half*       Pt  = g_ST16 + (size_t)b * N_ * N_;

    // blob: mainloop operand planes (40960 B), reused as staged P^T tile (34816 B)
    __shared__ __align__(16) char blob[40960];
    __shared__ float shr[128], shc[128];

    WARP_COORDS

    const unsigned sAu = smem_u32(blob);
    const unsigned sBu = sAu + 2 * BUFH;
    LDSM16_BASES_U(sAu, sBu)

    const int frow = tid >> 1, fg0 = (tid & 1) * 2;

#define FILL_S16(pp, kk0)                                                    \
    _Pragma("unroll")                                                        \
    for (int r = 0; r < 2; r++) {                                            \
        int gq = fg0 + r;                                                    \
        unsigned o = (pp) * BUFH + ((unsigned)frow * LDH + gq * 8) * 2u;     \
        CPA16(sAu + o, A16 + (size_t)frow * PC_ + (kk0) + gq * 8);           \
        CPA16(sBu + o, B16 + (size_t)frow * PC_ + (kk0) + gq * 8);           \
    }                                                                        \
    CPA_COMMIT();

    ZERO_ACC

    FILL_S16(0, 0)
    int p = 0;
    for (int ch = 0; ch < 4; ch++) {             // PC_/32 chunks
        if (ch + 1 < 4) { FILL_S16(p ^ 1, (ch + 1) * 32) CPA_WAIT1(); }
        else            { CPA_WAIT0(); }
        __syncthreads();
        const unsigned off = p * BUFH;
        MMA16_TILE_BODY(off)
        __syncthreads();
        p ^= 1;
    }
#undef FILL_S16

    // epilogue: operand planes are dead; reuse blob as the P^T staging tile.
    __half* Tsm = (__half*)blob;
    if (tid < 128) { shr[tid] = 0.f; shc[tid] = 0.f; }
    __syncthreads();

    float rs[4][2] = {{0.f,0.f},{0.f,0.f},{0.f,0.f},{0.f,0.f}};
    float cs[4][2] = {{0.f,0.f},{0.f,0.f},{0.f,0.f},{0.f,0.f}};
#pragma unroll
    for (int mf = 0; mf < 4; mf++) {
        int rl = wm * 64 + mf * 16 + g;          // local row in tile
        int row = i0 + rl;
#pragma unroll
        for (int nf = 0; nf < 4; nf++) {
            int cl = wn * 32 + nf * 8 + 2 * t;   // local col in tile
            float p0 = __expf(acc[mf][nf][0] * SCALE_);
            float p1 = __expf(acc[mf][nf][1] * SCALE_);
            float p2 = __expf(acc[mf][nf][2] * SCALE_);
            float p3 = __expf(acc[mf][nf][3] * SCALE_);
            *(unsigned*)&Pp[(size_t)row * N_ + j0 + cl]       = h2pack(p0, p1);
            *(unsigned*)&Pp[(size_t)(row + 8) * N_ + j0 + cl] = h2pack(p2, p3);
            Tsm[cl * LDT + rl]           = __float2half_rn(p0);
            Tsm[(cl + 1) * LDT + rl]     = __float2half_rn(p1);
            Tsm[cl * LDT + rl + 8]       = __float2half_rn(p2);
            Tsm[(cl + 1) * LDT + rl + 8] = __float2half_rn(p3);
            rs[mf][0] += p0 + p1; rs[mf][1] += p2 + p3;
            cs[nf][0] += p0 + p2; cs[nf][1] += p1 + p3;
        }
    }
#pragma unroll
    for (int mf = 0; mf < 4; mf++)
#pragma unroll
        for (int h = 0; h < 2; h++) {
            float v = rs[mf][h];
            v += __shfl_xor_sync(0xffffffffu, v, 1);
            v += __shfl_xor_sync(0xffffffffu, v, 2);
            if (t == 0) atomicAdd(&shr[wm * 64 + mf * 16 + h * 8 + g], v);
        }
#pragma unroll
    for (int nf = 0; nf < 4; nf++)
#pragma unroll
        for (int q = 0; q < 2; q++) {
            float v = cs[nf][q];
            v += __shfl_xor_sync(0xffffffffu, v, 4);
            v += __shfl_xor_sync(0xffffffffu, v, 8);
            v += __shfl_xor_sync(0xffffffffu, v, 16);
            if (g == 0) atomicAdd(&shc[wn * 32 + nf * 8 + 2 * t + q], v);
        }
    __syncthreads();

    // coalesced P^T write: 128 rows x 128 halves, uint4 chunks
#pragma unroll
    for (int i = tid; i < 128 * 16; i += 256) {
        int c = i >> 4, chk = i & 15;
        uint4 v = *(uint4*)&Tsm[c * LDT + chk * 8];
        *(uint4*)&Pt[(size_t)(j0 + c) * N_ + i0 + chk * 8] = v;
    }
    if (tid < 128) {
        atomicAdd(&g_rsum[b * N_ + i0 + tid], shr[tid]);
        atomicAdd(&g_csum[b * N_ + j0 + tid], shc[tid]);
    }
}

// ---------------- kernel 4: vT16 = half(VSCALE * ((Src@W^T)/sum))^T ----------
__global__ __launch_bounds__(256, 2) void k_vp(const float* __restrict__ w) {
    const int which = blockIdx.y;
    const int b  = blockIdx.z;
    const int j0 = blockIdx.x * 128;
    const __half* Src = (which ? g_ri16 : g_rp16) + (size_t)b * N_ * PC_ + (size_t)j0 * PC_;
    const float*  sum = (which ? g_rsum : g_csum) + b * N_;
    __half*       Dst = g_vT16[which] + (size_t)b * OC_ * N_;

    __shared__ __align__(16) __half AsT[2][128][LDH];
    __shared__ __align__(16) __half BsT[2][128][LDH];

    WARP_COORDS
    LDSM16_BASES_U(smem_u32(AsT), smem_u32(BsT))

    const unsigned sAu = smem_u32(AsT);
    const int frow = tid >> 1, fg0 = (tid & 1) * 2;

    ZERO_ACC

#define FILL_VP(pp, kk0)                                                     \
    _Pragma("unroll")                                                        \
    for (int r = 0; r < 2; r++) {                                            \
        int gq = fg0 + r;                                                    \
        unsigned o = (pp) * BUFH + ((unsigned)frow * LDH + gq * 8) * 2u;     \
        CPA16(sAu + o, Src + (size_t)frow * PC_ + (kk0) + gq * 8);           \
        const float* ws = &w[(size_t)frow * (2 * PC_) + which * PC_ + (kk0) + gq * 8]; \
        float4 v0 = *(const float4*)ws, v1 = *(const float4*)(ws + 4);       \
        *(uint4*)((char*)BsT + (pp) * BUFH + frow * (LDH * 2) + gq * 16) =   \
            make_uint4(h2pack(v0.x, v0.y), h2pack(v0.z, v0.w),               \
                       h2pack(v1.x, v1.y), h2pack(v1.z, v1.w));              \
    }                                                                        \
    CPA_COMMIT();

    FILL_VP(0, 0)
    int p = 0;
    for (int ch = 0; ch < 4; ch++) {
        if (ch + 1 < 4) { FILL_VP(p ^ 1, (ch + 1) * 32) CPA_WAIT1(); }
        else            { CPA_WAIT0(); }
        __syncthreads();
        const unsigned off = p * BUFH;
        MMA16_TILE_BODY(off)
        __syncthreads();
        p ^= 1;
    }
#undef FILL_VP

#pragma unroll
    for (int mf = 0; mf < 4; mf++) {
        int row = j0 + wm * 64 + mf * 16 + g;
        float inv0 = __fdividef(VSCALE, sum[row]);
        float inv8 = __fdividef(VSCALE, sum[row + 8]);
#pragma unroll
        for (int nf = 0; nf < 4; nf++) {
            int col = wn * 32 + nf * 8 + 2 * t;
            Dst[(size_t)col * N_ + row]           = __float2half_rn(acc[mf][nf][0] * inv0);
            Dst[(size_t)(col + 1) * N_ + row]     = __float2half_rn(acc[mf][nf][1] * inv0);
            Dst[(size_t)col * N_ + row + 8]       = __float2half_rn(acc[mf][nf][2] * inv8);
            Dst[(size_t)(col + 1) * N_ + row + 8] = __float2half_rn(acc[mf][nf][3] * inv8);
        }
    }
}

// ---------------- kernel 5: AV partial GEMMs (fp16, cp.async, 4-way ksplit) --
__global__ __launch_bounds__(256, 2) void k_av() {
    const int mode = blockIdx.x & 1;
    const int ks   = blockIdx.x >> 1;
    const int b    = blockIdx.z;
    const int i0   = blockIdx.y * 128;
    const int kb   = ks * KSPL;
    const __half* M  = (mode == 0 ? g_S16 : g_ST16) + (size_t)b * N_ * N_ + (size_t)i0 * N_;
    const __half* Vt = g_vT16[mode] + (size_t)b * OC_ * N_;
    float*        D  = g_d[(mode << 2) | ks] + (size_t)b * N_ * OC_;

    __shared__ __align__(16) __half AsT[2][128][LDH];
    __shared__ __align__(16) __half BsT[2][128][LDH];

    WARP_COORDS
    LDSM16_BASES_U(smem_u32(AsT), smem_u32(BsT))

    const unsigned sAu = smem_u32(AsT);
    const unsigned sBu = smem_u32(BsT);
    const int frow = tid >> 1, fg0 = (tid & 1) * 2;

#define FILL_AV16(pp, kk0)                                                   \
    _Pragma("unroll")                                                        \
    for (int r = 0; r < 2; r++) {                                            \
        int gq = fg0 + r;                                                    \
        unsigned o = (pp) * BUFH + ((unsigned)frow * LDH + gq * 8) * 2u;     \
        CPA16(sAu + o, M  + (size_t)frow * N_ + (kk0) + gq * 8);             \
        CPA16(sBu + o, Vt + (size_t)frow * N_ + (kk0) + gq * 8);             \
    }                                                                        \
    CPA_COMMIT();

    ZERO_ACC

    FILL_AV16(0, kb)
    int p = 0;
    const int NCH = KSPL / 32;
    for (int ch = 0; ch < NCH; ch++) {
        if (ch + 1 < NCH) { FILL_AV16(p ^ 1, kb + (ch + 1) * 32) CPA_WAIT1(); }
        else              { CPA_WAIT0(); }
        __syncthreads();
        const unsigned off = p * BUFH;
        MMA16_TILE_BODY(off)
        __syncthreads();
        p ^= 1;
    }
#undef FILL_AV16

#pragma unroll
    for (int mf = 0; mf < 4; mf++) {
        int row = i0 + wm * 64 + mf * 16 + g;
#pragma unroll
        for (int nf = 0; nf < 4; nf++) {
            int col = wn * 32 + nf * 8 + 2 * t;
            *(float2*)&D[(size_t)row * OC_ + col]       = make_float2(acc[mf][nf][0], acc[mf][nf][1]);
            *(float2*)&D[(size_t)(row + 8) * OC_ + col] = make_float2(acc[mf][nf][2], acc[mf][nf][3]);
        }
    }
}

// ---------------- kernel 6: sum partials/VSCALE + BN + ReLU + transpose ------
__global__ void k_bn(const float* __restrict__ cb,    const float* __restrict__ gamma,
                     const float* __restrict__ beta,  const float* __restrict__ mean,
                     const float* __restrict__ var,   float* __restrict__ out) {
    __shared__ float tile[32][33];
    const int b  = blockIdx.z;
    const int n0 = blockIdx.x * 32;
    const int o0 = blockIdx.y * 32;
    const int tx = threadIdx.x, ty = threadIdx.y;   // (32, 8)
#pragma unroll
    for (int j = 0; j < 32; j += 8) {
        size_t idx = (size_t)b * N_ * OC_ + (size_t)(n0 + ty + j) * OC_ + o0 + tx;
        float s = 0.f;
#pragma unroll
        for (int m = 0; m < 8; m++) s += g_d[m][idx];
        tile[ty + j][tx] = s * (1.0f / VSCALE);
    }
    __syncthreads();
#pragma unroll
    for (int j = 0; j < 32; j += 8) {
        int o = o0 + ty + j;
        float gm   = gamma[o] * rsqrtf(var[o] + 1e-5f);
        float base = gm * (cb[o] - mean[o]) + beta[o];
        out[(size_t)b * OC_ * N_ + (size_t)o * N_ + n0 + tx] =
            fmaxf(gm * tile[tx][ty + j] + base, 0.f);
    }
}

// ---------------- launch -----------------------------------------------------
extern "C" void kernel_launch(void* const* d_in, const int* in_sizes, int n_in,
                              void* d_out, int out_size) {
    const float* pf     = (const float*)d_in[0];
    const float* img    = (const float*)d_in[1];
    const float* fc2_w  = (const float*)d_in[2];
    const float* fc2_b  = (const float*)d_in[3];
    const float* conv_w = (const float*)d_in[4];
    const float* conv_b = (const float*)d_in[5];
    const float* gamma  = (const float*)d_in[6];
    const float* beta   = (const float*)d_in[7];
    const float* mean   = (const float*)d_in[8];
    const float* var    = (const float*)d_in[9];
    float* out = (float*)d_out;

    k_zero     <<<(B_ * N_ + 511) / 512, 512>>>();
    k_transpose<<<dim3(N_ / 32, PC_ / 32, B_), dim3(32, 8)>>>(pf);
    k_ri       <<<dim3(N_ / 128, B_),           256>>>(img, fc2_w, fc2_b);
    k_s        <<<dim3(N_ / 128, N_ / 128, B_), 256>>>();
    k_vp       <<<dim3(N_ / 128, 2, B_),        256>>>(conv_w);
    k_av       <<<dim3(8, N_ / 128, B_),        256>>>();
    k_bn       <<<dim3(N_ / 32, OC_ / 32, B_),  dim3(32, 8)>>>(conv_b, gamma, beta,
                                                               mean, var, out);
}

// round 13
// speedup vs baseline: 3.4704x; 1.0326x over previous
#include <cuda_runtime.h>
#include <cuda_fp16.h>
#include <math.h>

#define B_   2
#define N_   4096
#define IC_  256
#define PC_  128
#define OC_  128
#define SCALE_ 0.08838834764831845f   // 1/sqrt(128)
#define VSCALE 4096.0f                 // vT scaling to stay in fp16 normal range
#define LDK  20                        // tf32 tile pitch (floats) — k_ri only
#define BUFB (128u * LDK * 4u)
#define LDH  40                        // fp16 tile pitch (halves), 80 B/row
#define BUFH (128u * LDH * 2u)         // 10240 B per fp16 plane
#define KSPL (N_ / 4)
#define LDT  136                       // staging tile pitch (halves)
#define TILEB (128u * LDT * 2u)        // 34816 B per staged tile
#define KS_DSMEM (2u * TILEB)          // 69632 B dynamic smem for k_s

// ---------------- scratch (device globals) ----------------------------------
static __device__ __align__(16) __half g_rp16[(size_t)B_ * N_ * PC_];
static __device__ __align__(16) __half g_ri16[(size_t)B_ * N_ * PC_];
static __device__ __align__(16) __half g_S16 [(size_t)B_ * N_ * N_];   // P
static __device__ __align__(16) __half g_ST16[(size_t)B_ * N_ * N_];   // P^T
static __device__ __align__(16) __half g_vT16[2][(size_t)B_ * OC_ * N_]; // v^T * VSCALE
static __device__ __align__(16) float  g_csum[B_ * N_];
static __device__ __align__(16) float  g_rsum[B_ * N_];
static __device__ __align__(16) float  g_d   [8][(size_t)B_ * N_ * OC_]; // fp32 partials

// ---------------- helpers ----------------------------------------------------
__device__ __forceinline__ unsigned tf32_of(float x) {
    unsigned r; asm("cvt.rna.tf32.f32 %0, %1;" : "=r"(r) : "f"(x)); return r;
}
__device__ __forceinline__ uint4 cvt4(float a, float b, float c, float d) {
    return make_uint4(tf32_of(a), tf32_of(b), tf32_of(c), tf32_of(d));
}
__device__ __forceinline__ unsigned h2pack(float a, float b) {
    __half2 h = __floats2half2_rn(a, b);
    return *reinterpret_cast<unsigned*>(&h);
}
__device__ __forceinline__ void mma_tf32(float* c, unsigned a0, unsigned a1,
                                         unsigned a2, unsigned a3,
                                         unsigned b0, unsigned b1) {
    asm volatile(
        "mma.sync.aligned.m16n8k8.row.col.f32.tf32.tf32.f32 "
        "{%0,%1,%2,%3}, {%4,%5,%6,%7}, {%8,%9}, {%0,%1,%2,%3};"
        : "+f"(c[0]), "+f"(c[1]), "+f"(c[2]), "+f"(c[3])
        : "r"(a0), "r"(a1), "r"(a2), "r"(a3), "r"(b0), "r"(b1));
}
__device__ __forceinline__ void mma_f16(float* c, unsigned a0, unsigned a1,
                                        unsigned a2, unsigned a3,
                                        unsigned b0, unsigned b1) {
    asm volatile(
        "mma.sync.aligned.m16n8k16.row.col.f32.f16.f16.f32 "
        "{%0,%1,%2,%3}, {%4,%5,%6,%7}, {%8,%9}, {%0,%1,%2,%3};"
        : "+f"(c[0]), "+f"(c[1]), "+f"(c[2]), "+f"(c[3])
        : "r"(a0), "r"(a1), "r"(a2), "r"(a3), "r"(b0), "r"(b1));
}
__device__ __forceinline__ unsigned smem_u32(const void* p) {
    unsigned a;
    asm("{.reg .u64 t; cvta.to.shared.u64 t, %1; cvt.u32.u64 %0, t;}"
        : "=r"(a) : "l"(p));
    return a;
}
__device__ __forceinline__ void ldsm4(unsigned& r0, unsigned& r1,
                                      unsigned& r2, unsigned& r3, unsigned addr) {
    asm volatile("ldmatrix.sync.aligned.m8n8.x4.shared.b16 {%0,%1,%2,%3}, [%4];"
                 : "=r"(r0), "=r"(r1), "=r"(r2), "=r"(r3) : "r"(addr));
}
#define CPA16(dst, src) asm volatile("cp.async.cg.shared.global [%0], [%1], 16;" \
                                     :: "r"(dst), "l"(src) : "memory")
#define CPA_COMMIT()    asm volatile("cp.async.commit_group;" ::: "memory")
#define CPA_WAIT0()     asm volatile("cp.async.wait_group 0;" ::: "memory")
#define CPA_WAIT1()     asm volatile("cp.async.wait_group 1;" ::: "memory")

#define WARP_COORDS                                                          \
    const int tid  = threadIdx.x;                                            \
    const int lane = tid & 31, wid = tid >> 5;                               \
    const int wm = wid & 1, wn = wid >> 1;                                   \
    const int g = lane >> 2, t = lane & 3;                                   \
    const int jm = lane >> 3;                                                \
    (void)g; (void)t; (void)jm;

#define ZERO_ACC                                                             \
    float acc[4][4][4];                                                      \
    _Pragma("unroll")                                                        \
    for (int mf = 0; mf < 4; mf++)                                           \
        _Pragma("unroll")                                                    \
        for (int nf = 0; nf < 4; nf++)                                       \
            _Pragma("unroll")                                                 \
            for (int q = 0; q < 4; q++) acc[mf][nf][q] = 0.f;

// ----- tf32 path (k_ri only) -----
#define LDSM_BASES(AsT, BsT)                                                 \
    const unsigned baseA = smem_u32(&AsT[0][0][0]) +                         \
        (((wm * 64) + ((jm & 1) * 8) + (lane & 7)) * LDK + ((jm >> 1) * 4)) * 4u; \
    const unsigned baseB = smem_u32(&BsT[0][0][0]) +                         \
        (((wn * 32) + ((jm >> 1) * 8) + (lane & 7)) * LDK + ((jm & 1) * 4)) * 4u;

#define MMA_TILE_BODY(off)                                                   \
    for (int kk = 0; kk < 16; kk += 8) {                                     \
        unsigned a[4][4], bb[4][2];                                          \
        _Pragma("unroll")                                                    \
        for (int mf = 0; mf < 4; mf++)                                       \
            ldsm4(a[mf][0], a[mf][1], a[mf][2], a[mf][3],                    \
                  baseA + (off) + (mf * 16 * LDK + kk) * 4u);                \
        ldsm4(bb[0][0], bb[0][1], bb[1][0], bb[1][1],                        \
              baseB + (off) + kk * 4u);                                      \
        ldsm4(bb[2][0], bb[2][1], bb[3][0], bb[3][1],                        \
              baseB + (off) + (16 * LDK + kk) * 4u);                         \
        _Pragma("unroll")                                                    \
        for (int mf = 0; mf < 4; mf++)                                       \
            _Pragma("unroll")                                                \
            for (int nf = 0; nf < 4; nf++)                                   \
                mma_tf32(acc[mf][nf], a[mf][0], a[mf][1], a[mf][2], a[mf][3],\
                         bb[nf][0], bb[nf][1]);                              \
    }

// ----- fp16 path: BK = 32 halves, bases given as raw smem addresses -----
#define LDSM16_BASES_U(aU, bU)                                               \
    const unsigned baseA = (aU) +                                            \
        ((((wm * 64) + (lane & 15)) * LDH + ((lane >> 4) * 8)) * 2u);        \
    const unsigned baseB = (bU) +                                            \
        ((((wn * 32) + (lane & 7) + ((lane >> 4) * 8)) * LDH +               \
          (((lane >> 3) & 1) * 8)) * 2u);

#define MMA16_TILE_BODY(off)                                                 \
    _Pragma("unroll")                                                        \
    for (int kk = 0; kk < 2; kk++) {                                         \
        unsigned a[4][4], bb[4][2];                                          \
        _Pragma("unroll")                                                    \
        for (int mf = 0; mf < 4; mf++)                                       \
            ldsm4(a[mf][0], a[mf][1], a[mf][2], a[mf][3],                    \
                  baseA + (off) + (mf * 16 * LDH + kk * 16) * 2u);           \
        ldsm4(bb[0][0], bb[0][1], bb[1][0], bb[1][1],                        \
              baseB + (off) + (kk * 16) * 2u);                               \
        ldsm4(bb[2][0], bb[2][1], bb[3][0], bb[3][1],                        \
              baseB + (off) + (16 * LDH + kk * 16) * 2u);                    \
        _Pragma("unroll")                                                    \
        for (int mf = 0; mf < 4; mf++)                                       \
            _Pragma("unroll")                                                \
            for (int nf = 0; nf < 4; nf++)                                   \
                mma_f16(acc[mf][nf], a[mf][0], a[mf][1], a[mf][2], a[mf][3], \
                        bb[nf][0], bb[nf][1]);                               \
    }

// ---------------- kernel 0: zero the sum accumulators ------------------------
__global__ void k_zero() {
    int i = blockIdx.x * blockDim.x + threadIdx.x;
    if (i < B_ * N_) { g_csum[i] = 0.f; g_rsum[i] = 0.f; }
}

// ---------------- kernel 1: transpose pf [B,PC,N] -> rp16 [B,N,PC] -----------
__global__ void k_transpose(const float* __restrict__ pf) {
    __shared__ float tile[32][33];
    const int b  = blockIdx.z;
    const int n0 = blockIdx.x * 32;
    const int d0 = blockIdx.y * 32;
    const float* src = pf + (size_t)b * PC_ * N_;
    __half*      dst = g_rp16 + (size_t)b * N_ * PC_;
    const int tx = threadIdx.x, ty = threadIdx.y;   // (32, 8)
#pragma unroll
    for (int j = 0; j < 32; j += 8)
        tile[ty + j][tx] = src[(size_t)(d0 + ty + j) * N_ + n0 + tx];
    __syncthreads();
#pragma unroll
    for (int j = 0; j < 32; j += 8)
        dst[(size_t)(n0 + ty + j) * PC_ + d0 + tx] = __float2half_rn(tile[tx][ty + j]);
}

// ---------------- kernel 2: ri16 = half(img^T @ fc2_w^T + fc2_b) -------------
__global__ __launch_bounds__(256, 2) void k_ri(const float* __restrict__ img,
                                               const float* __restrict__ w,
                                               const float* __restrict__ bias) {
    const int b  = blockIdx.y;
    const int n0 = blockIdx.x * 128;
    const float* X = img + (size_t)b * IC_ * N_;
    __half*      R = g_ri16 + (size_t)b * N_ * PC_;

    __shared__ __align__(16) unsigned AsT[2][128][LDK];
    __shared__ __align__(16) unsigned BsT[2][128][LDK];

    WARP_COORDS
    LDSM_BASES(AsT, BsT)

    const int rowT = (wid & 3) * 32 + lane;
    const int kcb  = wid >> 2;
    const int fi = tid >> 2, fc = (tid & 3) * 4;

    ZERO_ACC

    float va[2][4]; float4 rb[2];
#pragma unroll
    for (int r = 0; r < 2; r++) {
        int kc = kcb + 2 * r;
#pragma unroll
        for (int j = 0; j < 4; j++)
            va[r][j] = X[(size_t)(kc * 4 + j) * N_ + n0 + rowT];
        rb[r] = *(const float4*)&w[(size_t)(fi + r * 64) * IC_ + fc];
    }

    int p = 0;
    for (int k0 = 0; k0 < IC_; k0 += 16) {
#pragma unroll
        for (int r = 0; r < 2; r++) {
            int kc = kcb + 2 * r;
            *(uint4*)&AsT[p][rowT][kc * 4]    = cvt4(va[r][0], va[r][1], va[r][2], va[r][3]);
            *(uint4*)&BsT[p][fi + r * 64][fc] = cvt4(rb[r].x, rb[r].y, rb[r].z, rb[r].w);
        }
        __syncthreads();
        if (k0 + 16 < IC_) {
            int kn = k0 + 16;
#pragma unroll
            for (int r = 0; r < 2; r++) {
                int kc = kcb + 2 * r;
#pragma unroll
                for (int j = 0; j < 4; j++)
                    va[r][j] = X[(size_t)(kn + kc * 4 + j) * N_ + n0 + rowT];
                rb[r] = *(const float4*)&w[(size_t)(fi + r * 64) * IC_ + kn + fc];
            }
        }
        const unsigned off = p * BUFB;
        MMA_TILE_BODY(off)
        __syncthreads();
        p ^= 1;
    }
#pragma unroll
    for (int mf = 0; mf < 4; mf++) {
        int row = n0 + wm * 64 + mf * 16 + g;
#pragma unroll
        for (int nf = 0; nf < 4; nf++) {
            int col = wn * 32 + nf * 8 + 2 * t;
            float b0 = bias[col], b1 = bias[col + 1];
            *(unsigned*)&R[(size_t)row * PC_ + col] =
                h2pack(acc[mf][nf][0] + b0, acc[mf][nf][1] + b1);
            *(unsigned*)&R[(size_t)(row + 8) * PC_ + col] =
                h2pack(acc[mf][nf][2] + b0, acc[mf][nf][3] + b1);
        }
    }
}

// ---------------- kernel 3: P = exp(scale * rp @ ri^T); staged P + P^T, sums -
__global__ __launch_bounds__(256, 2) void k_s() {
    extern __shared__ __align__(16) char dyn[];   // KS_DSMEM bytes
    const int b  = blockIdx.z;
    const int i0 = blockIdx.y * 128;
    const int j0 = blockIdx.x * 128;
    const __half* A16 = g_rp16 + (size_t)b * N_ * PC_ + (size_t)i0 * PC_;
    const __half* B16 = g_ri16 + (size_t)b * N_ * PC_ + (size_t)j0 * PC_;
    __half*       Pp  = g_S16  + (size_t)b * N_ * N_;
    __half*       Pt  = g_ST16 + (size_t)b * N_ * N_;

    __shared__ float shr[128], shc[128];

    WARP_COORDS

    const unsigned sAu = smem_u32(dyn);
    const unsigned sBu = sAu + 2 * BUFH;
    LDSM16_BASES_U(sAu, sBu)

    const int frow = tid >> 1, fg0 = (tid & 1) * 2;

#define FILL_S16(pp, kk0)                                                    \
    _Pragma("unroll")                                                        \
    for (int r = 0; r < 2; r++) {                                            \
        int gq = fg0 + r;                                                    \
        unsigned o = (pp) * BUFH + ((unsigned)frow * LDH + gq * 8) * 2u;     \
        CPA16(sAu + o, A16 + (size_t)frow * PC_ + (kk0) + gq * 8);           \
        CPA16(sBu + o, B16 + (size_t)frow * PC_ + (kk0) + gq * 8);           \
    }                                                                        \
    CPA_COMMIT();

    ZERO_ACC

    FILL_S16(0, 0)
    int p = 0;
    for (int ch = 0; ch < 4; ch++) {             // PC_/32 chunks
        if (ch + 1 < 4) { FILL_S16(p ^ 1, (ch + 1) * 32) CPA_WAIT1(); }
        else            { CPA_WAIT0(); }
        __syncthreads();
        const unsigned off = p * BUFH;
        MMA16_TILE_BODY(off)
        __syncthreads();
        p ^= 1;
    }
#undef FILL_S16

    // epilogue: operand planes are dead; stage BOTH P and P^T tiles.
    __half* Psm = (__half*)dyn;
    __half* Tsm = (__half*)(dyn + TILEB);
    if (tid < 128) { shr[tid] = 0.f; shc[tid] = 0.f; }
    __syncthreads();

    float rs[4][2] = {{0.f,0.f},{0.f,0.f},{0.f,0.f},{0.f,0.f}};
    float cs[4][2] = {{0.f,0.f},{0.f,0.f},{0.f,0.f},{0.f,0.f}};
#pragma unroll
    for (int mf = 0; mf < 4; mf++) {
        int rl = wm * 64 + mf * 16 + g;          // local row
#pragma unroll
        for (int nf = 0; nf < 4; nf++) {
            int cl = wn * 32 + nf * 8 + 2 * t;   // local col
            float p0 = __expf(acc[mf][nf][0] * SCALE_);
            float p1 = __expf(acc[mf][nf][1] * SCALE_);
            float p2 = __expf(acc[mf][nf][2] * SCALE_);
            float p3 = __expf(acc[mf][nf][3] * SCALE_);
            *(unsigned*)&Psm[rl * LDT + cl]       = h2pack(p0, p1);
            *(unsigned*)&Psm[(rl + 8) * LDT + cl] = h2pack(p2, p3);
            Tsm[cl * LDT + rl]           = __float2half_rn(p0);
            Tsm[(cl + 1) * LDT + rl]     = __float2half_rn(p1);
            Tsm[cl * LDT + rl + 8]       = __float2half_rn(p2);
            Tsm[(cl + 1) * LDT + rl + 8] = __float2half_rn(p3);
            rs[mf][0] += p0 + p1; rs[mf][1] += p2 + p3;
            cs[nf][0] += p0 + p2; cs[nf][1] += p1 + p3;
        }
    }
#pragma unroll
    for (int mf = 0; mf < 4; mf++)
#pragma unroll
        for (int h = 0; h < 2; h++) {
            float v = rs[mf][h];
            v += __shfl_xor_sync(0xffffffffu, v, 1);
            v += __shfl_xor_sync(0xffffffffu, v, 2);
            if (t == 0) atomicAdd(&shr[wm * 64 + mf * 16 + h * 8 + g], v);
        }
#pragma unroll
    for (int nf = 0; nf < 4; nf++)
#pragma unroll
        for (int q = 0; q < 2; q++) {
            float v = cs[nf][q];
            v += __shfl_xor_sync(0xffffffffu, v, 4);
            v += __shfl_xor_sync(0xffffffffu, v, 8);
            v += __shfl_xor_sync(0xffffffffu, v, 16);
            if (g == 0) atomicAdd(&shc[wn * 32 + nf * 8 + 2 * t + q], v);
        }
    __syncthreads();

    // coalesced writes: P rows and P^T rows, uint4 chunks
#pragma unroll
    for (int i = tid; i < 128 * 16; i += 256) {
        int r = i >> 4, chk = i & 15;
        uint4 v = *(uint4*)&Psm[r * LDT + chk * 8];
        *(uint4*)&Pp[(size_t)(i0 + r) * N_ + j0 + chk * 8] = v;
        uint4 u = *(uint4*)&Tsm[r * LDT + chk * 8];
        *(uint4*)&Pt[(size_t)(j0 + r) * N_ + i0 + chk * 8] = u;
    }
    if (tid < 128) {
        atomicAdd(&g_rsum[b * N_ + i0 + tid], shr[tid]);
        atomicAdd(&g_csum[b * N_ + j0 + tid], shc[tid]);
    }
}

// ---------------- kernel 4: vT16 = half(VSCALE*((Src@W^T)/sum))^T, staged ----
__global__ __launch_bounds__(256, 2) void k_vp(const float* __restrict__ w) {
    const int which = blockIdx.y;
    const int b  = blockIdx.z;
    const int j0 = blockIdx.x * 128;
    const __half* Src = (which ? g_ri16 : g_rp16) + (size_t)b * N_ * PC_ + (size_t)j0 * PC_;
    const float*  sum = (which ? g_rsum : g_csum) + b * N_;
    __half*       Dst = g_vT16[which] + (size_t)b * OC_ * N_;

    __shared__ __align__(16) char blob[4 * BUFH];   // operand planes / staging tile

    WARP_COORDS

    const unsigned sAu = smem_u32(blob);
    const unsigned sBu = sAu + 2 * BUFH;
    LDSM16_BASES_U(sAu, sBu)

    const int frow = tid >> 1, fg0 = (tid & 1) * 2;

    ZERO_ACC

#define FILL_VP(pp, kk0)                                                     \
    _Pragma("unroll")                                                        \
    for (int r = 0; r < 2; r++) {                                            \
        int gq = fg0 + r;                                                    \
        unsigned o = (pp) * BUFH + ((unsigned)frow * LDH + gq * 8) * 2u;     \
        CPA16(sAu + o, Src + (size_t)frow * PC_ + (kk0) + gq * 8);           \
        const float* ws = &w[(size_t)frow * (2 * PC_) + which * PC_ + (kk0) + gq * 8]; \
        float4 v0 = *(const float4*)ws, v1 = *(const float4*)(ws + 4);       \
        *(uint4*)(blob + 2 * BUFH + (pp) * BUFH + frow * (LDH * 2) + gq * 16) = \
            make_uint4(h2pack(v0.x, v0.y), h2pack(v0.z, v0.w),               \
                       h2pack(v1.x, v1.y), h2pack(v1.z, v1.w));              \
    }                                                                        \
    CPA_COMMIT();

    FILL_VP(0, 0)
    int p = 0;
    for (int ch = 0; ch < 4; ch++) {
        if (ch + 1 < 4) { FILL_VP(p ^ 1, (ch + 1) * 32) CPA_WAIT1(); }
        else            { CPA_WAIT0(); }
        __syncthreads();
        const unsigned off = p * BUFH;
        MMA16_TILE_BODY(off)
        __syncthreads();
        p ^= 1;
    }
#undef FILL_VP

    // stage transposed result tile, then coalesced write
    __half* Vsm = (__half*)blob;
#pragma unroll
    for (int mf = 0; mf < 4; mf++) {
        int rl = wm * 64 + mf * 16 + g;
        float inv0 = __fdividef(VSCALE, sum[j0 + rl]);
        float inv8 = __fdividef(VSCALE, sum[j0 + rl + 8]);
#pragma unroll
        for (int nf = 0; nf < 4; nf++) {
            int cl = wn * 32 + nf * 8 + 2 * t;
            Vsm[cl * LDT + rl]           = __float2half_rn(acc[mf][nf][0] * inv0);
            Vsm[(cl + 1) * LDT + rl]     = __float2half_rn(acc[mf][nf][1] * inv0);
            Vsm[cl * LDT + rl + 8]       = __float2half_rn(acc[mf][nf][2] * inv8);
            Vsm[(cl + 1) * LDT + rl + 8] = __float2half_rn(acc[mf][nf][3] * inv8);
        }
    }
    __syncthreads();
#pragma unroll
    for (int i = tid; i < 128 * 16; i += 256) {
        int c = i >> 4, chk = i & 15;
        uint4 v = *(uint4*)&Vsm[c * LDT + chk * 8];
        *(uint4*)&Dst[(size_t)c * N_ + j0 + chk * 8] = v;
    }
}

// ---------------- kernel 5: AV partial GEMMs (fp16, cp.async, 4-way ksplit) --
__global__ __launch_bounds__(256, 2) void k_av() {
    const int mode = blockIdx.x & 1;
    const int ks   = blockIdx.x >> 1;
    const int b    = blockIdx.z;
    const int i0   = blockIdx.y * 128;
    const int kb   = ks * KSPL;
    const __half* M  = (mode == 0 ? g_S16 : g_ST16) + (size_t)b * N_ * N_ + (size_t)i0 * N_;
    const __half* Vt = g_vT16[mode] + (size_t)b * OC_ * N_;
    float*        D  = g_d[(mode << 2) | ks] + (size_t)b * N_ * OC_;

    __shared__ __align__(16) __half AsT[2][128][LDH];
    __shared__ __align__(16) __half BsT[2][128][LDH];

    WARP_COORDS
    LDSM16_BASES_U(smem_u32(AsT), smem_u32(BsT))

    const unsigned sAu = smem_u32(AsT);
    const unsigned sBu = smem_u32(BsT);
    const int frow = tid >> 1, fg0 = (tid & 1) * 2;

#define FILL_AV16(pp, kk0)                                                   \
    _Pragma("unroll")                                                        \
    for (int r = 0; r < 2; r++) {                                            \
        int gq = fg0 + r;                                                    \
        unsigned o = (pp) * BUFH + ((unsigned)frow * LDH + gq * 8) * 2u;     \
        CPA16(sAu + o, M  + (size_t)frow * N_ + (kk0) + gq * 8);             \
        CPA16(sBu + o, Vt + (size_t)frow * N_ + (kk0) + gq * 8);             \
    }                                                                        \
    CPA_COMMIT();

    ZERO_ACC

    FILL_AV16(0, kb)
    int p = 0;
    const int NCH = KSPL / 32;
    for (int ch = 0; ch < NCH; ch++) {
        if (ch + 1 < NCH) { FILL_AV16(p ^ 1, kb + (ch + 1) * 32) CPA_WAIT1(); }
        else              { CPA_WAIT0(); }
        __syncthreads();
        const unsigned off = p * BUFH;
        MMA16_TILE_BODY(off)
        __syncthreads();
        p ^= 1;
    }
#undef FILL_AV16

#pragma unroll
    for (int mf = 0; mf < 4; mf++) {
        int row = i0 + wm * 64 + mf * 16 + g;
#pragma unroll
        for (int nf = 0; nf < 4; nf++) {
            int col = wn * 32 + nf * 8 + 2 * t;
            *(float2*)&D[(size_t)row * OC_ + col]       = make_float2(acc[mf][nf][0], acc[mf][nf][1]);
            *(float2*)&D[(size_t)(row + 8) * OC_ + col] = make_float2(acc[mf][nf][2], acc[mf][nf][3]);
        }
    }
}

// ---------------- kernel 6: sum partials/VSCALE + BN + ReLU + transpose ------
__global__ void k_bn(const float* __restrict__ cb,    const float* __restrict__ gamma,
                     const float* __restrict__ beta,  const float* __restrict__ mean,
                     const float* __restrict__ var,   float* __restrict__ out) {
    __shared__ float tile[32][33];
    const int b  = blockIdx.z;
    const int n0 = blockIdx.x * 32;
    const int o0 = blockIdx.y * 32;
    const int tx = threadIdx.x, ty = threadIdx.y;   // (32, 8)
#pragma unroll
    for (int j = 0; j < 32; j += 8) {
        size_t idx = (size_t)b * N_ * OC_ + (size_t)(n0 + ty + j) * OC_ + o0 + tx;
        float s = 0.f;
#pragma unroll
        for (int m = 0; m < 8; m++) s += g_d[m][idx];
        tile[ty + j][tx] = s * (1.0f / VSCALE);
    }
    __syncthreads();
#pragma unroll
    for (int j = 0; j < 32; j += 8) {
        int o = o0 + ty + j;
        float gm   = gamma[o] * rsqrtf(var[o] + 1e-5f);
        float base = gm * (cb[o] - mean[o]) + beta[o];
        out[(size_t)b * OC_ * N_ + (size_t)o * N_ + n0 + tx] =
            fmaxf(gm * tile[tx][ty + j] + base, 0.f);
    }
}

// ---------------- launch -----------------------------------------------------
extern "C" void kernel_launch(void* const* d_in, const int* in_sizes, int n_in,
                              void* d_out, int out_size) {
    const float* pf     = (const float*)d_in[0];
    const float* img    = (const float*)d_in[1];
    const float* fc2_w  = (const float*)d_in[2];
    const float* fc2_b  = (const float*)d_in[3];
    const float* conv_w = (const float*)d_in[4];
    const float* conv_b = (const float*)d_in[5];
    const float* gamma  = (const float*)d_in[6];
    const float* beta   = (const float*)d_in[7];
    const float* mean   = (const float*)d_in[8];
    const float* var    = (const float*)d_in[9];
    float* out = (float*)d_out;

    cudaFuncSetAttribute(k_s, cudaFuncAttributeMaxDynamicSharedMemorySize, KS_DSMEM);

    k_zero     <<<(B_ * N_ + 511) / 512, 512>>>();
    k_transpose<<<dim3(N_ / 32, PC_ / 32, B_), dim3(32, 8)>>>(pf);
    k_ri       <<<dim3(N_ / 128, B_),           256>>>(img, fc2_w, fc2_b);
    k_s        <<<dim3(N_ / 128, N_ / 128, B_), 256, KS_DSMEM>>>();
    k_vp       <<<dim3(N_ / 128, 2, B_),        256>>>(conv_w);
    k_av       <<<dim3(8, N_ / 128, B_),        256>>>();
    k_bn       <<<dim3(N_ / 32, OC_ / 32, B_),  dim3(32, 8)>>>(conv_b, gamma, beta,
                                                               mean, var, out);
}

// round 15
// speedup vs baseline: 3.8473x; 1.1086x over previous
#include <cuda_runtime.h>
#include <cuda_fp16.h>
#include <math.h>

#define B_   2
#define N_   4096
#define IC_  256
#define PC_  128
#define OC_  128
#define SCALE_ 0.08838834764831845f   // 1/sqrt(128)
#define VSCALE 4096.0f                 // vT scaling to stay in fp16 normal range
#define LDK  20                        // tf32 tile pitch (floats) — k_ri only
#define BUFB (128u * LDK * 4u)
#define LDH  40                        // fp16 tile pitch (halves), 80 B/row
#define BUFH (128u * LDH * 2u)         // 10240 B per fp16 plane
#define KSPL (N_ / 4)
#define LDT  136                       // staging / K-major tile pitch (halves)
#define TKB  (32u * LDT * 2u)          // 8704 B per K-major A plane (32 k-rows)

// ---------------- scratch (device globals) ----------------------------------
static __device__ __align__(16) __half g_rp16[(size_t)B_ * N_ * PC_];
static __device__ __align__(16) __half g_ri16[(size_t)B_ * N_ * PC_];
static __device__ __align__(16) __half g_S16 [(size_t)B_ * N_ * N_];   // P
static __device__ __align__(16) __half g_vT16[2][(size_t)B_ * OC_ * N_]; // v^T * VSCALE
static __device__ __align__(16) float  g_csum[B_ * N_];
static __device__ __align__(16) float  g_rsum[B_ * N_];
static __device__ __align__(16) float  g_d   [8][(size_t)B_ * N_ * OC_]; // fp32 partials

// ---------------- helpers ----------------------------------------------------
__device__ __forceinline__ unsigned tf32_of(float x) {
    unsigned r; asm("cvt.rna.tf32.f32 %0, %1;" : "=r"(r) : "f"(x)); return r;
}
__device__ __forceinline__ uint4 cvt4(float a, float b, float c, float d) {
    return make_uint4(tf32_of(a), tf32_of(b), tf32_of(c), tf32_of(d));
}
__device__ __forceinline__ unsigned h2pack(float a, float b) {
    __half2 h = __floats2half2_rn(a, b);
    return *reinterpret_cast<unsigned*>(&h);
}
__device__ __forceinline__ void mma_tf32(float* c, unsigned a0, unsigned a1,
                                         unsigned a2, unsigned a3,
                                         unsigned b0, unsigned b1) {
    asm volatile(
        "mma.sync.aligned.m16n8k8.row.col.f32.tf32.tf32.f32 "
        "{%0,%1,%2,%3}, {%4,%5,%6,%7}, {%8,%9}, {%0,%1,%2,%3};"
        : "+f"(c[0]), "+f"(c[1]), "+f"(c[2]), "+f"(c[3])
        : "r"(a0), "r"(a1), "r"(a2), "r"(a3), "r"(b0), "r"(b1));
}
__device__ __forceinline__ void mma_f16(float* c, unsigned a0, unsigned a1,
                                        unsigned a2, unsigned a3,
                                        unsigned b0, unsigned b1) {
    asm volatile(
        "mma.sync.aligned.m16n8k16.row.col.f32.f16.f16.f32 "
        "{%0,%1,%2,%3}, {%4,%5,%6,%7}, {%8,%9}, {%0,%1,%2,%3};"
        : "+f"(c[0]), "+f"(c[1]), "+f"(c[2]), "+f"(c[3])
        : "r"(a0), "r"(a1), "r"(a2), "r"(a3), "r"(b0), "r"(b1));
}
__device__ __forceinline__ unsigned smem_u32(const void* p) {
    unsigned a;
    asm("{.reg .u64 t; cvta.to.shared.u64 t, %1; cvt.u32.u64 %0, t;}"
        : "=r"(a) : "l"(p));
    return a;
}
__device__ __forceinline__ void ldsm4(unsigned& r0, unsigned& r1,
                                      unsigned& r2, unsigned& r3, unsigned addr) {
    asm volatile("ldmatrix.sync.aligned.m8n8.x4.shared.b16 {%0,%1,%2,%3}, [%4];"
                 : "=r"(r0), "=r"(r1), "=r"(r2), "=r"(r3) : "r"(addr));
}
__device__ __forceinline__ void ldsm4t(unsigned& r0, unsigned& r1,
                                       unsigned& r2, unsigned& r3, unsigned addr) {
    asm volatile("ldmatrix.sync.aligned.m8n8.x4.trans.shared.b16 {%0,%1,%2,%3}, [%4];"
                 : "=r"(r0), "=r"(r1), "=r"(r2), "=r"(r3) : "r"(addr));
}
#define CPA16(dst, src) asm volatile("cp.async.cg.shared.global [%0], [%1], 16;" \
                                     :: "r"(dst), "l"(src) : "memory")
#define CPA_COMMIT()    asm volatile("cp.async.commit_group;" ::: "memory")
#define CPA_WAIT0()     asm volatile("cp.async.wait_group 0;" ::: "memory")
#define CPA_WAIT1()     asm volatile("cp.async.wait_group 1;" ::: "memory")

#define WARP_COORDS                                                          \
    const int tid  = threadIdx.x;                                            \
    const int lane = tid & 31, wid = tid >> 5;                               \
    const int wm = wid & 1, wn = wid >> 1;                                   \
    const int g = lane >> 2, t = lane & 3;                                   \
    const int jm = lane >> 3;                                                \
    (void)g; (void)t; (void)jm;

#define ZERO_ACC                                                             \
    float acc[4][4][4];                                                      \
    _Pragma("unroll")                                                        \
    for (int mf = 0; mf < 4; mf++)                                           \
        _Pragma("unroll")                                                    \
        for (int nf = 0; nf < 4; nf++)                                       \
            _Pragma("unroll")                                                 \
            for (int q = 0; q < 4; q++) acc[mf][nf][q] = 0.f;

// ----- tf32 path (k_ri only) -----
#define LDSM_BASES(AsT, BsT)                                                 \
    const unsigned baseA = smem_u32(&AsT[0][0][0]) +                         \
        (((wm * 64) + ((jm & 1) * 8) + (lane & 7)) * LDK + ((jm >> 1) * 4)) * 4u; \
    const unsigned baseB = smem_u32(&BsT[0][0][0]) +                         \
        (((wn * 32) + ((jm >> 1) * 8) + (lane & 7)) * LDK + ((jm & 1) * 4)) * 4u;

#define MMA_TILE_BODY(off)                                                   \
    for (int kk = 0; kk < 16; kk += 8) {                                     \
        unsigned a[4][4], bb[4][2];                                          \
        _Pragma("unroll")                                                    \
        for (int mf = 0; mf < 4; mf++)                                       \
            ldsm4(a[mf][0], a[mf][1], a[mf][2], a[mf][3],                    \
                  baseA + (off) + (mf * 16 * LDK + kk) * 4u);                \
        ldsm4(bb[0][0], bb[0][1], bb[1][0], bb[1][1],                        \
              baseB + (off) + kk * 4u);                                      \
        ldsm4(bb[2][0], bb[2][1], bb[3][0], bb[3][1],                        \
              baseB + (off) + (16 * LDK + kk) * 4u);                         \
        _Pragma("unroll")                                                    \
        for (int mf = 0; mf < 4; mf++)                                       \
            _Pragma("unroll")                                                \
            for (int nf = 0; nf < 4; nf++)                                   \
                mma_tf32(acc[mf][nf], a[mf][0], a[mf][1], a[mf][2], a[mf][3],\
                         bb[nf][0], bb[nf][1]);                              \
    }

// ----- fp16 path: BK = 32 halves -----
#define LDSM16_BASES_U(aU, bU)                                               \
    const unsigned baseA = (aU) +                                            \
        ((((wm * 64) + (lane & 15)) * LDH + ((lane >> 4) * 8)) * 2u);        \
    const unsigned baseB = (bU) +                                            \
        ((((wn * 32) + (lane & 7) + ((lane >> 4) * 8)) * LDH +               \
          (((lane >> 3) & 1) * 8)) * 2u);

#define MMA16_TILE_BODY(off)                                                 \
    _Pragma("unroll")                                                        \
    for (int kk = 0; kk < 2; kk++) {                                         \
        unsigned a[4][4], bb[4][2];                                          \
        _Pragma("unroll")                                                    \
        for (int mf = 0; mf < 4; mf++)                                       \
            ldsm4(a[mf][0], a[mf][1], a[mf][2], a[mf][3],                    \
                  baseA + (off) + (mf * 16 * LDH + kk * 16) * 2u);           \
        ldsm4(bb[0][0], bb[0][1], bb[1][0], bb[1][1],                        \
              baseB + (off) + (kk * 16) * 2u);                               \
        ldsm4(bb[2][0], bb[2][1], bb[3][0], bb[3][1],                        \
              baseB + (off) + (16 * LDH + kk * 16) * 2u);                    \
        _Pragma("unroll")                                                    \
        for (int mf = 0; mf < 4; mf++)                                       \
            _Pragma("unroll")                                                \
            for (int nf = 0; nf < 4; nf++)                                   \
                mma_f16(acc[mf][nf], a[mf][0], a[mf][1], a[mf][2], a[mf][3], \
                        bb[nf][0], bb[nf][1]);                               \
    }

// transposed-A variant: A tile is K-major [32 k-rows][128 m-cols], pitch LDT.
#define MMA16_TILE_BODY_T(offA, offB)                                        \
    _Pragma("unroll")                                                        \
    for (int kk = 0; kk < 2; kk++) {                                         \
        unsigned a[4][4], bb[4][2];                                          \
        _Pragma("unroll")                                                    \
        for (int mf = 0; mf < 4; mf++)                                       \
            ldsm4t(a[mf][0], a[mf][1], a[mf][2], a[mf][3],                   \
                   baseAT + (offA) + (kk * 16 * LDT + mf * 16) * 2u);        \
        ldsm4(bb[0][0], bb[0][1], bb[1][0], bb[1][1],                        \
              baseB + (offB) + (kk * 16) * 2u);                              \
        ldsm4(bb[2][0], bb[2][1], bb[3][0], bb[3][1],                        \
              baseB + (offB) + (16 * LDH + kk * 16) * 2u);                   \
        _Pragma("unroll")                                                    \
        for (int mf = 0; mf < 4; mf++)                                       \
            _Pragma("unroll")                                                \
            for (int nf = 0; nf < 4; nf++)                                   \
                mma_f16(acc[mf][nf], a[mf][0], a[mf][1], a[mf][2], a[mf][3], \
                        bb[nf][0], bb[nf][1]);                               \
    }

// ---------------- kernel 0: zero the sum accumulators ------------------------
__global__ void k_zero() {
    int i = blockIdx.x * blockDim.x + threadIdx.x;
    if (i < B_ * N_) { g_csum[i] = 0.f; g_rsum[i] = 0.f; }
}

// ---------------- kernel 1: transpose pf [B,PC,N] -> rp16 [B,N,PC] -----------
__global__ void k_transpose(const float* __restrict__ pf) {
    __shared__ float tile[32][33];
    const int b  = blockIdx.z;
    const int n0 = blockIdx.x * 32;
    const int d0 = blockIdx.y * 32;
    const float* src = pf + (size_t)b * PC_ * N_;
    __half*      dst = g_rp16 + (size_t)b * N_ * PC_;
    const int tx = threadIdx.x, ty = threadIdx.y;   // (32, 8)
#pragma unroll
    for (int j = 0; j < 32; j += 8)
        tile[ty + j][tx] = src[(size_t)(d0 + ty + j) * N_ + n0 + tx];
    __syncthreads();
#pragma unroll
    for (int j = 0; j < 32; j += 8)
        dst[(size_t)(n0 + ty + j) * PC_ + d0 + tx] = __float2half_rn(tile[tx][ty + j]);
}

// ---------------- kernel 2: ri16 = half(img^T @ fc2_w^T + fc2_b) -------------
__global__ __launch_bounds__(256, 2) void k_ri(const float* __restrict__ img,
                                               const float* __restrict__ w,
                                               const float* __restrict__ bias) {
    const int b  = blockIdx.y;
    const int n0 = blockIdx.x * 128;
    const float* X = img + (size_t)b * IC_ * N_;
    __half*      R = g_ri16 + (size_t)b * N_ * PC_;

    __shared__ __align__(16) unsigned AsT[2][128][LDK];
    __shared__ __align__(16) unsigned BsT[2][128][LDK];

    WARP_COORDS
    LDSM_BASES(AsT, BsT)

    const int rowT = (wid & 3) * 32 + lane;
    const int kcb  = wid >> 2;
    const int fi = tid >> 2, fc = (tid & 3) * 4;

    ZERO_ACC

    float va[2][4]; float4 rb[2];
#pragma unroll
    for (int r = 0; r < 2; r++) {
        int kc = kcb + 2 * r;
#pragma unroll
        for (int j = 0; j < 4; j++)
            va[r][j] = X[(size_t)(kc * 4 + j) * N_ + n0 + rowT];
        rb[r] = *(const float4*)&w[(size_t)(fi + r * 64) * IC_ + fc];
    }

    int p = 0;
    for (int k0 = 0; k0 < IC_; k0 += 16) {
#pragma unroll
        for (int r = 0; r < 2; r++) {
            int kc = kcb + 2 * r;
            *(uint4*)&AsT[p][rowT][kc * 4]    = cvt4(va[r][0], va[r][1], va[r][2], va[r][3]);
            *(uint4*)&BsT[p][fi + r * 64][fc] = cvt4(rb[r].x, rb[r].y, rb[r].z, rb[r].w);
        }
        __syncthreads();
        if (k0 + 16 < IC_) {
            int kn = k0 + 16;
#pragma unroll
            for (int r = 0; r < 2; r++) {
                int kc = kcb + 2 * r;
#pragma unroll
                for (int j = 0; j < 4; j++)
                    va[r][j] = X[(size_t)(kn + kc * 4 + j) * N_ + n0 + rowT];
                rb[r] = *(const float4*)&w[(size_t)(fi + r * 64) * IC_ + kn + fc];
            }
        }
        const unsigned off = p * BUFB;
        MMA_TILE_BODY(off)
        __syncthreads();
        p ^= 1;
    }
#pragma unroll
    for (int mf = 0; mf < 4; mf++) {
        int row = n0 + wm * 64 + mf * 16 + g;
#pragma unroll
        for (int nf = 0; nf < 4; nf++) {
            int col = wn * 32 + nf * 8 + 2 * t;
            float b0 = bias[col], b1 = bias[col + 1];
            *(unsigned*)&R[(size_t)row * PC_ + col] =
                h2pack(acc[mf][nf][0] + b0, acc[mf][nf][1] + b1);
            *(unsigned*)&R[(size_t)(row + 8) * PC_ + col] =
                h2pack(acc[mf][nf][2] + b0, acc[mf][nf][3] + b1);
        }
    }
}

// ---------------- kernel 3: P = exp(scale * rp @ ri^T); staged P, sums -------
__global__ __launch_bounds__(256, 2) void k_s() {
    const int b  = blockIdx.z;
    const int i0 = blockIdx.y * 128;
    const int j0 = blockIdx.x * 128;
    const __half* A16 = g_rp16 + (size_t)b * N_ * PC_ + (size_t)i0 * PC_;
    const __half* B16 = g_ri16 + (size_t)b * N_ * PC_ + (size_t)j0 * PC_;
    __half*       Pp  = g_S16  + (size_t)b * N_ * N_;

    __shared__ __align__(16) char blob[4 * BUFH];   // operands, then P staging tile
    __shared__ float shr[128], shc[128];

    WARP_COORDS

    const unsigned sAu = smem_u32(blob);
    const unsigned sBu = sAu + 2 * BUFH;
    LDSM16_BASES_U(sAu, sBu)

    const int frow = tid >> 1, fg0 = (tid & 1) * 2;

#define FILL_S16(pp, kk0)                                                    \
    _Pragma("unroll")                                                        \
    for (int r = 0; r < 2; r++) {                                            \
        int gq = fg0 + r;                                                    \
        unsigned o = (pp) * BUFH + ((unsigned)frow * LDH + gq * 8) * 2u;     \
        CPA16(sAu + o, A16 + (size_t)frow * PC_ + (kk0) + gq * 8);           \
        CPA16(sBu + o, B16 + (size_t)frow * PC_ + (kk0) + gq * 8);           \
    }                                                                        \
    CPA_COMMIT();

    ZERO_ACC

    FILL_S16(0, 0)
    int p = 0;
    for (int ch = 0; ch < 4; ch++) {             // PC_/32 chunks
        if (ch + 1 < 4) { FILL_S16(p ^ 1, (ch + 1) * 32) CPA_WAIT1(); }
        else            { CPA_WAIT0(); }
        __syncthreads();
        const unsigned off = p * BUFH;
        MMA16_TILE_BODY(off)
        __syncthreads();
        p ^= 1;
    }
#undef FILL_S16

    // epilogue: operand planes dead; stage P tile, reduce sums, coalesced write.
    __half* Psm = (__half*)blob;
    if (tid < 128) { shr[tid] = 0.f; shc[tid] = 0.f; }
    __syncthreads();

    float rs[4][2] = {{0.f,0.f},{0.f,0.f},{0.f,0.f},{0.f,0.f}};
    float cs[4][2] = {{0.f,0.f},{0.f,0.f},{0.f,0.f},{0.f,0.f}};
#pragma unroll
    for (int mf = 0; mf < 4; mf++) {
        int rl = wm * 64 + mf * 16 + g;
#pragma unroll
        for (int nf = 0; nf < 4; nf++) {
            int cl = wn * 32 + nf * 8 + 2 * t;
            float p0 = __expf(acc[mf][nf][0] * SCALE_);
            float p1 = __expf(acc[mf][nf][1] * SCALE_);
            float p2 = __expf(acc[mf][nf][2] * SCALE_);
            float p3 = __expf(acc[mf][nf][3] * SCALE_);
            *(unsigned*)&Psm[rl * LDT + cl]       = h2pack(p0, p1);
            *(unsigned*)&Psm[(rl + 8) * LDT + cl] = h2pack(p2, p3);
            rs[mf][0] += p0 + p1; rs[mf][1] += p2 + p3;
            cs[nf][0] += p0 + p2; cs[nf][1] += p1 + p3;
        }
    }
#pragma unroll
    for (int mf = 0; mf < 4; mf++)
#pragma unroll
        for (int h = 0; h < 2; h++) {
            float v = rs[mf][h];
            v += __shfl_xor_sync(0xffffffffu, v, 1);
            v += __shfl_xor_sync(0xffffffffu, v, 2);
            if (t == 0) atomicAdd(&shr[wm * 64 + mf * 16 + h * 8 + g], v);
        }
#pragma unroll
    for (int nf = 0; nf < 4; nf++)
#pragma unroll
        for (int q = 0; q < 2; q++) {
            float v = cs[nf][q];
            v += __shfl_xor_sync(0xffffffffu, v, 4);
            v += __shfl_xor_sync(0xffffffffu, v, 8);
            v += __shfl_xor_sync(0xffffffffu, v, 16);
            if (g == 0) atomicAdd(&shc[wn * 32 + nf * 8 + 2 * t + q], v);
        }
    __syncthreads();

#pragma unroll
    for (int i = tid; i < 128 * 16; i += 256) {
        int r = i >> 4, chk = i & 15;
        uint4 v = *(uint4*)&Psm[r * LDT + chk * 8];
        *(uint4*)&Pp[(size_t)(i0 + r) * N_ + j0 + chk * 8] = v;
    }
    if (tid < 128) {
        atomicAdd(&g_rsum[b * N_ + i0 + tid], shr[tid]);
        atomicAdd(&g_csum[b * N_ + j0 + tid], shc[tid]);
    }
}

// ---------------- kernel 4: vT16 = half(VSCALE*((Src@W^T)/sum))^T, staged ----
__global__ __launch_bounds__(256, 2) void k_vp(const float* __restrict__ w) {
    const int which = blockIdx.y;
    const int b  = blockIdx.z;
    const int j0 = blockIdx.x * 128;
    const __half* Src = (which ? g_ri16 : g_rp16) + (size_t)b * N_ * PC_ + (size_t)j0 * PC_;
    const float*  sum = (which ? g_rsum : g_csum) + b * N_;
    __half*       Dst = g_vT16[which] + (size_t)b * OC_ * N_;

    __shared__ __align__(16) char blob[4 * BUFH];

    WARP_COORDS

    const unsigned sAu = smem_u32(blob);
    const unsigned sBu = sAu + 2 * BUFH;
    LDSM16_BASES_U(sAu, sBu)

    const int frow = tid >> 1, fg0 = (tid & 1) * 2;

    ZERO_ACC

#define FILL_VP(pp, kk0)                                                     \
    _Pragma("unroll")                                                        \
    for (int r = 0; r < 2; r++) {                                            \
        int gq = fg0 + r;                                                    \
        unsigned o = (pp) * BUFH + ((unsigned)frow * LDH + gq * 8) * 2u;     \
        CPA16(sAu + o, Src + (size_t)frow * PC_ + (kk0) + gq * 8);           \
        const float* ws = &w[(size_t)frow * (2 * PC_) + which * PC_ + (kk0) + gq * 8]; \
        float4 v0 = *(const float4*)ws, v1 = *(const float4*)(ws + 4);       \
        *(uint4*)(blob + 2 * BUFH + (pp) * BUFH + frow * (LDH * 2) + gq * 16) = \
            make_uint4(h2pack(v0.x, v0.y), h2pack(v0.z, v0.w),               \
                       h2pack(v1.x, v1.y), h2pack(v1.z, v1.w));              \
    }                                                                        \
    CPA_COMMIT();

    FILL_VP(0, 0)
    int p = 0;
    for (int ch = 0; ch < 4; ch++) {
        if (ch + 1 < 4) { FILL_VP(p ^ 1, (ch + 1) * 32) CPA_WAIT1(); }
        else            { CPA_WAIT0(); }
        __syncthreads();
        const unsigned off = p * BUFH;
        MMA16_TILE_BODY(off)
        __syncthreads();
        p ^= 1;
    }
#undef FILL_VP

    __half* Vsm = (__half*)blob;
#pragma unroll
    for (int mf = 0; mf < 4; mf++) {
        int rl = wm * 64 + mf * 16 + g;
        float inv0 = __fdividef(VSCALE, sum[j0 + rl]);
        float inv8 = __fdividef(VSCALE, sum[j0 + rl + 8]);
#pragma unroll
        for (int nf = 0; nf < 4; nf++) {
            int cl = wn * 32 + nf * 8 + 2 * t;
            Vsm[cl * LDT + rl]           = __float2half_rn(acc[mf][nf][0] * inv0);
            Vsm[(cl + 1) * LDT + rl]     = __float2half_rn(acc[mf][nf][1] * inv0);
            Vsm[cl * LDT + rl + 8]       = __float2half_rn(acc[mf][nf][2] * inv8);
            Vsm[(cl + 1) * LDT + rl + 8] = __float2half_rn(acc[mf][nf][3] * inv8);
        }
    }
    __syncthreads();
#pragma unroll
    for (int i = tid; i < 128 * 16; i += 256) {
        int c = i >> 4, chk = i & 15;
        uint4 v = *(uint4*)&Vsm[c * LDT + chk * 8];
        *(uint4*)&Dst[(size_t)c * N_ + j0 + chk * 8] = v;
    }
}

// ---------------- kernel 5: AV partial GEMMs --------------------------------
// mode 0: d = P[i-block, krange] @ vp^T-rows     (A m-major, non-trans ldsm)
// mode 1: d = P^T[i-block, krange] @ vi^T-rows   (A = P rows K-major, trans ldsm)
__global__ __launch_bounds__(256, 2) void k_av() {
    const int mode = blockIdx.x & 1;
    const int ks   = blockIdx.x >> 1;
    const int b    = blockIdx.z;
    const int i0   = blockIdx.y * 128;
    const int kb   = ks * KSPL;
    const __half* Pb = g_S16 + (size_t)b * N_ * N_;
    const __half* M0 = Pb + (size_t)i0 * N_;        // mode 0 A source
    const __half* Vt = g_vT16[mode] + (size_t)b * OC_ * N_;
    float*        D  = g_d[(mode << 2) | ks] + (size_t)b * N_ * OC_;

    __shared__ __align__(16) char blob[4 * BUFH];

    WARP_COORDS

    const unsigned sAu = smem_u32(blob);
    const unsigned sBu = sAu + 2 * BUFH;
    LDSM16_BASES_U(sAu, sBu)
    // trans-A base: K-major tile [32 rows][128 cols], pitch LDT.
    // matrix q=jm: k-row (lane&7)+(jm>>1)*8, m-col wm*64+(jm&1)*8.
    const unsigned baseAT = sAu +
        ((((lane & 7) + ((jm >> 1) * 8)) * LDT) + (wm * 64) + ((jm & 1) * 8)) * 2u;

    const int frow = tid >> 1, fg0 = (tid & 1) * 2;   // mode-0 / B fill coords
    const int trow = tid >> 3, tseg = tid & 7;        // mode-1 A fill coords

#define FILL_A0(pp, kk0)                                                     \
    _Pragma("unroll")                                                        \
    for (int r = 0; r < 2; r++) {                                            \
        int gq = fg0 + r;                                                    \
        CPA16(sAu + (pp) * BUFH + ((unsigned)frow * LDH + gq * 8) * 2u,      \
              M0 + (size_t)frow * N_ + (kk0) + gq * 8);                      \
    }
#define FILL_A1(pp, kk0)                                                     \
    _Pragma("unroll")                                                        \
    for (int r = 0; r < 2; r++) {                                            \
        int seg = tseg + r * 8;                                              \
        CPA16(sAu + (pp) * TKB + ((unsigned)trow * LDT + seg * 8) * 2u,      \
              Pb + (size_t)((kk0) + trow) * N_ + i0 + seg * 8);              \
    }
#define FILL_B(pp, kk0)                                                      \
    _Pragma("unroll")                                                        \
    for (int r = 0; r < 2; r++) {                                            \
        int gq = fg0 + r;                                                    \
        CPA16(sBu + (pp) * BUFH + ((unsigned)frow * LDH + gq * 8) * 2u,      \
              Vt + (size_t)frow * N_ + (kk0) + gq * 8);                      \
    }

    ZERO_ACC

    const int NCH = KSPL / 32;
    int p = 0;
    if (mode == 0) {
        FILL_A0(0, kb) FILL_B(0, kb) CPA_COMMIT();
        for (int ch = 0; ch < NCH; ch++) {
            if (ch + 1 < NCH) {
                FILL_A0(p ^ 1, kb + (ch + 1) * 32) FILL_B(p ^ 1, kb + (ch + 1) * 32)
                CPA_COMMIT(); CPA_WAIT1();
            } else CPA_WAIT0();
            __syncthreads();
            const unsigned off = p * BUFH;
            MMA16_TILE_BODY(off)
            __syncthreads();
            p ^= 1;
        }
    } else {
        FILL_A1(0, kb) FILL_B(0, kb) CPA_COMMIT();
        for (int ch = 0; ch < NCH; ch++) {
            if (ch + 1 < NCH) {
                FILL_A1(p ^ 1, kb + (ch + 1) * 32) FILL_B(p ^ 1, kb + (ch + 1) * 32)
                CPA_COMMIT(); CPA_WAIT1();
            } else CPA_WAIT0();
            __syncthreads();
            MMA16_TILE_BODY_T(p * TKB, p * BUFH)
            __syncthreads();
            p ^= 1;
        }
    }
#undef FILL_A0
#undef FILL_A1
#undef FILL_B

#pragma unroll
    for (int mf = 0; mf < 4; mf++) {
        int row = i0 + wm * 64 + mf * 16 + g;
#pragma unroll
        for (int nf = 0; nf < 4; nf++) {
            int col = wn * 32 + nf * 8 + 2 * t;
            *(float2*)&D[(size_t)row * OC_ + col]       = make_float2(acc[mf][nf][0], acc[mf][nf][1]);
            *(float2*)&D[(size_t)(row + 8) * OC_ + col] = make_float2(acc[mf][nf][2], acc[mf][nf][3]);
        }
    }
}

// ---------------- kernel 6: sum partials/VSCALE + BN + ReLU + transpose ------
__global__ void k_bn(const float* __restrict__ cb,    const float* __restrict__ gamma,
                     const float* __restrict__ beta,  const float* __restrict__ mean,
                     const float* __restrict__ var,   float* __restrict__ out) {
    __shared__ float tile[32][33];
    const int b  = blockIdx.z;
    const int n0 = blockIdx.x * 32;
    const int o0 = blockIdx.y * 32;
    const int tx = threadIdx.x, ty = threadIdx.y;   // (32, 8)
#pragma unroll
    for (int j = 0; j < 32; j += 8) {
        size_t idx = (size_t)b * N_ * OC_ + (size_t)(n0 + ty + j) * OC_ + o0 + tx;
        float s = 0.f;
#pragma unroll
        for (int m = 0; m < 8; m++) s += g_d[m][idx];
        tile[ty + j][tx] = s * (1.0f / VSCALE);
    }
    __syncthreads();
#pragma unroll
    for (int j = 0; j < 32; j += 8) {
        int o = o0 + ty + j;
        float gm   = gamma[o] * rsqrtf(var[o] + 1e-5f);
        float base = gm * (cb[o] - mean[o]) + beta[o];
        out[(size_t)b * OC_ * N_ + (size_t)o * N_ + n0 + tx] =
            fmaxf(gm * tile[tx][ty + j] + base, 0.f);
    }
}

// ---------------- launch -----------------------------------------------------
extern "C" void kernel_launch(void* const* d_in, const int* in_sizes, int n_in,
                              void* d_out, int out_size) {
    const float* pf     = (const float*)d_in[0];
    const float* img    = (const float*)d_in[1];
    const float* fc2_w  = (const float*)d_in[2];
    const float* fc2_b  = (const float*)d_in[3];
    const float* conv_w = (const float*)d_in[4];
    const float* conv_b = (const float*)d_in[5];
    const float* gamma  = (const float*)d_in[6];
    const float* beta   = (const float*)d_in[7];
    const float* mean   = (const float*)d_in[8];
    const float* var    = (const float*)d_in[9];
    float* out = (float*)d_out;

    k_zero     <<<(B_ * N_ + 511) / 512, 512>>>();
    k_transpose<<<dim3(N_ / 32, PC_ / 32, B_), dim3(32, 8)>>>(pf);
    k_ri       <<<dim3(N_ / 128, B_),           256>>>(img, fc2_w, fc2_b);
    k_s        <<<dim3(N_ / 128, N_ / 128, B_), 256>>>();
    k_vp       <<<dim3(N_ / 128, 2, B_),        256>>>(conv_w);
    k_av       <<<dim3(8, N_ / 128, B_),        256>>>();
    k_bn       <<<dim3(N_ / 32, OC_ / 32, B_),  dim3(32, 8)>>>(conv_b, gamma, beta,
                                                               mean, var, out);
}

// round 16
// speedup vs baseline: 4.0515x; 1.0531x over previous
#include <cuda_runtime.h>
#include <cuda_fp16.h>
#include <math.h>

#define B_   2
#define N_   4096
#define IC_  256
#define PC_  128
#define OC_  128
#define SCALE_ 0.08838834764831845f   // 1/sqrt(128)
#define VSCALE 4096.0f                 // vT scaling to stay in fp16 normal range
#define LDH  40                        // fp16 tile pitch (halves), 80 B/row
#define BUFH (128u * LDH * 2u)         // 10240 B per fp16 plane
#define KSPL (N_ / 4)
#define LDT  136                       // staging / K-major tile pitch (halves)
#define TKB  (32u * LDT * 2u)          // 8704 B per K-major A plane (32 k-rows)
#define KAV_SMEM (6u * BUFH)           // 61440 B: 3-stage A + B planes

// ---------------- scratch (device globals) ----------------------------------
static __device__ __align__(16) __half g_rp16[(size_t)B_ * N_ * PC_];
static __device__ __align__(16) __half g_ri16[(size_t)B_ * N_ * PC_];
static __device__ __align__(16) __half g_S16 [(size_t)B_ * N_ * N_];   // P
static __device__ __align__(16) __half g_vT16[2][(size_t)B_ * OC_ * N_]; // v^T * VSCALE
static __device__ __align__(16) float  g_csum[B_ * N_];
static __device__ __align__(16) float  g_rsum[B_ * N_];
static __device__ __align__(16) float  g_d   [8][(size_t)B_ * N_ * OC_]; // fp32 partials

// ---------------- helpers ----------------------------------------------------
__device__ __forceinline__ unsigned h2pack(float a, float b) {
    __half2 h = __floats2half2_rn(a, b);
    return *reinterpret_cast<unsigned*>(&h);
}
__device__ __forceinline__ void mma_f16(float* c, unsigned a0, unsigned a1,
                                        unsigned a2, unsigned a3,
                                        unsigned b0, unsigned b1) {
    asm volatile(
        "mma.sync.aligned.m16n8k16.row.col.f32.f16.f16.f32 "
        "{%0,%1,%2,%3}, {%4,%5,%6,%7}, {%8,%9}, {%0,%1,%2,%3};"
        : "+f"(c[0]), "+f"(c[1]), "+f"(c[2]), "+f"(c[3])
        : "r"(a0), "r"(a1), "r"(a2), "r"(a3), "r"(b0), "r"(b1));
}
__device__ __forceinline__ unsigned smem_u32(const void* p) {
    unsigned a;
    asm("{.reg .u64 t; cvta.to.shared.u64 t, %1; cvt.u32.u64 %0, t;}"
        : "=r"(a) : "l"(p));
    return a;
}
__device__ __forceinline__ void ldsm4(unsigned& r0, unsigned& r1,
                                      unsigned& r2, unsigned& r3, unsigned addr) {
    asm volatile("ldmatrix.sync.aligned.m8n8.x4.shared.b16 {%0,%1,%2,%3}, [%4];"
                 : "=r"(r0), "=r"(r1), "=r"(r2), "=r"(r3) : "r"(addr));
}
__device__ __forceinline__ void ldsm4t(unsigned& r0, unsigned& r1,
                                       unsigned& r2, unsigned& r3, unsigned addr) {
    asm volatile("ldmatrix.sync.aligned.m8n8.x4.trans.shared.b16 {%0,%1,%2,%3}, [%4];"
                 : "=r"(r0), "=r"(r1), "=r"(r2), "=r"(r3) : "r"(addr));
}
#define CPA16(dst, src) asm volatile("cp.async.cg.shared.global [%0], [%1], 16;" \
                                     :: "r"(dst), "l"(src) : "memory")
#define CPA_COMMIT()    asm volatile("cp.async.commit_group;" ::: "memory")
#define CPA_WAIT0()     asm volatile("cp.async.wait_group 0;" ::: "memory")
#define CPA_WAIT1()     asm volatile("cp.async.wait_group 1;" ::: "memory")
#define CPA_WAIT2()     asm volatile("cp.async.wait_group 2;" ::: "memory")

#define WARP_COORDS                                                          \
    const int tid  = threadIdx.x;                                            \
    const int lane = tid & 31, wid = tid >> 5;                               \
    const int wm = wid & 1, wn = wid >> 1;                                   \
    const int g = lane >> 2, t = lane & 3;                                   \
    const int jm = lane >> 3;                                                \
    (void)g; (void)t; (void)jm;

#define ZERO_ACC                                                             \
    float acc[4][4][4];                                                      \
    _Pragma("unroll")                                                        \
    for (int mf = 0; mf < 4; mf++)                                           \
        _Pragma("unroll")                                                    \
        for (int nf = 0; nf < 4; nf++)                                       \
            _Pragma("unroll")                                                 \
            for (int q = 0; q < 4; q++) acc[mf][nf][q] = 0.f;

// ----- fp16 path: BK = 32 halves -----
#define LDSM16_BASES_U(aU, bU)                                               \
    const unsigned baseA = (aU) +                                            \
        ((((wm * 64) + (lane & 15)) * LDH + ((lane >> 4) * 8)) * 2u);        \
    const unsigned baseB = (bU) +                                            \
        ((((wn * 32) + (lane & 7) + ((lane >> 4) * 8)) * LDH +               \
          (((lane >> 3) & 1) * 8)) * 2u);

#define LDSMT_BASE(aU)                                                       \
    const unsigned baseAT = (aU) +                                           \
        ((((lane & 7) + ((jm >> 1) * 8)) * LDT) + (wm * 64) + ((jm & 1) * 8)) * 2u;

#define MMA16_TILE_BODY(offA, offB)                                          \
    _Pragma("unroll")                                                        \
    for (int kk = 0; kk < 2; kk++) {                                         \
        unsigned a[4][4], bb[4][2];                                          \
        _Pragma("unroll")                                                    \
        for (int mf = 0; mf < 4; mf++)                                       \
            ldsm4(a[mf][0], a[mf][1], a[mf][2], a[mf][3],                    \
                  baseA + (offA) + (mf * 16 * LDH + kk * 16) * 2u);          \
        ldsm4(bb[0][0], bb[0][1], bb[1][0], bb[1][1],                        \
              baseB + (offB) + (kk * 16) * 2u);                              \
        ldsm4(bb[2][0], bb[2][1], bb[3][0], bb[3][1],                        \
              baseB + (offB) + (16 * LDH + kk * 16) * 2u);                   \
        _Pragma("unroll")                                                    \
        for (int mf = 0; mf < 4; mf++)                                       \
            _Pragma("unroll")                                                \
            for (int nf = 0; nf < 4; nf++)                                   \
                mma_f16(acc[mf][nf], a[mf][0], a[mf][1], a[mf][2], a[mf][3], \
                        bb[nf][0], bb[nf][1]);                               \
    }

// transposed-A variant: A tile is K-major [32 k-rows][128 m-cols], pitch LDT.
#define MMA16_TILE_BODY_T(offA, offB)                                        \
    _Pragma("unroll")                                                        \
    for (int kk = 0; kk < 2; kk++) {                                         \
        unsigned a[4][4], bb[4][2];                                          \
        _Pragma("unroll")                                                    \
        for (int mf = 0; mf < 4; mf++)                                       \
            ldsm4t(a[mf][0], a[mf][1], a[mf][2], a[mf][3],                   \
                   baseAT + (offA) + (kk * 16 * LDT + mf * 16) * 2u);        \
        ldsm4(bb[0][0], bb[0][1], bb[1][0], bb[1][1],                        \
              baseB + (offB) + (kk * 16) * 2u);                              \
        ldsm4(bb[2][0], bb[2][1], bb[3][0], bb[3][1],                        \
              baseB + (offB) + (16 * LDH + kk * 16) * 2u);                   \
        _Pragma("unroll")                                                    \
        for (int mf = 0; mf < 4; mf++)                                       \
            _Pragma("unroll")                                                \
            for (int nf = 0; nf < 4; nf++)                                   \
                mma_f16(acc[mf][nf], a[mf][0], a[mf][1], a[mf][2], a[mf][3], \
                        bb[nf][0], bb[nf][1]);                               \
    }

// ---------------- kernel 1: transpose pf -> rp16, plus zero sums -------------
__global__ void k_transpose(const float* __restrict__ pf) {
    __shared__ float tile[32][33];
    const int b  = blockIdx.z;
    const int n0 = blockIdx.x * 32;
    const int d0 = blockIdx.y * 32;
    const float* src = pf + (size_t)b * PC_ * N_;
    __half*      dst = g_rp16 + (size_t)b * N_ * PC_;
    const int tx = threadIdx.x, ty = threadIdx.y;   // (32, 8)
    if (blockIdx.y == 0) {                           // fold in k_zero
        int lt = ty * 32 + tx;
        if (lt < 32) {
            int zi = (b * (N_ / 32) + blockIdx.x) * 32 + lt;
            g_csum[zi] = 0.f; g_rsum[zi] = 0.f;
        }
    }
#pragma unroll
    for (int j = 0; j < 32; j += 8)
        tile[ty + j][tx] = src[(size_t)(d0 + ty + j) * N_ + n0 + tx];
    __syncthreads();
#pragma unroll
    for (int j = 0; j < 32; j += 8)
        dst[(size_t)(n0 + ty + j) * PC_ + d0 + tx] = __float2half_rn(tile[tx][ty + j]);
}

// ---------------- kernel 2: ri16 = half(img^T @ fc2_w^T + fc2_b)  (fp16 mma) -
// A = X rows K-major [32 c][128 n] (trans ldsm); B = w rows [128 d][32 c].
__global__ __launch_bounds__(256, 2) void k_ri(const float* __restrict__ img,
                                               const float* __restrict__ w,
                                               const float* __restrict__ bias) {
    const int b  = blockIdx.y;
    const int n0 = blockIdx.x * 128;
    const float* X = img + (size_t)b * IC_ * N_;
    __half*      R = g_ri16 + (size_t)b * N_ * PC_;

    __shared__ __align__(16) char blob[2 * TKB + 2 * BUFH];

    WARP_COORDS
    const unsigned sAu = smem_u32(blob);
    const unsigned sBu = sAu + 2 * TKB;
    LDSMT_BASE(sAu)
    const unsigned baseB = sBu +
        ((((wn * 32) + (lane & 7) + ((lane >> 4) * 8)) * LDH +
          (((lane >> 3) & 1) * 8)) * 2u);

    const int trow = tid >> 3, tn0 = (tid & 7) * 16;  // A: c-row, 16-n segment
    const int frow = tid >> 1, fg0 = (tid & 1) * 2;   // B: d-row, c-quads

    ZERO_ACC

    float4 xa[4]; float4 wb[2];
#pragma unroll
    for (int r = 0; r < 4; r++)
        xa[r] = *(const float4*)&X[(size_t)trow * N_ + n0 + tn0 + r * 4];
#pragma unroll
    for (int r = 0; r < 2; r++)
        wb[r] = *(const float4*)&w[(size_t)frow * IC_ + (fg0 + r) * 8];

    int p = 0;
    for (int ch = 0; ch < IC_ / 32; ch++) {
        // convert + store A (K-major) and B
        {
            uint4 u0 = make_uint4(h2pack(xa[0].x, xa[0].y), h2pack(xa[0].z, xa[0].w),
                                  h2pack(xa[1].x, xa[1].y), h2pack(xa[1].z, xa[1].w));
            uint4 u1 = make_uint4(h2pack(xa[2].x, xa[2].y), h2pack(xa[2].z, xa[2].w),
                                  h2pack(xa[3].x, xa[3].y), h2pack(xa[3].z, xa[3].w));
            char* ap = blob + p * TKB + (trow * LDT + tn0) * 2;
            *(uint4*)ap = u0; *(uint4*)(ap + 16) = u1;
#pragma unroll
            for (int r = 0; r < 2; r++) {
                int gq = fg0 + r;
                float4 v0 = wb[r];
                // second half of the 8-float group: load now (8 regs saved)
                float4 v1 = *(const float4*)&w[(size_t)frow * IC_ + ch * 32 + gq * 8 + 4];
                *(uint4*)(blob + 2 * TKB + p * BUFH + (frow * LDH + gq * 8) * 2) =
                    make_uint4(h2pack(v0.x, v0.y), h2pack(v0.z, v0.w),
                               h2pack(v1.x, v1.y), h2pack(v1.z, v1.w));
            }
        }
        __syncthreads();
        if (ch + 1 < IC_ / 32) {
            int kn = (ch + 1) * 32;
#pragma unroll
            for (int r = 0; r < 4; r++)
                xa[r] = *(const float4*)&X[(size_t)(kn + trow) * N_ + n0 + tn0 + r * 4];
#pragma unroll
            for (int r = 0; r < 2; r++)
                wb[r] = *(const float4*)&w[(size_t)frow * IC_ + kn + (fg0 + r) * 8];
        }
        MMA16_TILE_BODY_T(p * TKB, p * BUFH)
        __syncthreads();
        p ^= 1;
    }

#pragma unroll
    for (int mf = 0; mf < 4; mf++) {
        int row = n0 + wm * 64 + mf * 16 + g;
#pragma unroll
        for (int nf = 0; nf < 4; nf++) {
            int col = wn * 32 + nf * 8 + 2 * t;
            float b0 = bias[col], b1 = bias[col + 1];
            *(unsigned*)&R[(size_t)row * PC_ + col] =
                h2pack(acc[mf][nf][0] + b0, acc[mf][nf][1] + b1);
            *(unsigned*)&R[(size_t)(row + 8) * PC_ + col] =
                h2pack(acc[mf][nf][2] + b0, acc[mf][nf][3] + b1);
        }
    }
}

// ---------------- kernel 3: P = exp(scale * rp @ ri^T); staged P, sums -------
__global__ __launch_bounds__(256, 2) void k_s() {
    const int b  = blockIdx.z;
    const int i0 = blockIdx.y * 128;
    const int j0 = blockIdx.x * 128;
    const __half* A16 = g_rp16 + (size_t)b * N_ * PC_ + (size_t)i0 * PC_;
    const __half* B16 = g_ri16 + (size_t)b * N_ * PC_ + (size_t)j0 * PC_;
    __half*       Pp  = g_S16  + (size_t)b * N_ * N_;

    __shared__ __align__(16) char blob[4 * BUFH];   // operands, then P staging tile
    __shared__ float shr[128], shc[128];

    WARP_COORDS

    const unsigned sAu = smem_u32(blob);
    const unsigned sBu = sAu + 2 * BUFH;
    LDSM16_BASES_U(sAu, sBu)

    const int frow = tid >> 1, fg0 = (tid & 1) * 2;

#define FILL_S16(pp, kk0)                                                    \
    _Pragma("unroll")                                                        \
    for (int r = 0; r < 2; r++) {                                            \
        int gq = fg0 + r;                                                    \
        unsigned o = (pp) * BUFH + ((unsigned)frow * LDH + gq * 8) * 2u;     \
        CPA16(sAu + o, A16 + (size_t)frow * PC_ + (kk0) + gq * 8);           \
        CPA16(sBu + o, B16 + (size_t)frow * PC_ + (kk0) + gq * 8);           \
    }                                                                        \
    CPA_COMMIT();

    ZERO_ACC

    FILL_S16(0, 0)
    int p = 0;
    for (int ch = 0; ch < 4; ch++) {             // PC_/32 chunks
        if (ch + 1 < 4) { FILL_S16(p ^ 1, (ch + 1) * 32) CPA_WAIT1(); }
        else            { CPA_WAIT0(); }
        __syncthreads();
        MMA16_TILE_BODY(p * BUFH, p * BUFH)
        __syncthreads();
        p ^= 1;
    }
#undef FILL_S16

    __half* Psm = (__half*)blob;
    if (tid < 128) { shr[tid] = 0.f; shc[tid] = 0.f; }
    __syncthreads();

    float rs[4][2] = {{0.f,0.f},{0.f,0.f},{0.f,0.f},{0.f,0.f}};
    float cs[4][2] = {{0.f,0.f},{0.f,0.f},{0.f,0.f},{0.f,0.f}};
#pragma unroll
    for (int mf = 0; mf < 4; mf++) {
        int rl = wm * 64 + mf * 16 + g;
#pragma unroll
        for (int nf = 0; nf < 4; nf++) {
            int cl = wn * 32 + nf * 8 + 2 * t;
            float p0 = __expf(acc[mf][nf][0] * SCALE_);
            float p1 = __expf(acc[mf][nf][1] * SCALE_);
            float p2 = __expf(acc[mf][nf][2] * SCALE_);
            float p3 = __expf(acc[mf][nf][3] * SCALE_);
            *(unsigned*)&Psm[rl * LDT + cl]       = h2pack(p0, p1);
            *(unsigned*)&Psm[(rl + 8) * LDT + cl] = h2pack(p2, p3);
            rs[mf][0] += p0 + p1; rs[mf][1] += p2 + p3;
            cs[nf][0] += p0 + p2; cs[nf][1] += p1 + p3;
        }
    }
#pragma unroll
    for (int mf = 0; mf < 4; mf++)
#pragma unroll
        for (int h = 0; h < 2; h++) {
            float v = rs[mf][h];
            v += __shfl_xor_sync(0xffffffffu, v, 1);
            v += __shfl_xor_sync(0xffffffffu, v, 2);
            if (t == 0) atomicAdd(&shr[wm * 64 + mf * 16 + h * 8 + g], v);
        }
#pragma unroll
    for (int nf = 0; nf < 4; nf++)
#pragma unroll
        for (int q = 0; q < 2; q++) {
            float v = cs[nf][q];
            v += __shfl_xor_sync(0xffffffffu, v, 4);
            v += __shfl_xor_sync(0xffffffffu, v, 8);
            v += __shfl_xor_sync(0xffffffffu, v, 16);
            if (g == 0) atomicAdd(&shc[wn * 32 + nf * 8 + 2 * t + q], v);
        }
    __syncthreads();

#pragma unroll
    for (int i = tid; i < 128 * 16; i += 256) {
        int r = i >> 4, chk = i & 15;
        uint4 v = *(uint4*)&Psm[r * LDT + chk * 8];
        *(uint4*)&Pp[(size_t)(i0 + r) * N_ + j0 + chk * 8] = v;
    }
    if (tid < 128) {
        atomicAdd(&g_rsum[b * N_ + i0 + tid], shr[tid]);
        atomicAdd(&g_csum[b * N_ + j0 + tid], shc[tid]);
    }
}

// ---------------- kernel 4: vT16 = half(VSCALE*((Src@W^T)/sum))^T, staged ----
__global__ __launch_bounds__(256, 2) void k_vp(const float* __restrict__ w) {
    const int which = blockIdx.y;
    const int b  = blockIdx.z;
    const int j0 = blockIdx.x * 128;
    const __half* Src = (which ? g_ri16 : g_rp16) + (size_t)b * N_ * PC_ + (size_t)j0 * PC_;
    const float*  sum = (which ? g_rsum : g_csum) + b * N_;
    __half*       Dst = g_vT16[which] + (size_t)b * OC_ * N_;

    __shared__ __align__(16) char blob[4 * BUFH];

    WARP_COORDS

    const unsigned sAu = smem_u32(blob);
    const unsigned sBu = sAu + 2 * BUFH;
    LDSM16_BASES_U(sAu, sBu)

    const int frow = tid >> 1, fg0 = (tid & 1) * 2;

    ZERO_ACC

#define FILL_VP(pp, kk0)                                                     \
    _Pragma("unroll")                                                        \
    for (int r = 0; r < 2; r++) {                                            \
        int gq = fg0 + r;                                                    \
        unsigned o = (pp) * BUFH + ((unsigned)frow * LDH + gq * 8) * 2u;     \
        CPA16(sAu + o, Src + (size_t)frow * PC_ + (kk0) + gq * 8);           \
        const float* ws = &w[(size_t)frow * (2 * PC_) + which * PC_ + (kk0) + gq * 8]; \
        float4 v0 = *(const float4*)ws, v1 = *(const float4*)(ws + 4);       \
        *(uint4*)(blob + 2 * BUFH + (pp) * BUFH + frow * (LDH * 2) + gq * 16) = \
            make_uint4(h2pack(v0.x, v0.y), h2pack(v0.z, v0.w),               \
                       h2pack(v1.x, v1.y), h2pack(v1.z, v1.w));              \
    }                                                                        \
    CPA_COMMIT();

    FILL_VP(0, 0)
    int p = 0;
    for (int ch = 0; ch < 4; ch++) {
        if (ch + 1 < 4) { FILL_VP(p ^ 1, (ch + 1) * 32) CPA_WAIT1(); }
        else            { CPA_WAIT0(); }
        __syncthreads();
        MMA16_TILE_BODY(p * BUFH, p * BUFH)
        __syncthreads();
        p ^= 1;
    }
#undef FILL_VP

    __half* Vsm = (__half*)blob;
#pragma unroll
    for (int mf = 0; mf < 4; mf++) {
        int rl = wm * 64 + mf * 16 + g;
        float inv0 = __fdividef(VSCALE, sum[j0 + rl]);
        float inv8 = __fdividef(VSCALE, sum[j0 + rl + 8]);
#pragma unroll
        for (int nf = 0; nf < 4; nf++) {
            int cl = wn * 32 + nf * 8 + 2 * t;
            Vsm[cl * LDT + rl]           = __float2half_rn(acc[mf][nf][0] * inv0);
            Vsm[(cl + 1) * LDT + rl]     = __float2half_rn(acc[mf][nf][1] * inv0);
            Vsm[cl * LDT + rl + 8]       = __float2half_rn(acc[mf][nf][2] * inv8);
            Vsm[(cl + 1) * LDT + rl + 8] = __float2half_rn(acc[mf][nf][3] * inv8);
        }
    }
    __syncthreads();
#pragma unroll
    for (int i = tid; i < 128 * 16; i += 256) {
        int c = i >> 4, chk = i & 15;
        uint4 v = *(uint4*)&Vsm[c * LDT + chk * 8];
        *(uint4*)&Dst[(size_t)c * N_ + j0 + chk * 8] = v;
    }
}

// ---------------- kernel 5: AV partial GEMMs (3-stage cp.async pipeline) -----
// mode 0: d = P[i-block, krange] @ vp^T-rows     (A m-major, non-trans ldsm)
// mode 1: d = P^T[i-block, krange] @ vi^T-rows   (A = P rows K-major, trans ldsm)
__global__ __launch_bounds__(256, 2) void k_av() {
    extern __shared__ __align__(16) char dyn[];    // KAV_SMEM bytes
    const int mode = blockIdx.x & 1;
    const int ks   = blockIdx.x >> 1;
    const int b    = blockIdx.z;
    const int i0   = blockIdx.y * 128;
    const int kb   = ks * KSPL;
    const __half* Pb = g_S16 + (size_t)b * N_ * N_;
    const __half* M0 = Pb + (size_t)i0 * N_;        // mode 0 A source
    const __half* Vt = g_vT16[mode] + (size_t)b * OC_ * N_;
    float*        D  = g_d[(mode << 2) | ks] + (size_t)b * N_ * OC_;

    WARP_COORDS

    const unsigned sAu = smem_u32(dyn);
    const unsigned sBu = sAu + 3 * BUFH;
    LDSM16_BASES_U(sAu, sBu)
    LDSMT_BASE(sAu)

    const int frow = tid >> 1, fg0 = (tid & 1) * 2;   // mode-0 / B fill coords
    const int trow = tid >> 3, tseg = tid & 7;        // mode-1 A fill coords

#define FILL_A0(ss, kk0)                                                     \
    _Pragma("unroll")                                                        \
    for (int r = 0; r < 2; r++) {                                            \
        int gq = fg0 + r;                                                    \
        CPA16(sAu + (ss) * BUFH + ((unsigned)frow * LDH + gq * 8) * 2u,      \
              M0 + (size_t)frow * N_ + (kk0) + gq * 8);                      \
    }
#define FILL_A1(ss, kk0)                                                     \
    _Pragma("unroll")                                                        \
    for (int r = 0; r < 2; r++) {                                            \
        int seg = tseg + r * 8;                                              \
        CPA16(sAu + (ss) * BUFH + ((unsigned)trow * LDT + seg * 8) * 2u,     \
              Pb + (size_t)((kk0) + trow) * N_ + i0 + seg * 8);              \
    }
#define FILL_B(ss, kk0)                                                      \
    _Pragma("unroll")                                                        \
    for (int r = 0; r < 2; r++) {                                            \
        int gq = fg0 + r;                                                    \
        CPA16(sBu + (ss) * BUFH + ((unsigned)frow * LDH + gq * 8) * 2u,      \
              Vt + (size_t)frow * N_ + (kk0) + gq * 8);                      \
    }

    ZERO_ACC

    const int NCH = KSPL / 32;
    if (mode == 0) {
        FILL_A0(0, kb) FILL_B(0, kb) CPA_COMMIT();
        FILL_A0(1, kb + 32) FILL_B(1, kb + 32) CPA_COMMIT();
        for (int ch = 0; ch < NCH; ch++) {
            int s = ch % 3;
            if (ch + 2 < NCH) {
                int sn = (ch + 2) % 3, kn = kb + (ch + 2) * 32;
                FILL_A0(sn, kn) FILL_B(sn, kn) CPA_COMMIT(); CPA_WAIT2();
            } else if (ch + 1 < NCH) CPA_WAIT1(); else CPA_WAIT0();
            __syncthreads();
            MMA16_TILE_BODY(s * BUFH, s * BUFH)
            __syncthreads();
        }
    } else {
        FILL_A1(0, kb) FILL_B(0, kb) CPA_COMMIT();
        FILL_A1(1, kb + 32) FILL_B(1, kb + 32) CPA_COMMIT();
        for (int ch = 0; ch < NCH; ch++) {
            int s = ch % 3;
            if (ch + 2 < NCH) {
                int sn = (ch + 2) % 3, kn = kb + (ch + 2) * 32;
                FILL_A1(sn, kn) FILL_B(sn, kn) CPA_COMMIT(); CPA_WAIT2();
            } else if (ch + 1 < NCH) CPA_WAIT1(); else CPA_WAIT0();
            __syncthreads();
            MMA16_TILE_BODY_T(s * BUFH, s * BUFH)
            __syncthreads();
        }
    }
#undef FILL_A0
#undef FILL_A1
#undef FILL_B

#pragma unroll
    for (int mf = 0; mf < 4; mf++) {
        int row = i0 + wm * 64 + mf * 16 + g;
#pragma unroll
        for (int nf = 0; nf < 4; nf++) {
            int col = wn * 32 + nf * 8 + 2 * t;
            *(float2*)&D[(size_t)row * OC_ + col]       = make_float2(acc[mf][nf][0], acc[mf][nf][1]);
            *(float2*)&D[(size_t)(row + 8) * OC_ + col] = make_float2(acc[mf][nf][2], acc[mf][nf][3]);
        }
    }
}

// ---------------- kernel 6: sum partials/VSCALE + BN + ReLU + transpose ------
__global__ void k_bn(const float* __restrict__ cb,    const float* __restrict__ gamma,
                     const float* __restrict__ beta,  const float* __restrict__ mean,
                     const float* __restrict__ var,   float* __restrict__ out) {
    __shared__ float tile[32][33];
    const int b  = blockIdx.z;
    const int n0 = blockIdx.x * 32;
    const int o0 = blockIdx.y * 32;
    const int tx = threadIdx.x, ty = threadIdx.y;   // (32, 8)
#pragma unroll
    for (int j = 0; j < 32; j += 8) {
        size_t idx = (size_t)b * N_ * OC_ + (size_t)(n0 + ty + j) * OC_ + o0 + tx;
        float s = 0.f;
#pragma unroll
        for (int m = 0; m < 8; m++) s += g_d[m][idx];
        tile[ty + j][tx] = s * (1.0f / VSCALE);
    }
    __syncthreads();
#pragma unroll
    for (int j = 0; j < 32; j += 8) {
        int o = o0 + ty + j;
        float gm   = gamma[o] * rsqrtf(var[o] + 1e-5f);
        float base = gm * (cb[o] - mean[o]) + beta[o];
        out[(size_t)b * OC_ * N_ + (size_t)o * N_ + n0 + tx] =
            fmaxf(gm * tile[tx][ty + j] + base, 0.f);
    }
}

// ---------------- launch -----------------------------------------------------
extern "C" void kernel_launch(void* const* d_in, const int* in_sizes, int n_in,
                              void* d_out, int out_size) {
    const float* pf     = (const float*)d_in[0];
    const float* img    = (const float*)d_in[1];
    const float* fc2_w  = (const float*)d_in[2];
    const float* fc2_b  = (const float*)d_in[3];
    const float* conv_w = (const float*)d_in[4];
    const float* conv_b = (const float*)d_in[5];
    const float* gamma  = (const float*)d_in[6];
    const float* beta   = (const float*)d_in[7];
    const float* mean   = (const float*)d_in[8];
    const float* var    = (const float*)d_in[9];
    float* out = (float*)d_out;

    cudaFuncSetAttribute(k_av, cudaFuncAttributeMaxDynamicSharedMemorySize, KAV_SMEM);

    k_transpose<<<dim3(N_ / 32, PC_ / 32, B_), dim3(32, 8)>>>(pf);
    k_ri       <<<dim3(N_ / 128, B_),           256>>>(img, fc2_w, fc2_b);
    k_s        <<<dim3(N_ / 128, N_ / 128, B_), 256>>>();
    k_vp       <<<dim3(N_ / 128, 2, B_),        256>>>(conv_w);
    k_av       <<<dim3(8, N_ / 128, B_),        256, KAV_SMEM>>>();
    k_bn       <<<dim3(N_ / 32, OC_ / 32, B_),  dim3(32, 8)>>>(conv_b, gamma, beta,
                                                               mean, var, out);
}